// round 6
// baseline (speedup 1.0000x reference)
#include <cuda_runtime.h>
#include <cuda_bf16.h>
#include <math.h>
#include <stddef.h>
#include <stdint.h>

// ---------------- problem constants ----------------
#define BB   2
#define SS   2048
#define DD   1024
#define HH   16
#define HDIM 64
#define DFFC 2048
#define BH   (BB*HH)
#define NTOK (BB*SS)

#define MU_C   1.0f
#define K_C    3.0f
#define DT_C   0.02f
#define MIX_C  0.3f
#define CA_C   0.9950041652780258f
#define SA_C   0.09983341664682815f

// ---------------- scratch ----------------
__device__ float g_S [(size_t)BH * SS * SS];
__device__ __nv_bfloat16 g_Ahi[(size_t)BH * SS * SS];
__device__ __nv_bfloat16 g_Alo[(size_t)BH * SS * SS];
__device__ float g_xn  [(size_t)NTOK * DD];
__device__ __nv_bfloat16 g_xnhi[(size_t)NTOK * DD];
__device__ __nv_bfloat16 g_xnlo[(size_t)NTOK * DD];
__device__ __nv_bfloat16 g_qhi[(size_t)BH * SS * 64];
__device__ __nv_bfloat16 g_qlo[(size_t)BH * SS * 64];
__device__ __nv_bfloat16 g_khi[(size_t)BH * SS * 64];
__device__ __nv_bfloat16 g_klo[(size_t)BH * SS * 64];
__device__ float g_ab  [(size_t)BH * SS * 128];
__device__ float g_d1  [(size_t)BH * SS * 128];
__device__ __nv_bfloat16 g_abThi[(size_t)BH * SS * 128];
__device__ __nv_bfloat16 g_abTlo[(size_t)BH * SS * 128];
__device__ __nv_bfloat16 g_pThi [(size_t)BH * SS * 128];
__device__ __nv_bfloat16 g_pTlo [(size_t)BH * SS * 128];
__device__ float g_attnv[(size_t)BH * SS * 64];
__device__ float g_mix  [(size_t)BH * SS * 64];
__device__ float g_x1   [(size_t)NTOK * DD];
__device__ __nv_bfloat16 g_ffhi[(size_t)NTOK * DFFC];
__device__ __nv_bfloat16 g_fflo[(size_t)NTOK * DFFC];
__device__ __nv_bfloat16 g_W1hi[(size_t)DD * DFFC];
__device__ __nv_bfloat16 g_W1lo[(size_t)DD * DFFC];
__device__ __nv_bfloat16 g_W2hi[(size_t)DFFC * DD];
__device__ __nv_bfloat16 g_W2lo[(size_t)DFFC * DD];

// ---------------- low-level helpers ----------------
__device__ __forceinline__ uint32_t smem_u32(const void* p) {
    uint32_t a;
    asm("{ .reg .u64 t; cvta.to.shared.u64 t, %1; cvt.u32.u64 %0, t; }" : "=r"(a) : "l"(p));
    return a;
}
__device__ __forceinline__ void cp16(uint32_t s, const void* g) {
    asm volatile("cp.async.cg.shared.global [%0], [%1], 16;" :: "r"(s), "l"(g));
}
__device__ __forceinline__ void cp_commit() {
    asm volatile("cp.async.commit_group;" ::: "memory");
}
template <int N>
__device__ __forceinline__ void cp_wait() {
    asm volatile("cp.async.wait_group %0;" :: "n"(N) : "memory");
}
__device__ __forceinline__ void ldm_x4(uint32_t* r, uint32_t addr) {
    asm volatile("ldmatrix.sync.aligned.m8n8.x4.shared.b16 {%0,%1,%2,%3}, [%4];"
        : "=r"(r[0]), "=r"(r[1]), "=r"(r[2]), "=r"(r[3]) : "r"(addr));
}
__device__ __forceinline__ void ldm_x4t(uint32_t* r, uint32_t addr) {
    asm volatile("ldmatrix.sync.aligned.m8n8.x4.trans.shared.b16 {%0,%1,%2,%3}, [%4];"
        : "=r"(r[0]), "=r"(r[1]), "=r"(r[2]), "=r"(r[3]) : "r"(addr));
}
__device__ __forceinline__ void mma_bf16(float* c, const uint32_t* a, const uint32_t* b) {
    asm volatile("mma.sync.aligned.m16n8k16.row.col.f32.bf16.bf16.f32 "
        "{%0,%1,%2,%3}, {%4,%5,%6,%7}, {%8,%9}, {%0,%1,%2,%3};"
        : "+f"(c[0]), "+f"(c[1]), "+f"(c[2]), "+f"(c[3])
        : "r"(a[0]), "r"(a[1]), "r"(a[2]), "r"(a[3]), "r"(b[0]), "r"(b[1]));
}
__device__ __forceinline__ float gelu_tanh(float x) {
    float x3 = x * x * x;
    float t  = tanhf(0.7978845608028654f * (x + 0.044715f * x3));
    return 0.5f * x * (1.0f + t);
}
__device__ __forceinline__ void bf16_split2(float a, float b,
                                            __nv_bfloat162& h, __nv_bfloat162& l) {
    h.x = __float2bfloat16(a); h.y = __float2bfloat16(b);
    l.x = __float2bfloat16(a - __bfloat162float(h.x));
    l.y = __float2bfloat16(b - __bfloat162float(h.y));
}

// ---------------- unified 3-product bf16 HMMA GEMM, fusable ODE epilogue ----------------
// EPI: 0 = plain C output; 1 = fused ode_ew1; 2 = fused ode_ew2.
#define AST 72
#define BSTN 72
#define BSTT 136
#define OFF_AL 18432
#define OFF_BH 36864
#define OFF_BL 55296
#define STAGE_BYTES 73728
#define NSTG 3
#define HSMEM (NSTG * STAGE_BYTES)     // 221184

template<bool TRANSB, int EPI>
__global__ void __launch_bounds__(256, 1)
hgemm_kernel(const __nv_bfloat16* __restrict__ Ahi, const __nv_bfloat16* __restrict__ Alo,
             const __nv_bfloat16* __restrict__ Bhi, const __nv_bfloat16* __restrict__ Blo,
             int K, int lda, int ldb, int ldc,
             long long sA, long long sB, long long sC,
             float* __restrict__ outF,
             __nv_bfloat16* __restrict__ outHi, __nv_bfloat16* __restrict__ outLo,
             const float* __restrict__ bias, const float* __restrict__ addsrc, int do_gelu,
             const float* __restrict__ omg, float* __restrict__ abf,
             float* __restrict__ d1f, float* __restrict__ attnv,
             float* __restrict__ mixed, int flag)
{
    extern __shared__ char smem[];
    const uint32_t sb = smem_u32(smem);
    const int tid = threadIdx.x;
    const int lane = tid & 31, w = tid >> 5;
    const int wm = w >> 2, wn = w & 3;
    const int n0 = blockIdx.x * 128;
    const int m0 = blockIdx.y * 128;
    const long long bz = blockIdx.z;

    Ahi += bz * sA; Alo += bz * sA;
    Bhi += bz * sB; Blo += bz * sB;

    float acc[4][4][4];
#pragma unroll
    for (int i = 0; i < 4; i++)
#pragma unroll
        for (int j = 0; j < 4; j++)
#pragma unroll
            for (int r = 0; r < 4; r++) acc[i][j][r] = 0.f;

    auto issue = [&](int chunk, int buf) {
        const int k0 = chunk << 6;
        const uint32_t st = sb + buf * STAGE_BYTES;
        {
            const int row = tid >> 3, col = (tid & 7) * 8;
            const __nv_bfloat16* gH = Ahi + (size_t)(m0 + row) * lda + k0 + col;
            const __nv_bfloat16* gL = Alo + (size_t)(m0 + row) * lda + k0 + col;
            uint32_t s = st + (row * AST + col) * 2;
#pragma unroll
            for (int j = 0; j < 4; j++) {
                cp16(s + j * 32 * (AST * 2),          gH + (size_t)j * 32 * lda);
                cp16(s + OFF_AL + j * 32 * (AST * 2), gL + (size_t)j * 32 * lda);
            }
        }
        if (TRANSB) {
            const int rk = tid >> 2, col = (tid & 3) * 8;
            const __nv_bfloat16* gH = Bhi + (size_t)(k0 + rk) * ldb + n0 + col;
            const __nv_bfloat16* gL = Blo + (size_t)(k0 + rk) * ldb + n0 + col;
            uint32_t s = st + OFF_BH + (rk * BSTT + col) * 2;
#pragma unroll
            for (int j = 0; j < 4; j++) {
                cp16(s + j * 64,                     gH + j * 32);
                cp16(s + (OFF_BL - OFF_BH) + j * 64, gL + j * 32);
            }
        } else {
            const int rn = tid >> 3, col = (tid & 7) * 8;
            const __nv_bfloat16* gH = Bhi + (size_t)(n0 + rn) * ldb + k0 + col;
            const __nv_bfloat16* gL = Blo + (size_t)(n0 + rn) * ldb + k0 + col;
            uint32_t s = st + OFF_BH + (rn * BSTN + col) * 2;
#pragma unroll
            for (int j = 0; j < 4; j++) {
                cp16(s + j * 32 * (BSTN * 2),                     gH + (size_t)j * 32 * ldb);
                cp16(s + (OFF_BL - OFF_BH) + j * 32 * (BSTN * 2), gL + (size_t)j * 32 * ldb);
            }
        }
        cp_commit();
    };

    auto compute = [&](int buf) {
        const uint32_t st = sb + buf * STAGE_BYTES;
#pragma unroll
        for (int k16 = 0; k16 < 4; k16++) {
            uint32_t afrH[4][4], afrL[4][4], bfrH[4][2], bfrL[4][2];
#pragma unroll
            for (int ms = 0; ms < 4; ms++) {
                int row = wm * 64 + ms * 16 + (lane & 15);
                int col = k16 * 16 + (lane >> 4) * 8;
                ldm_x4(afrH[ms], st + (row * AST + col) * 2);
                ldm_x4(afrL[ms], st + OFF_AL + (row * AST + col) * 2);
            }
            if (TRANSB) {
                const int mat = lane >> 3, rr = lane & 7;
#pragma unroll
                for (int p = 0; p < 2; p++) {
                    int rk = k16 * 16 + (mat & 1) * 8 + rr;
                    int cn = wn * 32 + p * 16 + (mat >> 1) * 8;
                    ldm_x4t(&bfrH[p * 2][0], st + OFF_BH + (rk * BSTT + cn) * 2);
                    ldm_x4t(&bfrL[p * 2][0], st + OFF_BL + (rk * BSTT + cn) * 2);
                }
            } else {
                const int mat = lane >> 3, rr = lane & 7;
#pragma unroll
                for (int p = 0; p < 2; p++) {
                    int rn = wn * 32 + p * 16 + (mat >> 1) * 8 + rr;
                    int ck = k16 * 16 + (mat & 1) * 8;
                    ldm_x4(&bfrH[p * 2][0], st + OFF_BH + (rn * BSTN + ck) * 2);
                    ldm_x4(&bfrL[p * 2][0], st + OFF_BL + (rn * BSTN + ck) * 2);
                }
            }
#pragma unroll
            for (int ms = 0; ms < 4; ms++)
#pragma unroll
                for (int ns = 0; ns < 4; ns++) {
                    mma_bf16(acc[ms][ns], afrH[ms], bfrH[ns]);
                    mma_bf16(acc[ms][ns], afrH[ms], bfrL[ns]);
                    mma_bf16(acc[ms][ns], afrL[ms], bfrH[ns]);
                }
        }
    };

    const int nchunk = K >> 6;
    issue(0, 0);
    if (nchunk > 1) issue(1, 1);
#pragma unroll 1
    for (int i = 0; i < nchunk; i++) {
        if (i + 2 < nchunk)      { issue(i + 2, (i + 2) % NSTG); cp_wait<2>(); }
        else if (i + 1 < nchunk) { cp_wait<1>(); }
        else                     { cp_wait<0>(); }
        __syncthreads();
        compute(i % NSTG);
        __syncthreads();
    }

    if (EPI == 0) {
        const long long cb = bz * sC;
#pragma unroll
        for (int ms = 0; ms < 4; ms++) {
#pragma unroll
            for (int ns = 0; ns < 4; ns++) {
                int r0 = wm * 64 + ms * 16 + (lane >> 2);
                int c0 = n0 + wn * 32 + ns * 8 + (lane & 3) * 2;
#pragma unroll
                for (int half = 0; half < 2; half++) {
                    long long r = m0 + r0 + half * 8;
                    float vx = acc[ms][ns][half * 2 + 0];
                    float vy = acc[ms][ns][half * 2 + 1];
                    if (bias)   { vx += bias[c0]; vy += bias[c0 + 1]; }
                    if (addsrc) {
                        float2 s = *reinterpret_cast<const float2*>(addsrc + r * ldc + c0);
                        vx += s.x; vy += s.y;
                    }
                    if (do_gelu) { vx = gelu_tanh(vx); vy = gelu_tanh(vy); }
                    long long o = cb + r * ldc + c0;
                    if (outF)
                        *reinterpret_cast<float2*>(outF + o) = make_float2(vx, vy);
                    if (outHi) {
                        __nv_bfloat162 h, l;
                        bf16_split2(vx, vy, h, l);
                        *reinterpret_cast<__nv_bfloat162*>(outHi + o) = h;
                        *reinterpret_cast<__nv_bfloat162*>(outLo + o) = l;
                    }
                }
            }
        }
    } else {
        // stage z tile (128x128) into smem, then fused ODE elementwise
        float* zsm = reinterpret_cast<float*>(smem);
#pragma unroll
        for (int ms = 0; ms < 4; ms++)
#pragma unroll
            for (int ns = 0; ns < 4; ns++) {
                int r0 = wm * 64 + ms * 16 + (lane >> 2);
                int c0 = wn * 32 + ns * 8 + (lane & 3) * 2;
                zsm[r0 * 132 + c0]     = acc[ms][ns][0];
                zsm[r0 * 132 + c0 + 1] = acc[ms][ns][1];
                zsm[(r0 + 8) * 132 + c0]     = acc[ms][ns][2];
                zsm[(r0 + 8) * 132 + c0 + 1] = acc[ms][ns][3];
            }
        __syncthreads();
        const int h = (int)(bz & 15);
#pragma unroll 1
        for (int it = 0; it < 32; it++) {
            int lin = it * 256 + tid;           // 8192 (r, c) pairs
            int r = lin >> 6, c = lin & 63;
            size_t row = (size_t)bz * SS + m0 + r;
            size_t base = row * 128 + c;
            float za = zsm[r * 132 + c], zb = zsm[r * 132 + c + 64];
            float om = omg[h * 64 + c];
            float a = abf[base], b = abf[base + 64];
            float ra = za * CA_C + zb * SA_C;
            float rb = zb * CA_C - za * SA_C;
            if (EPI == 1) {
                if (flag) attnv[row * 64 + c] = za;
                float r2 = a * a + b * b;
                float da = (MU_C - r2) * a - om * b + K_C * (ra - a);
                float db = (MU_C - r2) * b + om * a + K_C * (rb - b);
                d1f[base] = da; d1f[base + 64] = db;
                float ap = a + DT_C * da, bp = b + DT_C * db;
                __nv_bfloat16 hA = __float2bfloat16(ap);
                __nv_bfloat16 hB = __float2bfloat16(bp);
                outHi[base]      = hA;
                outLo[base]      = __float2bfloat16(ap - __bfloat162float(hA));
                outHi[base + 64] = hB;
                outLo[base + 64] = __float2bfloat16(bp - __bfloat162float(hB));
            } else {
                float da1 = d1f[base], db1 = d1f[base + 64];
                float ap = a + DT_C * da1, bp = b + DT_C * db1;
                float r2 = ap * ap + bp * bp;
                float da2 = (MU_C - r2) * ap - om * bp + K_C * (ra - ap);
                float db2 = (MU_C - r2) * bp + om * ap + K_C * (rb - bp);
                float an = a + 0.5f * DT_C * (da1 + da2);
                float bn = b + 0.5f * DT_C * (db1 + db2);
                abf[base]      = an;
                abf[base + 64] = bn;
                if (flag) {
                    mixed[row * 64 + c] = MIX_C * attnv[row * 64 + c] + (1.0f - MIX_C) * an;
                } else {
                    __nv_bfloat16 hA = __float2bfloat16(an);
                    __nv_bfloat16 hB = __float2bfloat16(bn);
                    outHi[base]      = hA;
                    outLo[base]      = __float2bfloat16(an - __bfloat162float(hA));
                    outHi[base + 64] = hB;
                    outLo[base + 64] = __float2bfloat16(bn - __bfloat162float(hB));
                }
            }
        }
    }
}

// ---------------- fp32 -> bf16 hi/lo split ----------------
__global__ void splitW_kernel(const float* __restrict__ A,
                              __nv_bfloat16* __restrict__ hi, __nv_bfloat16* __restrict__ lo)
{
    size_t i = ((size_t)blockIdx.x * blockDim.x + threadIdx.x) * 4;
    float4 v = *reinterpret_cast<const float4*>(A + i);
    __nv_bfloat162 h0, h1, l0, l1;
    bf16_split2(v.x, v.y, h0, l0);
    bf16_split2(v.z, v.w, h1, l1);
    *reinterpret_cast<__nv_bfloat162*>(hi + i)     = h0;
    *reinterpret_cast<__nv_bfloat162*>(hi + i + 2) = h1;
    *reinterpret_cast<__nv_bfloat162*>(lo + i)     = l0;
    *reinterpret_cast<__nv_bfloat162*>(lo + i + 2) = l1;
}

// ---------------- LayerNorm (optional bf16 hi/lo outputs) ----------------
__global__ void ln_kernel(const float* __restrict__ x, const float* __restrict__ g,
                          const float* __restrict__ be, float* __restrict__ out,
                          __nv_bfloat16* __restrict__ outHi, __nv_bfloat16* __restrict__ outLo)
{
    __shared__ float sh[8];
    size_t row = blockIdx.x;
    int tid = threadIdx.x, lane = tid & 31, wid = tid >> 5;
    float4 v = reinterpret_cast<const float4*>(x + row * DD)[tid];

    float s = v.x + v.y + v.z + v.w;
#pragma unroll
    for (int o = 16; o; o >>= 1) s += __shfl_xor_sync(0xffffffffu, s, o);
    if (lane == 0) sh[wid] = s;
    __syncthreads();
    float tot = 0.f;
#pragma unroll
    for (int i = 0; i < 8; i++) tot += sh[i];
    float mean = tot * (1.0f / DD);

    float dx = v.x - mean, dy = v.y - mean, dz = v.z - mean, dw = v.w - mean;
    float s2 = dx*dx + dy*dy + dz*dz + dw*dw;
#pragma unroll
    for (int o = 16; o; o >>= 1) s2 += __shfl_xor_sync(0xffffffffu, s2, o);
    __syncthreads();
    if (lane == 0) sh[wid] = s2;
    __syncthreads();
    float tot2 = 0.f;
#pragma unroll
    for (int i = 0; i < 8; i++) tot2 += sh[i];
    float rstd = rsqrtf(tot2 * (1.0f / DD) + 1e-5f);

    float4 gv = reinterpret_cast<const float4*>(g)[tid];
    float4 bv = reinterpret_cast<const float4*>(be)[tid];
    float4 o4;
    o4.x = dx * rstd * gv.x + bv.x;
    o4.y = dy * rstd * gv.y + bv.y;
    o4.z = dz * rstd * gv.z + bv.z;
    o4.w = dw * rstd * gv.w + bv.w;
    reinterpret_cast<float4*>(out + row * DD)[tid] = o4;
    if (outHi) {
        size_t i = row * DD + tid * 4;
        __nv_bfloat162 h0, h1, l0, l1;
        bf16_split2(o4.x, o4.y, h0, l0);
        bf16_split2(o4.z, o4.w, h1, l1);
        *reinterpret_cast<__nv_bfloat162*>(outHi + i)     = h0;
        *reinterpret_cast<__nv_bfloat162*>(outHi + i + 2) = h1;
        *reinterpret_cast<__nv_bfloat162*>(outLo + i)     = l0;
        *reinterpret_cast<__nv_bfloat162*>(outLo + i + 2) = l1;
    }
}

// ---------------- QKV projection: one block per (s-tile, bh, w) ----------------
__global__ void qkv_kernel(const float* __restrict__ xn,
                           const float* __restrict__ Wq, const float* __restrict__ Wk,
                           const float* __restrict__ Wv,
                           __nv_bfloat16* __restrict__ qhi, __nv_bfloat16* __restrict__ qlo,
                           __nv_bfloat16* __restrict__ khi, __nv_bfloat16* __restrict__ klo,
                           float* __restrict__ ab,
                           __nv_bfloat16* __restrict__ abThi, __nv_bfloat16* __restrict__ abTlo)
{
    __shared__ float sx[64][65];
    __shared__ float sw[64][65];
    int bh = blockIdx.y, b = bh >> 4, h = bh & 15;
    int wsel = blockIdx.z;
    int s0 = blockIdx.x * 64;
    int tid = threadIdx.x;

    const float* W = (wsel == 0 ? Wq : (wsel == 1 ? Wk : Wv)) + h * 4096;
    for (int idx = tid; idx < 4096; idx += 256) {
        int r = idx >> 6, d = idx & 63;
        sx[r][d] = xn[((size_t)(b * SS + s0 + r)) * DD + h * 64 + d];
        sw[r][d] = W[idx];
    }
    __syncthreads();
    int e = tid & 63, rq = tid >> 6;
#pragma unroll
    for (int i = 0; i < 16; i++) {
        int r = rq * 16 + i;
        float acc = 0.f;
#pragma unroll
        for (int d = 0; d < 64; d++) acc = fmaf(sx[r][d], sw[d][e], acc);
        size_t srow = (size_t)bh * SS + s0 + r;
        __nv_bfloat16 hi = __float2bfloat16(acc);
        __nv_bfloat16 lo = __float2bfloat16(acc - __bfloat162float(hi));
        if (wsel == 0)      { qhi[srow * 64 + e] = hi; qlo[srow * 64 + e] = lo; }
        else if (wsel == 1) { khi[srow * 64 + e] = hi; klo[srow * 64 + e] = lo; }
        else {
            ab[srow * 128 + e] = acc; ab[srow * 128 + 64 + e] = 0.f;
            abThi[srow * 128 + e] = hi; abTlo[srow * 128 + e] = lo;
            abThi[srow * 128 + 64 + e] = __float2bfloat16(0.f);
            abTlo[srow * 128 + 64 + e] = __float2bfloat16(0.f);
        }
    }
}

// ---------------- fused softmax + bf16 split ----------------
__global__ void softmax_split_kernel(const float* __restrict__ S,
                                     __nv_bfloat16* __restrict__ Ahi,
                                     __nv_bfloat16* __restrict__ Alo)
{
    __shared__ float sh[8];
    size_t row = blockIdx.x;
    const float* p = S + row * (size_t)SS;
    int tid = threadIdx.x, lane = tid & 31, wid = tid >> 5;

    float4 v0 = reinterpret_cast<const float4*>(p)[tid];
    float4 v1 = reinterpret_cast<const float4*>(p)[tid + 256];
    const float sc = 0.125f;
    v0.x *= sc; v0.y *= sc; v0.z *= sc; v0.w *= sc;
    v1.x *= sc; v1.y *= sc; v1.z *= sc; v1.w *= sc;

    float mx = fmaxf(fmaxf(fmaxf(v0.x, v0.y), fmaxf(v0.z, v0.w)),
                     fmaxf(fmaxf(v1.x, v1.y), fmaxf(v1.z, v1.w)));
#pragma unroll
    for (int o = 16; o; o >>= 1) mx = fmaxf(mx, __shfl_xor_sync(0xffffffffu, mx, o));
    if (lane == 0) sh[wid] = mx;
    __syncthreads();
    float m = sh[0];
#pragma unroll
    for (int i = 1; i < 8; i++) m = fmaxf(m, sh[i]);

    v0.x = expf(v0.x - m); v0.y = expf(v0.y - m);
    v0.z = expf(v0.z - m); v0.w = expf(v0.w - m);
    v1.x = expf(v1.x - m); v1.y = expf(v1.y - m);
    v1.z = expf(v1.z - m); v1.w = expf(v1.w - m);

    float s = v0.x + v0.y + v0.z + v0.w + v1.x + v1.y + v1.z + v1.w;
#pragma unroll
    for (int o = 16; o; o >>= 1) s += __shfl_xor_sync(0xffffffffu, s, o);
    __syncthreads();
    if (lane == 0) sh[wid] = s;
    __syncthreads();
    float tot = 0.f;
#pragma unroll
    for (int i = 0; i < 8; i++) tot += sh[i];
    float inv = 1.0f / tot;

    v0.x *= inv; v0.y *= inv; v0.z *= inv; v0.w *= inv;
    v1.x *= inv; v1.y *= inv; v1.z *= inv; v1.w *= inv;

    size_t ob = row * (size_t)SS;
    auto emit = [&](size_t off, float a, float b) {
        __nv_bfloat162 h, l;
        bf16_split2(a, b, h, l);
        *reinterpret_cast<__nv_bfloat162*>(Ahi + ob + off) = h;
        *reinterpret_cast<__nv_bfloat162*>(Alo + ob + off) = l;
    };
    emit(tid * 4 + 0, v0.x, v0.y);
    emit(tid * 4 + 2, v0.z, v0.w);
    emit((tid + 256) * 4 + 0, v1.x, v1.y);
    emit((tid + 256) * 4 + 2, v1.z, v1.w);
}

// ---------------- head projection + residual ----------------
__global__ void headout_kernel(const float* __restrict__ mix, const float* __restrict__ Wo,
                               const float* __restrict__ x, float* __restrict__ x1)
{
    __shared__ float sx[64][65];
    __shared__ float sw[64][65];
    int bh = blockIdx.y, b = bh >> 4, h = bh & 15;
    int s0 = blockIdx.x * 64;
    int tid = threadIdx.x;

    for (int idx = tid; idx < 4096; idx += 256) {
        int r = idx >> 6, d = idx & 63;
        sx[r][d] = mix[((size_t)bh * SS + s0 + r) * 64 + d];
        sw[r][d] = Wo[h * 4096 + idx];
    }
    __syncthreads();
    int e = tid & 63, rq = tid >> 6;
#pragma unroll
    for (int i = 0; i < 16; i++) {
        int r = rq * 16 + i;
        float acc = 0.f;
#pragma unroll
        for (int d = 0; d < 64; d++) acc = fmaf(sx[r][d], sw[d][e], acc);
        size_t o = ((size_t)(b * SS + s0 + r)) * DD + h * 64 + e;
        x1[o] = x[o] + acc;
    }
}

// ---------------- host side ----------------
extern "C" void kernel_launch(void* const* d_in, const int* in_sizes, int n_in,
                              void* d_out, int out_size)
{
    const float* x   = (const float*)d_in[0];
    const float* Wq  = (const float*)d_in[1];
    const float* Wk  = (const float*)d_in[2];
    const float* Wv  = (const float*)d_in[3];
    const float* Wo  = (const float*)d_in[4];
    const float* om  = (const float*)d_in[5];
    const float* g1  = (const float*)d_in[6];
    const float* be1 = (const float*)d_in[7];
    const float* g2  = (const float*)d_in[8];
    const float* be2 = (const float*)d_in[9];
    const float* W1  = (const float*)d_in[10];
    const float* bf1 = (const float*)d_in[11];
    const float* W2  = (const float*)d_in[12];
    const float* bf2 = (const float*)d_in[13];
    float* out = (float*)d_out;
    (void)in_sizes; (void)n_in; (void)out_size;

    float *S_, *xn, *ab, *d1, *attnv, *mixb, *x1;
    __nv_bfloat16 *Ahi, *Alo, *xnhi, *xnlo, *qhi, *qlo, *khi, *klo;
    __nv_bfloat16 *abThi, *abTlo, *pThi, *pTlo, *ffhi, *fflo;
    __nv_bfloat16 *W1hi, *W1lo, *W2hi, *W2lo;
    cudaGetSymbolAddress((void**)&S_,    g_S);
    cudaGetSymbolAddress((void**)&Ahi,   g_Ahi);
    cudaGetSymbolAddress((void**)&Alo,   g_Alo);
    cudaGetSymbolAddress((void**)&xn,    g_xn);
    cudaGetSymbolAddress((void**)&xnhi,  g_xnhi);
    cudaGetSymbolAddress((void**)&xnlo,  g_xnlo);
    cudaGetSymbolAddress((void**)&qhi,   g_qhi);
    cudaGetSymbolAddress((void**)&qlo,   g_qlo);
    cudaGetSymbolAddress((void**)&khi,   g_khi);
    cudaGetSymbolAddress((void**)&klo,   g_klo);
    cudaGetSymbolAddress((void**)&ab,    g_ab);
    cudaGetSymbolAddress((void**)&d1,    g_d1);
    cudaGetSymbolAddress((void**)&abThi, g_abThi);
    cudaGetSymbolAddress((void**)&abTlo, g_abTlo);
    cudaGetSymbolAddress((void**)&pThi,  g_pThi);
    cudaGetSymbolAddress((void**)&pTlo,  g_pTlo);
    cudaGetSymbolAddress((void**)&attnv, g_attnv);
    cudaGetSymbolAddress((void**)&mixb,  g_mix);
    cudaGetSymbolAddress((void**)&x1,    g_x1);
    cudaGetSymbolAddress((void**)&ffhi,  g_ffhi);
    cudaGetSymbolAddress((void**)&fflo,  g_fflo);
    cudaGetSymbolAddress((void**)&W1hi,  g_W1hi);
    cudaGetSymbolAddress((void**)&W1lo,  g_W1lo);
    cudaGetSymbolAddress((void**)&W2hi,  g_W2hi);
    cudaGetSymbolAddress((void**)&W2lo,  g_W2lo);

    cudaFuncSetAttribute(hgemm_kernel<true, 0>,
                         cudaFuncAttributeMaxDynamicSharedMemorySize, HSMEM);
    cudaFuncSetAttribute(hgemm_kernel<false, 0>,
                         cudaFuncAttributeMaxDynamicSharedMemorySize, HSMEM);
    cudaFuncSetAttribute(hgemm_kernel<true, 1>,
                         cudaFuncAttributeMaxDynamicSharedMemorySize, HSMEM);
    cudaFuncSetAttribute(hgemm_kernel<true, 2>,
                         cudaFuncAttributeMaxDynamicSharedMemorySize, HSMEM);

    const long long sQK = (long long)SS * 64;
    const long long sAA = (long long)SS * SS;
    const long long sAB = (long long)SS * 128;

    splitW_kernel<<<(unsigned)((size_t)DD * DFFC / 1024), 256>>>(W1, W1hi, W1lo);
    splitW_kernel<<<(unsigned)((size_t)DFFC * DD / 1024), 256>>>(W2, W2hi, W2lo);

    // 1. LN1
    ln_kernel<<<NTOK, 256>>>(x, g1, be1, xn, nullptr, nullptr);
    // 2. QKV (3-way parallel over weights)
    qkv_kernel<<<dim3(SS / 64, BH, 3), 256>>>(xn, Wq, Wk, Wv, qhi, qlo, khi, klo,
                                              ab, abThi, abTlo);
    // 3. scores: S = q @ k^T
    hgemm_kernel<false, 0><<<dim3(16, 16, BH), 256, HSMEM>>>(
        qhi, qlo, khi, klo, 64, 64, 64, SS, sQK, sQK, sAA,
        S_, nullptr, nullptr, nullptr, nullptr, 0,
        nullptr, nullptr, nullptr, nullptr, nullptr, 0);
    // 4. softmax + split
    softmax_split_kernel<<<BH * SS, 256>>>(S_, Ahi, Alo);
    // 5. Heun loop with fused ODE epilogues
    for (int st = 0; st < 5; st++) {
        hgemm_kernel<true, 1><<<dim3(1, 16, BH), 256, HSMEM>>>(
            Ahi, Alo, abThi, abTlo, SS, SS, 128, 128, sAA, sAB, sAB,
            nullptr, pThi, pTlo, nullptr, nullptr, 0,
            om, ab, d1, attnv, nullptr, st == 0 ? 1 : 0);
        hgemm_kernel<true, 2><<<dim3(1, 16, BH), 256, HSMEM>>>(
            Ahi, Alo, pThi, pTlo, SS, SS, 128, 128, sAA, sAB, sAB,
            nullptr, abThi, abTlo, nullptr, nullptr, 0,
            om, ab, d1, attnv, mixb, st == 4 ? 1 : 0);
    }
    // 6. head projection + residual
    headout_kernel<<<dim3(SS / 64, BH), 256>>>(mixb, Wo, x, x1);
    // 7. LN2
    ln_kernel<<<NTOK, 256>>>(x1, g2, be2, xn, xnhi, xnlo);
    // 8. FFN1
    hgemm_kernel<true, 0><<<dim3(16, 32, 1), 256, HSMEM>>>(
        xnhi, xnlo, W1hi, W1lo, DD, DD, DFFC, DFFC, 0, 0, 0,
        nullptr, ffhi, fflo, bf1, nullptr, 1,
        nullptr, nullptr, nullptr, nullptr, nullptr, 0);
    // 9. FFN2
    hgemm_kernel<true, 0><<<dim3(8, 32, 1), 256, HSMEM>>>(
        ffhi, fflo, W2hi, W2lo, DFFC, DFFC, DD, DD, 0, 0, 0,
        out, nullptr, nullptr, bf2, x1, 0,
        nullptr, nullptr, nullptr, nullptr, nullptr, 0);
}

// round 8
// speedup vs baseline: 1.1217x; 1.1217x over previous
#include <cuda_runtime.h>
#include <cuda_bf16.h>
#include <math.h>
#include <stddef.h>
#include <stdint.h>

// ---------------- problem constants ----------------
#define BB   2
#define SS   2048
#define DD   1024
#define HH   16
#define HDIM 64
#define DFFC 2048
#define BH   (BB*HH)
#define NTOK (BB*SS)

#define MU_C   1.0f
#define K_C    3.0f
#define DT_C   0.02f
#define MIX_C  0.3f
#define CA_C   0.9950041652780258f
#define SA_C   0.09983341664682815f

// ---------------- scratch ----------------
__device__ float g_S [(size_t)BH * SS * SS];
__device__ __nv_bfloat16 g_Ahi[(size_t)BH * SS * SS];
__device__ __nv_bfloat16 g_Alo[(size_t)BH * SS * SS];
__device__ float g_xn  [(size_t)NTOK * DD];
__device__ __nv_bfloat16 g_xnhi[(size_t)NTOK * DD];
__device__ __nv_bfloat16 g_xnlo[(size_t)NTOK * DD];
__device__ __nv_bfloat16 g_qhi[(size_t)BH * SS * 64];
__device__ __nv_bfloat16 g_qlo[(size_t)BH * SS * 64];
__device__ __nv_bfloat16 g_khi[(size_t)BH * SS * 64];
__device__ __nv_bfloat16 g_klo[(size_t)BH * SS * 64];
__device__ float g_ab  [(size_t)BH * SS * 128];
__device__ float g_d1  [(size_t)BH * SS * 128];
__device__ __nv_bfloat16 g_abThi[(size_t)BH * SS * 128];
__device__ __nv_bfloat16 g_abTlo[(size_t)BH * SS * 128];
__device__ __nv_bfloat16 g_pThi [(size_t)BH * SS * 128];
__device__ __nv_bfloat16 g_pTlo [(size_t)BH * SS * 128];
__device__ float g_attnv[(size_t)BH * SS * 64];
__device__ float g_mix  [(size_t)BH * SS * 64];
__device__ float g_x1   [(size_t)NTOK * DD];
__device__ __nv_bfloat16 g_ffhi[(size_t)NTOK * DFFC];
__device__ __nv_bfloat16 g_fflo[(size_t)NTOK * DFFC];
__device__ __nv_bfloat16 g_W1hi[(size_t)DD * DFFC];
__device__ __nv_bfloat16 g_W1lo[(size_t)DD * DFFC];
__device__ __nv_bfloat16 g_W2hi[(size_t)DFFC * DD];
__device__ __nv_bfloat16 g_W2lo[(size_t)DFFC * DD];

// ---------------- low-level helpers ----------------
__device__ __forceinline__ uint32_t smem_u32(const void* p) {
    uint32_t a;
    asm("{ .reg .u64 t; cvta.to.shared.u64 t, %1; cvt.u32.u64 %0, t; }" : "=r"(a) : "l"(p));
    return a;
}
__device__ __forceinline__ void cp16(uint32_t s, const void* g) {
    asm volatile("cp.async.cg.shared.global [%0], [%1], 16;" :: "r"(s), "l"(g));
}
__device__ __forceinline__ void cp_commit() {
    asm volatile("cp.async.commit_group;" ::: "memory");
}
template <int N>
__device__ __forceinline__ void cp_wait() {
    asm volatile("cp.async.wait_group %0;" :: "n"(N) : "memory");
}
__device__ __forceinline__ void ldm_x4(uint32_t* r, uint32_t addr) {
    asm volatile("ldmatrix.sync.aligned.m8n8.x4.shared.b16 {%0,%1,%2,%3}, [%4];"
        : "=r"(r[0]), "=r"(r[1]), "=r"(r[2]), "=r"(r[3]) : "r"(addr));
}
__device__ __forceinline__ void ldm_x4t(uint32_t* r, uint32_t addr) {
    asm volatile("ldmatrix.sync.aligned.m8n8.x4.trans.shared.b16 {%0,%1,%2,%3}, [%4];"
        : "=r"(r[0]), "=r"(r[1]), "=r"(r[2]), "=r"(r[3]) : "r"(addr));
}
__device__ __forceinline__ void mma_bf16(float* c, const uint32_t* a, const uint32_t* b) {
    asm volatile("mma.sync.aligned.m16n8k16.row.col.f32.bf16.bf16.f32 "
        "{%0,%1,%2,%3}, {%4,%5,%6,%7}, {%8,%9}, {%0,%1,%2,%3};"
        : "+f"(c[0]), "+f"(c[1]), "+f"(c[2]), "+f"(c[3])
        : "r"(a[0]), "r"(a[1]), "r"(a[2]), "r"(a[3]), "r"(b[0]), "r"(b[1]));
}
__device__ __forceinline__ float gelu_tanh(float x) {
    float x3 = x * x * x;
    float t  = tanhf(0.7978845608028654f * (x + 0.044715f * x3));
    return 0.5f * x * (1.0f + t);
}
__device__ __forceinline__ void bf16_split2(float a, float b,
                                            __nv_bfloat162& h, __nv_bfloat162& l) {
    h.x = __float2bfloat16(a); h.y = __float2bfloat16(b);
    l.x = __float2bfloat16(a - __bfloat162float(h.x));
    l.y = __float2bfloat16(b - __bfloat162float(h.y));
}

// ---------------- unified 3-product bf16 HMMA GEMM, fusable ODE epilogue ----------------
// EPI: 0 = plain C output; 1 = fused ode_ew1; 2 = fused ode_ew2.
#define AST 72
#define BSTN 72
#define BSTT 136
#define OFF_AL 18432
#define OFF_BH 36864
#define OFF_BL 55296
#define STAGE_BYTES 73728
#define HSMEM (2 * STAGE_BYTES)     // 147456 (proven R5 config)

template<bool TRANSB, int EPI>
__global__ void __launch_bounds__(256, 1)
hgemm_kernel(const __nv_bfloat16* __restrict__ Ahi, const __nv_bfloat16* __restrict__ Alo,
             const __nv_bfloat16* __restrict__ Bhi, const __nv_bfloat16* __restrict__ Blo,
             int K, int lda, int ldb, int ldc,
             long long sA, long long sB, long long sC,
             float* __restrict__ outF,
             __nv_bfloat16* __restrict__ outHi, __nv_bfloat16* __restrict__ outLo,
             const float* __restrict__ bias, const float* __restrict__ addsrc, int do_gelu,
             const float* __restrict__ omg, float* __restrict__ abf,
             float* __restrict__ d1f, float* __restrict__ attnv,
             float* __restrict__ mixed, int flag)
{
    extern __shared__ char smem[];
    const uint32_t sb = smem_u32(smem);
    const int tid = threadIdx.x;
    const int lane = tid & 31, w = tid >> 5;
    const int wm = w >> 2, wn = w & 3;
    const int n0 = blockIdx.x * 128;
    const int m0 = blockIdx.y * 128;
    const long long bz = blockIdx.z;

    Ahi += bz * sA; Alo += bz * sA;
    Bhi += bz * sB; Blo += bz * sB;

    float acc[4][4][4];
#pragma unroll
    for (int i = 0; i < 4; i++)
#pragma unroll
        for (int j = 0; j < 4; j++)
#pragma unroll
            for (int r = 0; r < 4; r++) acc[i][j][r] = 0.f;

    auto issue = [&](int chunk, int buf) {
        const int k0 = chunk << 6;
        const uint32_t st = sb + buf * STAGE_BYTES;
        {
            const int row = tid >> 3, col = (tid & 7) * 8;
            const __nv_bfloat16* gH = Ahi + (size_t)(m0 + row) * lda + k0 + col;
            const __nv_bfloat16* gL = Alo + (size_t)(m0 + row) * lda + k0 + col;
            uint32_t s = st + (row * AST + col) * 2;
#pragma unroll
            for (int j = 0; j < 4; j++) {
                cp16(s + j * 32 * (AST * 2),          gH + (size_t)j * 32 * lda);
                cp16(s + OFF_AL + j * 32 * (AST * 2), gL + (size_t)j * 32 * lda);
            }
        }
        if (TRANSB) {
            const int rk = tid >> 2, col = (tid & 3) * 8;
            const __nv_bfloat16* gH = Bhi + (size_t)(k0 + rk) * ldb + n0 + col;
            const __nv_bfloat16* gL = Blo + (size_t)(k0 + rk) * ldb + n0 + col;
            uint32_t s = st + OFF_BH + (rk * BSTT + col) * 2;
#pragma unroll
            for (int j = 0; j < 4; j++) {
                cp16(s + j * 64,                     gH + j * 32);
                cp16(s + (OFF_BL - OFF_BH) + j * 64, gL + j * 32);
            }
        } else {
            const int rn = tid >> 3, col = (tid & 7) * 8;
            const __nv_bfloat16* gH = Bhi + (size_t)(n0 + rn) * ldb + k0 + col;
            const __nv_bfloat16* gL = Blo + (size_t)(n0 + rn) * ldb + k0 + col;
            uint32_t s = st + OFF_BH + (rn * BSTN + col) * 2;
#pragma unroll
            for (int j = 0; j < 4; j++) {
                cp16(s + j * 32 * (BSTN * 2),                     gH + (size_t)j * 32 * ldb);
                cp16(s + (OFF_BL - OFF_BH) + j * 32 * (BSTN * 2), gL + (size_t)j * 32 * ldb);
            }
        }
        cp_commit();
    };

    auto compute = [&](int buf) {
        const uint32_t st = sb + buf * STAGE_BYTES;
#pragma unroll
        for (int k16 = 0; k16 < 4; k16++) {
            uint32_t afrH[4][4], afrL[4][4], bfrH[4][2], bfrL[4][2];
#pragma unroll
            for (int ms = 0; ms < 4; ms++) {
                int row = wm * 64 + ms * 16 + (lane & 15);
                int col = k16 * 16 + (lane >> 4) * 8;
                ldm_x4(afrH[ms], st + (row * AST + col) * 2);
                ldm_x4(afrL[ms], st + OFF_AL + (row * AST + col) * 2);
            }
            if (TRANSB) {
                const int mat = lane >> 3, rr = lane & 7;
#pragma unroll
                for (int p = 0; p < 2; p++) {
                    int rk = k16 * 16 + (mat & 1) * 8 + rr;
                    int cn = wn * 32 + p * 16 + (mat >> 1) * 8;
                    ldm_x4t(&bfrH[p * 2][0], st + OFF_BH + (rk * BSTT + cn) * 2);
                    ldm_x4t(&bfrL[p * 2][0], st + OFF_BL + (rk * BSTT + cn) * 2);
                }
            } else {
                const int mat = lane >> 3, rr = lane & 7;
#pragma unroll
                for (int p = 0; p < 2; p++) {
                    int rn = wn * 32 + p * 16 + (mat >> 1) * 8 + rr;
                    int ck = k16 * 16 + (mat & 1) * 8;
                    ldm_x4(&bfrH[p * 2][0], st + OFF_BH + (rn * BSTN + ck) * 2);
                    ldm_x4(&bfrL[p * 2][0], st + OFF_BL + (rn * BSTN + ck) * 2);
                }
            }
#pragma unroll
            for (int ms = 0; ms < 4; ms++)
#pragma unroll
                for (int ns = 0; ns < 4; ns++) {
                    mma_bf16(acc[ms][ns], afrH[ms], bfrH[ns]);
                    mma_bf16(acc[ms][ns], afrH[ms], bfrL[ns]);
                    mma_bf16(acc[ms][ns], afrL[ms], bfrH[ns]);
                }
        }
    };

    const int nchunk = K >> 6;
    issue(0, 0);
#pragma unroll 1
    for (int i = 0; i < nchunk; i++) {
        if (i + 1 < nchunk) { issue(i + 1, (i + 1) & 1); cp_wait<1>(); }
        else                { cp_wait<0>(); }
        __syncthreads();
        compute(i & 1);
        __syncthreads();
    }

    if (EPI == 0) {
        const long long cb = bz * sC;
#pragma unroll
        for (int ms = 0; ms < 4; ms++) {
#pragma unroll
            for (int ns = 0; ns < 4; ns++) {
                int r0 = wm * 64 + ms * 16 + (lane >> 2);
                int c0 = n0 + wn * 32 + ns * 8 + (lane & 3) * 2;
#pragma unroll
                for (int half = 0; half < 2; half++) {
                    long long r = m0 + r0 + half * 8;
                    float vx = acc[ms][ns][half * 2 + 0];
                    float vy = acc[ms][ns][half * 2 + 1];
                    if (bias)   { vx += bias[c0]; vy += bias[c0 + 1]; }
                    if (addsrc) {
                        float2 s = *reinterpret_cast<const float2*>(addsrc + r * ldc + c0);
                        vx += s.x; vy += s.y;
                    }
                    if (do_gelu) { vx = gelu_tanh(vx); vy = gelu_tanh(vy); }
                    long long o = cb + r * ldc + c0;
                    if (outF)
                        *reinterpret_cast<float2*>(outF + o) = make_float2(vx, vy);
                    if (outHi) {
                        __nv_bfloat162 h, l;
                        bf16_split2(vx, vy, h, l);
                        *reinterpret_cast<__nv_bfloat162*>(outHi + o) = h;
                        *reinterpret_cast<__nv_bfloat162*>(outLo + o) = l;
                    }
                }
            }
        }
    } else {
        // stage z tile into smem, then MLP-batched fused ODE elementwise
        float* zsm = reinterpret_cast<float*>(smem);
#pragma unroll
        for (int ms = 0; ms < 4; ms++)
#pragma unroll
            for (int ns = 0; ns < 4; ns++) {
                int r0 = wm * 64 + ms * 16 + (lane >> 2);
                int c0 = wn * 32 + ns * 8 + (lane & 3) * 2;
                zsm[r0 * 132 + c0]     = acc[ms][ns][0];
                zsm[r0 * 132 + c0 + 1] = acc[ms][ns][1];
                zsm[(r0 + 8) * 132 + c0]     = acc[ms][ns][2];
                zsm[(r0 + 8) * 132 + c0 + 1] = acc[ms][ns][3];
            }
        __syncthreads();
        const int h = (int)(bz & 15);
        // 4096 column-pairs; 16 per thread; 2 batches of 8 (batched loads for MLP)
#pragma unroll 1
        for (int ib = 0; ib < 2; ib++) {
            float2 a2[8], b2[8], d1a[8], d1b[8];
            int r8[8], cp8[8];
            size_t base8[8];
#pragma unroll
            for (int j = 0; j < 8; j++) {
                int lin = (ib * 8 + j) * 256 + tid;
                int r = lin >> 5, cp = (lin & 31) * 2;
                r8[j] = r; cp8[j] = cp;
                size_t base = ((size_t)bz * SS + m0 + r) * 128 + cp;
                base8[j] = base;
                a2[j] = *reinterpret_cast<const float2*>(abf + base);
                b2[j] = *reinterpret_cast<const float2*>(abf + base + 64);
                if (EPI == 2) {
                    d1a[j] = *reinterpret_cast<const float2*>(d1f + base);
                    d1b[j] = *reinterpret_cast<const float2*>(d1f + base + 64);
                }
            }
#pragma unroll
            for (int j = 0; j < 8; j++) {
                int r = r8[j], cp = cp8[j];
                size_t base = base8[j];
                size_t row = (size_t)bz * SS + m0 + r;
                float2 om2 = *reinterpret_cast<const float2*>(omg + h * 64 + cp);
                float za0 = zsm[r * 132 + cp],     za1 = zsm[r * 132 + cp + 1];
                float zb0 = zsm[r * 132 + cp + 64], zb1 = zsm[r * 132 + cp + 65];
                float ra0 = za0 * CA_C + zb0 * SA_C, rb0 = zb0 * CA_C - za0 * SA_C;
                float ra1 = za1 * CA_C + zb1 * SA_C, rb1 = zb1 * CA_C - za1 * SA_C;
                if (EPI == 1) {
                    if (flag)
                        *reinterpret_cast<float2*>(attnv + row * 64 + cp) =
                            make_float2(za0, za1);
                    float r20 = a2[j].x * a2[j].x + b2[j].x * b2[j].x;
                    float r21 = a2[j].y * a2[j].y + b2[j].y * b2[j].y;
                    float da0 = (MU_C - r20) * a2[j].x - om2.x * b2[j].x + K_C * (ra0 - a2[j].x);
                    float db0 = (MU_C - r20) * b2[j].x + om2.x * a2[j].x + K_C * (rb0 - b2[j].x);
                    float da1 = (MU_C - r21) * a2[j].y - om2.y * b2[j].y + K_C * (ra1 - a2[j].y);
                    float db1 = (MU_C - r21) * b2[j].y + om2.y * a2[j].y + K_C * (rb1 - b2[j].y);
                    *reinterpret_cast<float2*>(d1f + base)      = make_float2(da0, da1);
                    *reinterpret_cast<float2*>(d1f + base + 64) = make_float2(db0, db1);
                    float ap0 = a2[j].x + DT_C * da0, ap1 = a2[j].y + DT_C * da1;
                    float bp0 = b2[j].x + DT_C * db0, bp1 = b2[j].y + DT_C * db1;
                    __nv_bfloat162 hA, lA, hB, lB;
                    bf16_split2(ap0, ap1, hA, lA);
                    bf16_split2(bp0, bp1, hB, lB);
                    *reinterpret_cast<__nv_bfloat162*>(outHi + base)      = hA;
                    *reinterpret_cast<__nv_bfloat162*>(outLo + base)      = lA;
                    *reinterpret_cast<__nv_bfloat162*>(outHi + base + 64) = hB;
                    *reinterpret_cast<__nv_bfloat162*>(outLo + base + 64) = lB;
                } else {
                    float ap0 = a2[j].x + DT_C * d1a[j].x, ap1 = a2[j].y + DT_C * d1a[j].y;
                    float bp0 = b2[j].x + DT_C * d1b[j].x, bp1 = b2[j].y + DT_C * d1b[j].y;
                    float r20 = ap0 * ap0 + bp0 * bp0;
                    float r21 = ap1 * ap1 + bp1 * bp1;
                    float da20 = (MU_C - r20) * ap0 - om2.x * bp0 + K_C * (ra0 - ap0);
                    float db20 = (MU_C - r20) * bp0 + om2.x * ap0 + K_C * (rb0 - bp0);
                    float da21 = (MU_C - r21) * ap1 - om2.y * bp1 + K_C * (ra1 - ap1);
                    float db21 = (MU_C - r21) * bp1 + om2.y * ap1 + K_C * (rb1 - bp1);
                    float an0 = a2[j].x + 0.5f * DT_C * (d1a[j].x + da20);
                    float an1 = a2[j].y + 0.5f * DT_C * (d1a[j].y + da21);
                    float bn0 = b2[j].x + 0.5f * DT_C * (d1b[j].x + db20);
                    float bn1 = b2[j].y + 0.5f * DT_C * (d1b[j].y + db21);
                    *reinterpret_cast<float2*>(abf + base)      = make_float2(an0, an1);
                    *reinterpret_cast<float2*>(abf + base + 64) = make_float2(bn0, bn1);
                    if (flag) {
                        float2 av = *reinterpret_cast<const float2*>(attnv + row * 64 + cp);
                        *reinterpret_cast<float2*>(mixed + row * 64 + cp) =
                            make_float2(MIX_C * av.x + (1.0f - MIX_C) * an0,
                                        MIX_C * av.y + (1.0f - MIX_C) * an1);
                    } else {
                        __nv_bfloat162 hA, lA, hB, lB;
                        bf16_split2(an0, an1, hA, lA);
                        bf16_split2(bn0, bn1, hB, lB);
                        *reinterpret_cast<__nv_bfloat162*>(outHi + base)      = hA;
                        *reinterpret_cast<__nv_bfloat162*>(outLo + base)      = lA;
                        *reinterpret_cast<__nv_bfloat162*>(outHi + base + 64) = hB;
                        *reinterpret_cast<__nv_bfloat162*>(outLo + base + 64) = lB;
                    }
                }
            }
        }
    }
}

// ---------------- fp32 -> bf16 hi/lo split ----------------
__global__ void splitW_kernel(const float* __restrict__ A,
                              __nv_bfloat16* __restrict__ hi, __nv_bfloat16* __restrict__ lo)
{
    size_t i = ((size_t)blockIdx.x * blockDim.x + threadIdx.x) * 4;
    float4 v = *reinterpret_cast<const float4*>(A + i);
    __nv_bfloat162 h0, h1, l0, l1;
    bf16_split2(v.x, v.y, h0, l0);
    bf16_split2(v.z, v.w, h1, l1);
    *reinterpret_cast<__nv_bfloat162*>(hi + i)     = h0;
    *reinterpret_cast<__nv_bfloat162*>(hi + i + 2) = h1;
    *reinterpret_cast<__nv_bfloat162*>(lo + i)     = l0;
    *reinterpret_cast<__nv_bfloat162*>(lo + i + 2) = l1;
}

// ---------------- LayerNorm ----------------
__global__ void ln_kernel(const float* __restrict__ x, const float* __restrict__ g,
                          const float* __restrict__ be, float* __restrict__ out,
                          __nv_bfloat16* __restrict__ outHi, __nv_bfloat16* __restrict__ outLo)
{
    __shared__ float sh[8];
    size_t row = blockIdx.x;
    int tid = threadIdx.x, lane = tid & 31, wid = tid >> 5;
    float4 v = reinterpret_cast<const float4*>(x + row * DD)[tid];

    float s = v.x + v.y + v.z + v.w;
#pragma unroll
    for (int o = 16; o; o >>= 1) s += __shfl_xor_sync(0xffffffffu, s, o);
    if (lane == 0) sh[wid] = s;
    __syncthreads();
    float tot = 0.f;
#pragma unroll
    for (int i = 0; i < 8; i++) tot += sh[i];
    float mean = tot * (1.0f / DD);

    float dx = v.x - mean, dy = v.y - mean, dz = v.z - mean, dw = v.w - mean;
    float s2 = dx*dx + dy*dy + dz*dz + dw*dw;
#pragma unroll
    for (int o = 16; o; o >>= 1) s2 += __shfl_xor_sync(0xffffffffu, s2, o);
    __syncthreads();
    if (lane == 0) sh[wid] = s2;
    __syncthreads();
    float tot2 = 0.f;
#pragma unroll
    for (int i = 0; i < 8; i++) tot2 += sh[i];
    float rstd = rsqrtf(tot2 * (1.0f / DD) + 1e-5f);

    float4 gv = reinterpret_cast<const float4*>(g)[tid];
    float4 bv = reinterpret_cast<const float4*>(be)[tid];
    float4 o4;
    o4.x = dx * rstd * gv.x + bv.x;
    o4.y = dy * rstd * gv.y + bv.y;
    o4.z = dz * rstd * gv.z + bv.z;
    o4.w = dw * rstd * gv.w + bv.w;
    reinterpret_cast<float4*>(out + row * DD)[tid] = o4;
    if (outHi) {
        size_t i = row * DD + tid * 4;
        __nv_bfloat162 h0, h1, l0, l1;
        bf16_split2(o4.x, o4.y, h0, l0);
        bf16_split2(o4.z, o4.w, h1, l1);
        *reinterpret_cast<__nv_bfloat162*>(outHi + i)     = h0;
        *reinterpret_cast<__nv_bfloat162*>(outHi + i + 2) = h1;
        *reinterpret_cast<__nv_bfloat162*>(outLo + i)     = l0;
        *reinterpret_cast<__nv_bfloat162*>(outLo + i + 2) = l1;
    }
}

// ---------------- QKV projection (3-way parallel) ----------------
__global__ void qkv_kernel(const float* __restrict__ xn,
                           const float* __restrict__ Wq, const float* __restrict__ Wk,
                           const float* __restrict__ Wv,
                           __nv_bfloat16* __restrict__ qhi, __nv_bfloat16* __restrict__ qlo,
                           __nv_bfloat16* __restrict__ khi, __nv_bfloat16* __restrict__ klo,
                           float* __restrict__ ab,
                           __nv_bfloat16* __restrict__ abThi, __nv_bfloat16* __restrict__ abTlo)
{
    __shared__ float sx[64][65];
    __shared__ float sw[64][65];
    int bh = blockIdx.y, b = bh >> 4, h = bh & 15;
    int wsel = blockIdx.z;
    int s0 = blockIdx.x * 64;
    int tid = threadIdx.x;

    const float* W = (wsel == 0 ? Wq : (wsel == 1 ? Wk : Wv)) + h * 4096;
    for (int idx = tid; idx < 4096; idx += 256) {
        int r = idx >> 6, d = idx & 63;
        sx[r][d] = xn[((size_t)(b * SS + s0 + r)) * DD + h * 64 + d];
        sw[r][d] = W[idx];
    }
    __syncthreads();
    int e = tid & 63, rq = tid >> 6;
#pragma unroll
    for (int i = 0; i < 16; i++) {
        int r = rq * 16 + i;
        float acc = 0.f;
#pragma unroll
        for (int d = 0; d < 64; d++) acc = fmaf(sx[r][d], sw[d][e], acc);
        size_t srow = (size_t)bh * SS + s0 + r;
        __nv_bfloat16 hi = __float2bfloat16(acc);
        __nv_bfloat16 lo = __float2bfloat16(acc - __bfloat162float(hi));
        if (wsel == 0)      { qhi[srow * 64 + e] = hi; qlo[srow * 64 + e] = lo; }
        else if (wsel == 1) { khi[srow * 64 + e] = hi; klo[srow * 64 + e] = lo; }
        else {
            ab[srow * 128 + e] = acc; ab[srow * 128 + 64 + e] = 0.f;
            abThi[srow * 128 + e] = hi; abTlo[srow * 128 + e] = lo;
            abThi[srow * 128 + 64 + e] = __float2bfloat16(0.f);
            abTlo[srow * 128 + 64 + e] = __float2bfloat16(0.f);
        }
    }
}

// ---------------- fused softmax + bf16 split ----------------
__global__ void softmax_split_kernel(const float* __restrict__ S,
                                     __nv_bfloat16* __restrict__ Ahi,
                                     __nv_bfloat16* __restrict__ Alo)
{
    __shared__ float sh[8];
    size_t row = blockIdx.x;
    const float* p = S + row * (size_t)SS;
    int tid = threadIdx.x, lane = tid & 31, wid = tid >> 5;

    float4 v0 = reinterpret_cast<const float4*>(p)[tid];
    float4 v1 = reinterpret_cast<const float4*>(p)[tid + 256];
    const float sc = 0.125f;
    v0.x *= sc; v0.y *= sc; v0.z *= sc; v0.w *= sc;
    v1.x *= sc; v1.y *= sc; v1.z *= sc; v1.w *= sc;

    float mx = fmaxf(fmaxf(fmaxf(v0.x, v0.y), fmaxf(v0.z, v0.w)),
                     fmaxf(fmaxf(v1.x, v1.y), fmaxf(v1.z, v1.w)));
#pragma unroll
    for (int o = 16; o; o >>= 1) mx = fmaxf(mx, __shfl_xor_sync(0xffffffffu, mx, o));
    if (lane == 0) sh[wid] = mx;
    __syncthreads();
    float m = sh[0];
#pragma unroll
    for (int i = 1; i < 8; i++) m = fmaxf(m, sh[i]);

    v0.x = expf(v0.x - m); v0.y = expf(v0.y - m);
    v0.z = expf(v0.z - m); v0.w = expf(v0.w - m);
    v1.x = expf(v1.x - m); v1.y = expf(v1.y - m);
    v1.z = expf(v1.z - m); v1.w = expf(v1.w - m);

    float s = v0.x + v0.y + v0.z + v0.w + v1.x + v1.y + v1.z + v1.w;
#pragma unroll
    for (int o = 16; o; o >>= 1) s += __shfl_xor_sync(0xffffffffu, s, o);
    __syncthreads();
    if (lane == 0) sh[wid] = s;
    __syncthreads();
    float tot = 0.f;
#pragma unroll
    for (int i = 0; i < 8; i++) tot += sh[i];
    float inv = 1.0f / tot;

    v0.x *= inv; v0.y *= inv; v0.z *= inv; v0.w *= inv;
    v1.x *= inv; v1.y *= inv; v1.z *= inv; v1.w *= inv;

    size_t ob = row * (size_t)SS;
    auto emit = [&](size_t off, float a, float b) {
        __nv_bfloat162 h, l;
        bf16_split2(a, b, h, l);
        *reinterpret_cast<__nv_bfloat162*>(Ahi + ob + off) = h;
        *reinterpret_cast<__nv_bfloat162*>(Alo + ob + off) = l;
    };
    emit(tid * 4 + 0, v0.x, v0.y);
    emit(tid * 4 + 2, v0.z, v0.w);
    emit((tid + 256) * 4 + 0, v1.x, v1.y);
    emit((tid + 256) * 4 + 2, v1.z, v1.w);
}

// ---------------- head projection + residual ----------------
__global__ void headout_kernel(const float* __restrict__ mix, const float* __restrict__ Wo,
                               const float* __restrict__ x, float* __restrict__ x1)
{
    __shared__ float sx[64][65];
    __shared__ float sw[64][65];
    int bh = blockIdx.y, b = bh >> 4, h = bh & 15;
    int s0 = blockIdx.x * 64;
    int tid = threadIdx.x;

    for (int idx = tid; idx < 4096; idx += 256) {
        int r = idx >> 6, d = idx & 63;
        sx[r][d] = mix[((size_t)bh * SS + s0 + r) * 64 + d];
        sw[r][d] = Wo[h * 4096 + idx];
    }
    __syncthreads();
    int e = tid & 63, rq = tid >> 6;
#pragma unroll
    for (int i = 0; i < 16; i++) {
        int r = rq * 16 + i;
        float acc = 0.f;
#pragma unroll
        for (int d = 0; d < 64; d++) acc = fmaf(sx[r][d], sw[d][e], acc);
        size_t o = ((size_t)(b * SS + s0 + r)) * DD + h * 64 + e;
        x1[o] = x[o] + acc;
    }
}

// ---------------- host side ----------------
extern "C" void kernel_launch(void* const* d_in, const int* in_sizes, int n_in,
                              void* d_out, int out_size)
{
    const float* x   = (const float*)d_in[0];
    const float* Wq  = (const float*)d_in[1];
    const float* Wk  = (const float*)d_in[2];
    const float* Wv  = (const float*)d_in[3];
    const float* Wo  = (const float*)d_in[4];
    const float* om  = (const float*)d_in[5];
    const float* g1  = (const float*)d_in[6];
    const float* be1 = (const float*)d_in[7];
    const float* g2  = (const float*)d_in[8];
    const float* be2 = (const float*)d_in[9];
    const float* W1  = (const float*)d_in[10];
    const float* bf1 = (const float*)d_in[11];
    const float* W2  = (const float*)d_in[12];
    const float* bf2 = (const float*)d_in[13];
    float* out = (float*)d_out;
    (void)in_sizes; (void)n_in; (void)out_size;

    float *S_, *xn, *ab, *d1, *attnv, *mixb, *x1;
    __nv_bfloat16 *Ahi, *Alo, *xnhi, *xnlo, *qhi, *qlo, *khi, *klo;
    __nv_bfloat16 *abThi, *abTlo, *pThi, *pTlo, *ffhi, *fflo;
    __nv_bfloat16 *W1hi, *W1lo, *W2hi, *W2lo;
    cudaGetSymbolAddress((void**)&S_,    g_S);
    cudaGetSymbolAddress((void**)&Ahi,   g_Ahi);
    cudaGetSymbolAddress((void**)&Alo,   g_Alo);
    cudaGetSymbolAddress((void**)&xn,    g_xn);
    cudaGetSymbolAddress((void**)&xnhi,  g_xnhi);
    cudaGetSymbolAddress((void**)&xnlo,  g_xnlo);
    cudaGetSymbolAddress((void**)&qhi,   g_qhi);
    cudaGetSymbolAddress((void**)&qlo,   g_qlo);
    cudaGetSymbolAddress((void**)&khi,   g_khi);
    cudaGetSymbolAddress((void**)&klo,   g_klo);
    cudaGetSymbolAddress((void**)&ab,    g_ab);
    cudaGetSymbolAddress((void**)&d1,    g_d1);
    cudaGetSymbolAddress((void**)&abThi, g_abThi);
    cudaGetSymbolAddress((void**)&abTlo, g_abTlo);
    cudaGetSymbolAddress((void**)&pThi,  g_pThi);
    cudaGetSymbolAddress((void**)&pTlo,  g_pTlo);
    cudaGetSymbolAddress((void**)&attnv, g_attnv);
    cudaGetSymbolAddress((void**)&mixb,  g_mix);
    cudaGetSymbolAddress((void**)&x1,    g_x1);
    cudaGetSymbolAddress((void**)&ffhi,  g_ffhi);
    cudaGetSymbolAddress((void**)&fflo,  g_fflo);
    cudaGetSymbolAddress((void**)&W1hi,  g_W1hi);
    cudaGetSymbolAddress((void**)&W1lo,  g_W1lo);
    cudaGetSymbolAddress((void**)&W2hi,  g_W2hi);
    cudaGetSymbolAddress((void**)&W2lo,  g_W2lo);

    cudaFuncSetAttribute(hgemm_kernel<true, 0>,
                         cudaFuncAttributeMaxDynamicSharedMemorySize, HSMEM);
    cudaFuncSetAttribute(hgemm_kernel<false, 0>,
                         cudaFuncAttributeMaxDynamicSharedMemorySize, HSMEM);
    cudaFuncSetAttribute(hgemm_kernel<true, 1>,
                         cudaFuncAttributeMaxDynamicSharedMemorySize, HSMEM);
    cudaFuncSetAttribute(hgemm_kernel<true, 2>,
                         cudaFuncAttributeMaxDynamicSharedMemorySize, HSMEM);

    const long long sQK = (long long)SS * 64;
    const long long sAA = (long long)SS * SS;
    const long long sAB = (long long)SS * 128;

    splitW_kernel<<<(unsigned)((size_t)DD * DFFC / 1024), 256>>>(W1, W1hi, W1lo);
    splitW_kernel<<<(unsigned)((size_t)DFFC * DD / 1024), 256>>>(W2, W2hi, W2lo);

    // 1. LN1
    ln_kernel<<<NTOK, 256>>>(x, g1, be1, xn, nullptr, nullptr);
    // 2. QKV (3-way parallel)
    qkv_kernel<<<dim3(SS / 64, BH, 3), 256>>>(xn, Wq, Wk, Wv, qhi, qlo, khi, klo,
                                              ab, abThi, abTlo);
    // 3. scores
    hgemm_kernel<false, 0><<<dim3(16, 16, BH), 256, HSMEM>>>(
        qhi, qlo, khi, klo, 64, 64, 64, SS, sQK, sQK, sAA,
        S_, nullptr, nullptr, nullptr, nullptr, 0,
        nullptr, nullptr, nullptr, nullptr, nullptr, 0);
    // 4. softmax + split
    softmax_split_kernel<<<BH * SS, 256>>>(S_, Ahi, Alo);
    // 5. Heun loop with fused (MLP-batched) ODE epilogues
    for (int st = 0; st < 5; st++) {
        hgemm_kernel<true, 1><<<dim3(1, 16, BH), 256, HSMEM>>>(
            Ahi, Alo, abThi, abTlo, SS, SS, 128, 128, sAA, sAB, sAB,
            nullptr, pThi, pTlo, nullptr, nullptr, 0,
            om, ab, d1, attnv, nullptr, st == 0 ? 1 : 0);
        hgemm_kernel<true, 2><<<dim3(1, 16, BH), 256, HSMEM>>>(
            Ahi, Alo, pThi, pTlo, SS, SS, 128, 128, sAA, sAB, sAB,
            nullptr, abThi, abTlo, nullptr, nullptr, 0,
            om, ab, d1, attnv, mixb, st == 4 ? 1 : 0);
    }
    // 6. head projection + residual
    headout_kernel<<<dim3(SS / 64, BH), 256>>>(mixb, Wo, x, x1);
    // 7. LN2
    ln_kernel<<<NTOK, 256>>>(x1, g2, be2, xn, xnhi, xnlo);
    // 8. FFN1
    hgemm_kernel<true, 0><<<dim3(16, 32, 1), 256, HSMEM>>>(
        xnhi, xnlo, W1hi, W1lo, DD, DD, DFFC, DFFC, 0, 0, 0,
        nullptr, ffhi, fflo, bf1, nullptr, 1,
        nullptr, nullptr, nullptr, nullptr, nullptr, 0);
    // 9. FFN2
    hgemm_kernel<true, 0><<<dim3(8, 32, 1), 256, HSMEM>>>(
        ffhi, fflo, W2hi, W2lo, DFFC, DFFC, DD, DD, 0, 0, 0,
        out, nullptr, nullptr, bf2, x1, 0,
        nullptr, nullptr, nullptr, nullptr, nullptr, 0);
}

// round 9
// speedup vs baseline: 1.4501x; 1.2928x over previous
#include <cuda_runtime.h>
#include <cuda_bf16.h>
#include <cuda_fp16.h>
#include <math.h>
#include <stddef.h>
#include <stdint.h>

// ---------------- problem constants ----------------
#define BB   2
#define SS   2048
#define DD   1024
#define HH   16
#define HDIM 64
#define DFFC 2048
#define BH   (BB*HH)
#define NTOK (BB*SS)

#define MU_C   1.0f
#define K_C    3.0f
#define DT_C   0.02f
#define MIX_C  0.3f
#define CA_C   0.9950041652780258f
#define SA_C   0.09983341664682815f
#define ASCALE 2048.0f
#define AINV   (1.0f / 2048.0f)

// ---------------- scratch ----------------
__device__ float g_S [(size_t)BH * SS * SS];
__device__ __nv_bfloat16 g_Ahi[(size_t)BH * SS * SS];   // holds fp16 bits (scaled A hi)
__device__ __nv_bfloat16 g_Alo[(size_t)BH * SS * SS];   // holds fp16 bits (scaled A lo)
__device__ float g_xn  [(size_t)NTOK * DD];
__device__ __nv_bfloat16 g_xnhi[(size_t)NTOK * DD];
__device__ __nv_bfloat16 g_xnlo[(size_t)NTOK * DD];
__device__ __nv_bfloat16 g_qhi[(size_t)BH * SS * 64];
__device__ __nv_bfloat16 g_qlo[(size_t)BH * SS * 64];
__device__ __nv_bfloat16 g_khi[(size_t)BH * SS * 64];
__device__ __nv_bfloat16 g_klo[(size_t)BH * SS * 64];
__device__ float g_ab  [(size_t)BH * SS * 128];
__device__ float g_d1  [(size_t)BH * SS * 128];
__device__ __nv_bfloat16 g_abX[(size_t)BH * SS * 128];  // holds fp16 bits (X state)
__device__ __nv_bfloat16 g_pX [(size_t)BH * SS * 128];  // holds fp16 bits (X predictor)
__device__ float g_attnv[(size_t)BH * SS * 64];
__device__ float g_mix  [(size_t)BH * SS * 64];
__device__ float g_x1   [(size_t)NTOK * DD];
__device__ __nv_bfloat16 g_ffhi[(size_t)NTOK * DFFC];
__device__ __nv_bfloat16 g_fflo[(size_t)NTOK * DFFC];
__device__ __nv_bfloat16 g_W1hi[(size_t)DD * DFFC];
__device__ __nv_bfloat16 g_W1lo[(size_t)DD * DFFC];
__device__ __nv_bfloat16 g_W2hi[(size_t)DFFC * DD];
__device__ __nv_bfloat16 g_W2lo[(size_t)DFFC * DD];

// ---------------- low-level helpers ----------------
__device__ __forceinline__ uint32_t smem_u32(const void* p) {
    uint32_t a;
    asm("{ .reg .u64 t; cvta.to.shared.u64 t, %1; cvt.u32.u64 %0, t; }" : "=r"(a) : "l"(p));
    return a;
}
__device__ __forceinline__ void cp16(uint32_t s, const void* g) {
    asm volatile("cp.async.cg.shared.global [%0], [%1], 16;" :: "r"(s), "l"(g));
}
__device__ __forceinline__ void cp_commit() {
    asm volatile("cp.async.commit_group;" ::: "memory");
}
template <int N>
__device__ __forceinline__ void cp_wait() {
    asm volatile("cp.async.wait_group %0;" :: "n"(N) : "memory");
}
__device__ __forceinline__ void ldm_x4(uint32_t* r, uint32_t addr) {
    asm volatile("ldmatrix.sync.aligned.m8n8.x4.shared.b16 {%0,%1,%2,%3}, [%4];"
        : "=r"(r[0]), "=r"(r[1]), "=r"(r[2]), "=r"(r[3]) : "r"(addr));
}
__device__ __forceinline__ void ldm_x4t(uint32_t* r, uint32_t addr) {
    asm volatile("ldmatrix.sync.aligned.m8n8.x4.trans.shared.b16 {%0,%1,%2,%3}, [%4];"
        : "=r"(r[0]), "=r"(r[1]), "=r"(r[2]), "=r"(r[3]) : "r"(addr));
}
__device__ __forceinline__ void mma_bf16(float* c, const uint32_t* a, const uint32_t* b) {
    asm volatile("mma.sync.aligned.m16n8k16.row.col.f32.bf16.bf16.f32 "
        "{%0,%1,%2,%3}, {%4,%5,%6,%7}, {%8,%9}, {%0,%1,%2,%3};"
        : "+f"(c[0]), "+f"(c[1]), "+f"(c[2]), "+f"(c[3])
        : "r"(a[0]), "r"(a[1]), "r"(a[2]), "r"(a[3]), "r"(b[0]), "r"(b[1]));
}
__device__ __forceinline__ void mma_f16(float* c, const uint32_t* a, const uint32_t* b) {
    asm volatile("mma.sync.aligned.m16n8k16.row.col.f32.f16.f16.f32 "
        "{%0,%1,%2,%3}, {%4,%5,%6,%7}, {%8,%9}, {%0,%1,%2,%3};"
        : "+f"(c[0]), "+f"(c[1]), "+f"(c[2]), "+f"(c[3])
        : "r"(a[0]), "r"(a[1]), "r"(a[2]), "r"(a[3]), "r"(b[0]), "r"(b[1]));
}
__device__ __forceinline__ float gelu_tanh(float x) {
    float x3 = x * x * x;
    float t  = tanhf(0.7978845608028654f * (x + 0.044715f * x3));
    return 0.5f * x * (1.0f + t);
}
__device__ __forceinline__ void bf16_split2(float a, float b,
                                            __nv_bfloat162& h, __nv_bfloat162& l) {
    h.x = __float2bfloat16(a); h.y = __float2bfloat16(b);
    l.x = __float2bfloat16(a - __bfloat162float(h.x));
    l.y = __float2bfloat16(b - __bfloat162float(h.y));
}

// ---------------- unified split-precision HMMA GEMM, fusable ODE epilogue ----------------
// EPI: 0 = plain C output; 1 = fused ode_ew1; 2 = fused ode_ew2.
// PROD: 3 = bf16 3-product (A hi/lo x B hi/lo).  2 = fp16 2-product (A hi+lo exact, B hi only).
#define AST 72
#define BSTN 72
#define BSTT 136
#define OFF_AL 18432
#define OFF_BH 36864
#define OFF_BL 55296
#define STG3 73728
#define STG2 55296
#define HSMEM3 (2 * STG3)     // 147456
#define HSMEM2 (3 * STG2)     // 165888

template<bool TRANSB, int EPI, int PROD>
__global__ void __launch_bounds__(256, 1)
hgemm_kernel(const __nv_bfloat16* __restrict__ Ahi, const __nv_bfloat16* __restrict__ Alo,
             const __nv_bfloat16* __restrict__ Bhi, const __nv_bfloat16* __restrict__ Blo,
             int K, int lda, int ldb, int ldc,
             long long sA, long long sB, long long sC,
             float* __restrict__ outF,
             __nv_bfloat16* __restrict__ outHi, __nv_bfloat16* __restrict__ outLo,
             const float* __restrict__ bias, const float* __restrict__ addsrc, int do_gelu,
             const float* __restrict__ omg, float* __restrict__ abf,
             float* __restrict__ d1f, float* __restrict__ attnv,
             float* __restrict__ mixed, int flag)
{
    constexpr int STGB = (PROD == 2) ? STG2 : STG3;
    extern __shared__ char smem[];
    const uint32_t sb = smem_u32(smem);
    const int tid = threadIdx.x;
    const int lane = tid & 31, w = tid >> 5;
    const int wm = w >> 2, wn = w & 3;
    const int n0 = blockIdx.x * 128;
    const int m0 = blockIdx.y * 128;
    const long long bz = blockIdx.z;

    Ahi += bz * sA; Alo += bz * sA;
    Bhi += bz * sB; if (PROD == 3) Blo += bz * sB;

    float acc[4][4][4];
#pragma unroll
    for (int i = 0; i < 4; i++)
#pragma unroll
        for (int j = 0; j < 4; j++)
#pragma unroll
            for (int r = 0; r < 4; r++) acc[i][j][r] = 0.f;

    auto issue = [&](int chunk, int buf) {
        const int k0 = chunk << 6;
        const uint32_t st = sb + buf * STGB;
        {
            const int row = tid >> 3, col = (tid & 7) * 8;
            const __nv_bfloat16* gH = Ahi + (size_t)(m0 + row) * lda + k0 + col;
            const __nv_bfloat16* gL = Alo + (size_t)(m0 + row) * lda + k0 + col;
            uint32_t s = st + (row * AST + col) * 2;
#pragma unroll
            for (int j = 0; j < 4; j++) {
                cp16(s + j * 32 * (AST * 2),          gH + (size_t)j * 32 * lda);
                cp16(s + OFF_AL + j * 32 * (AST * 2), gL + (size_t)j * 32 * lda);
            }
        }
        if (TRANSB) {
            const int rk = tid >> 2, col = (tid & 3) * 8;
            const __nv_bfloat16* gH = Bhi + (size_t)(k0 + rk) * ldb + n0 + col;
            uint32_t s = st + OFF_BH + (rk * BSTT + col) * 2;
#pragma unroll
            for (int j = 0; j < 4; j++)
                cp16(s + j * 64, gH + j * 32);
            if (PROD == 3) {
                const __nv_bfloat16* gL = Blo + (size_t)(k0 + rk) * ldb + n0 + col;
#pragma unroll
                for (int j = 0; j < 4; j++)
                    cp16(s + (OFF_BL - OFF_BH) + j * 64, gL + j * 32);
            }
        } else {
            const int rn = tid >> 3, col = (tid & 7) * 8;
            const __nv_bfloat16* gH = Bhi + (size_t)(n0 + rn) * ldb + k0 + col;
            uint32_t s = st + OFF_BH + (rn * BSTN + col) * 2;
#pragma unroll
            for (int j = 0; j < 4; j++)
                cp16(s + j * 32 * (BSTN * 2), gH + (size_t)j * 32 * ldb);
            if (PROD == 3) {
                const __nv_bfloat16* gL = Blo + (size_t)(n0 + rn) * ldb + k0 + col;
#pragma unroll
                for (int j = 0; j < 4; j++)
                    cp16(s + (OFF_BL - OFF_BH) + j * 32 * (BSTN * 2),
                         gL + (size_t)j * 32 * ldb);
            }
        }
        cp_commit();
    };

    auto compute = [&](int buf) {
        const uint32_t st = sb + buf * STGB;
#pragma unroll
        for (int k16 = 0; k16 < 4; k16++) {
            uint32_t afrH[4][4], afrL[4][4], bfrH[4][2], bfrL[4][2];
#pragma unroll
            for (int ms = 0; ms < 4; ms++) {
                int row = wm * 64 + ms * 16 + (lane & 15);
                int col = k16 * 16 + (lane >> 4) * 8;
                ldm_x4(afrH[ms], st + (row * AST + col) * 2);
                ldm_x4(afrL[ms], st + OFF_AL + (row * AST + col) * 2);
            }
            if (TRANSB) {
                const int mat = lane >> 3, rr = lane & 7;
#pragma unroll
                for (int p = 0; p < 2; p++) {
                    int rk = k16 * 16 + (mat & 1) * 8 + rr;
                    int cn = wn * 32 + p * 16 + (mat >> 1) * 8;
                    ldm_x4t(&bfrH[p * 2][0], st + OFF_BH + (rk * BSTT + cn) * 2);
                    if (PROD == 3)
                        ldm_x4t(&bfrL[p * 2][0], st + OFF_BL + (rk * BSTT + cn) * 2);
                }
            } else {
                const int mat = lane >> 3, rr = lane & 7;
#pragma unroll
                for (int p = 0; p < 2; p++) {
                    int rn = wn * 32 + p * 16 + (mat >> 1) * 8 + rr;
                    int ck = k16 * 16 + (mat & 1) * 8;
                    ldm_x4(&bfrH[p * 2][0], st + OFF_BH + (rn * BSTN + ck) * 2);
                    if (PROD == 3)
                        ldm_x4(&bfrL[p * 2][0], st + OFF_BL + (rn * BSTN + ck) * 2);
                }
            }
#pragma unroll
            for (int ms = 0; ms < 4; ms++)
#pragma unroll
                for (int ns = 0; ns < 4; ns++) {
                    if (PROD == 3) {
                        mma_bf16(acc[ms][ns], afrH[ms], bfrH[ns]);
                        mma_bf16(acc[ms][ns], afrH[ms], bfrL[ns]);
                        mma_bf16(acc[ms][ns], afrL[ms], bfrH[ns]);
                    } else {
                        mma_f16(acc[ms][ns], afrH[ms], bfrH[ns]);
                        mma_f16(acc[ms][ns], afrL[ms], bfrH[ns]);
                    }
                }
        }
    };

    const int nchunk = K >> 6;
    if (PROD == 2) {
        issue(0, 0);
        if (nchunk > 1) issue(1, 1);
#pragma unroll 1
        for (int i = 0; i < nchunk; i++) {
            if (i + 2 < nchunk)      { issue(i + 2, (i + 2) % 3); cp_wait<2>(); }
            else if (i + 1 < nchunk) { cp_wait<1>(); }
            else                     { cp_wait<0>(); }
            __syncthreads();
            compute(i % 3);
            __syncthreads();
        }
    } else {
        issue(0, 0);
#pragma unroll 1
        for (int i = 0; i < nchunk; i++) {
            if (i + 1 < nchunk) { issue(i + 1, (i + 1) & 1); cp_wait<1>(); }
            else                { cp_wait<0>(); }
            __syncthreads();
            compute(i & 1);
            __syncthreads();
        }
    }

    if (EPI == 0) {
        const long long cb = bz * sC;
#pragma unroll
        for (int ms = 0; ms < 4; ms++) {
#pragma unroll
            for (int ns = 0; ns < 4; ns++) {
                int r0 = wm * 64 + ms * 16 + (lane >> 2);
                int c0 = n0 + wn * 32 + ns * 8 + (lane & 3) * 2;
#pragma unroll
                for (int half = 0; half < 2; half++) {
                    long long r = m0 + r0 + half * 8;
                    float vx = acc[ms][ns][half * 2 + 0];
                    float vy = acc[ms][ns][half * 2 + 1];
                    if (bias)   { vx += bias[c0]; vy += bias[c0 + 1]; }
                    if (addsrc) {
                        float2 s = *reinterpret_cast<const float2*>(addsrc + r * ldc + c0);
                        vx += s.x; vy += s.y;
                    }
                    if (do_gelu) { vx = gelu_tanh(vx); vy = gelu_tanh(vy); }
                    long long o = cb + r * ldc + c0;
                    if (outF)
                        *reinterpret_cast<float2*>(outF + o) = make_float2(vx, vy);
                    if (outHi) {
                        __nv_bfloat162 h, l;
                        bf16_split2(vx, vy, h, l);
                        *reinterpret_cast<__nv_bfloat162*>(outHi + o) = h;
                        *reinterpret_cast<__nv_bfloat162*>(outLo + o) = l;
                    }
                }
            }
        }
    } else {
        // stage z tile into smem (unscaling by AINV for PROD2), then batched ODE elementwise
        float* zsm = reinterpret_cast<float*>(smem);
        const float zs = (PROD == 2) ? AINV : 1.0f;
#pragma unroll
        for (int ms = 0; ms < 4; ms++)
#pragma unroll
            for (int ns = 0; ns < 4; ns++) {
                int r0 = wm * 64 + ms * 16 + (lane >> 2);
                int c0 = wn * 32 + ns * 8 + (lane & 3) * 2;
                zsm[r0 * 132 + c0]     = acc[ms][ns][0] * zs;
                zsm[r0 * 132 + c0 + 1] = acc[ms][ns][1] * zs;
                zsm[(r0 + 8) * 132 + c0]     = acc[ms][ns][2] * zs;
                zsm[(r0 + 8) * 132 + c0 + 1] = acc[ms][ns][3] * zs;
            }
        __syncthreads();
        const int h = (int)(bz & 15);
        __half* Xout = reinterpret_cast<__half*>(outHi);
#pragma unroll 1
        for (int ib = 0; ib < 2; ib++) {
            float2 a2[8], b2[8], d1a[8], d1b[8];
            int r8[8], cp8[8];
            size_t base8[8];
#pragma unroll
            for (int j = 0; j < 8; j++) {
                int lin = (ib * 8 + j) * 256 + tid;
                int r = lin >> 5, cp = (lin & 31) * 2;
                r8[j] = r; cp8[j] = cp;
                size_t base = ((size_t)bz * SS + m0 + r) * 128 + cp;
                base8[j] = base;
                a2[j] = *reinterpret_cast<const float2*>(abf + base);
                b2[j] = *reinterpret_cast<const float2*>(abf + base + 64);
                if (EPI == 2) {
                    d1a[j] = *reinterpret_cast<const float2*>(d1f + base);
                    d1b[j] = *reinterpret_cast<const float2*>(d1f + base + 64);
                }
            }
#pragma unroll
            for (int j = 0; j < 8; j++) {
                int r = r8[j], cp = cp8[j];
                size_t base = base8[j];
                size_t row = (size_t)bz * SS + m0 + r;
                float2 om2 = *reinterpret_cast<const float2*>(omg + h * 64 + cp);
                float za0 = zsm[r * 132 + cp],     za1 = zsm[r * 132 + cp + 1];
                float zb0 = zsm[r * 132 + cp + 64], zb1 = zsm[r * 132 + cp + 65];
                float ra0 = za0 * CA_C + zb0 * SA_C, rb0 = zb0 * CA_C - za0 * SA_C;
                float ra1 = za1 * CA_C + zb1 * SA_C, rb1 = zb1 * CA_C - za1 * SA_C;
                if (EPI == 1) {
                    if (flag)
                        *reinterpret_cast<float2*>(attnv + row * 64 + cp) =
                            make_float2(za0, za1);
                    float r20 = a2[j].x * a2[j].x + b2[j].x * b2[j].x;
                    float r21 = a2[j].y * a2[j].y + b2[j].y * b2[j].y;
                    float da0 = (MU_C - r20) * a2[j].x - om2.x * b2[j].x + K_C * (ra0 - a2[j].x);
                    float db0 = (MU_C - r20) * b2[j].x + om2.x * a2[j].x + K_C * (rb0 - b2[j].x);
                    float da1 = (MU_C - r21) * a2[j].y - om2.y * b2[j].y + K_C * (ra1 - a2[j].y);
                    float db1 = (MU_C - r21) * b2[j].y + om2.y * a2[j].y + K_C * (rb1 - b2[j].y);
                    *reinterpret_cast<float2*>(d1f + base)      = make_float2(da0, da1);
                    *reinterpret_cast<float2*>(d1f + base + 64) = make_float2(db0, db1);
                    float ap0 = a2[j].x + DT_C * da0, ap1 = a2[j].y + DT_C * da1;
                    float bp0 = b2[j].x + DT_C * db0, bp1 = b2[j].y + DT_C * db1;
                    *reinterpret_cast<__half2*>(Xout + base) = __floats2half2_rn(ap0, ap1);
                    *reinterpret_cast<__half2*>(Xout + base + 64) = __floats2half2_rn(bp0, bp1);
                } else {
                    float ap0 = a2[j].x + DT_C * d1a[j].x, ap1 = a2[j].y + DT_C * d1a[j].y;
                    float bp0 = b2[j].x + DT_C * d1b[j].x, bp1 = b2[j].y + DT_C * d1b[j].y;
                    float r20 = ap0 * ap0 + bp0 * bp0;
                    float r21 = ap1 * ap1 + bp1 * bp1;
                    float da20 = (MU_C - r20) * ap0 - om2.x * bp0 + K_C * (ra0 - ap0);
                    float db20 = (MU_C - r20) * bp0 + om2.x * ap0 + K_C * (rb0 - bp0);
                    float da21 = (MU_C - r21) * ap1 - om2.y * bp1 + K_C * (ra1 - ap1);
                    float db21 = (MU_C - r21) * bp1 + om2.y * ap1 + K_C * (rb1 - bp1);
                    float an0 = a2[j].x + 0.5f * DT_C * (d1a[j].x + da20);
                    float an1 = a2[j].y + 0.5f * DT_C * (d1a[j].y + da21);
                    float bn0 = b2[j].x + 0.5f * DT_C * (d1b[j].x + db20);
                    float bn1 = b2[j].y + 0.5f * DT_C * (d1b[j].y + db21);
                    *reinterpret_cast<float2*>(abf + base)      = make_float2(an0, an1);
                    *reinterpret_cast<float2*>(abf + base + 64) = make_float2(bn0, bn1);
                    if (flag) {
                        float2 av = *reinterpret_cast<const float2*>(attnv + row * 64 + cp);
                        *reinterpret_cast<float2*>(mixed + row * 64 + cp) =
                            make_float2(MIX_C * av.x + (1.0f - MIX_C) * an0,
                                        MIX_C * av.y + (1.0f - MIX_C) * an1);
                    } else {
                        *reinterpret_cast<__half2*>(Xout + base) = __floats2half2_rn(an0, an1);
                        *reinterpret_cast<__half2*>(Xout + base + 64) = __floats2half2_rn(bn0, bn1);
                    }
                }
            }
        }
    }
}

// ---------------- fp32 -> bf16 hi/lo split ----------------
__global__ void splitW_kernel(const float* __restrict__ A,
                              __nv_bfloat16* __restrict__ hi, __nv_bfloat16* __restrict__ lo)
{
    size_t i = ((size_t)blockIdx.x * blockDim.x + threadIdx.x) * 4;
    float4 v = *reinterpret_cast<const float4*>(A + i);
    __nv_bfloat162 h0, h1, l0, l1;
    bf16_split2(v.x, v.y, h0, l0);
    bf16_split2(v.z, v.w, h1, l1);
    *reinterpret_cast<__nv_bfloat162*>(hi + i)     = h0;
    *reinterpret_cast<__nv_bfloat162*>(hi + i + 2) = h1;
    *reinterpret_cast<__nv_bfloat162*>(lo + i)     = l0;
    *reinterpret_cast<__nv_bfloat162*>(lo + i + 2) = l1;
}

// ---------------- LayerNorm ----------------
__global__ void ln_kernel(const float* __restrict__ x, const float* __restrict__ g,
                          const float* __restrict__ be, float* __restrict__ out,
                          __nv_bfloat16* __restrict__ outHi, __nv_bfloat16* __restrict__ outLo)
{
    __shared__ float sh[8];
    size_t row = blockIdx.x;
    int tid = threadIdx.x, lane = tid & 31, wid = tid >> 5;
    float4 v = reinterpret_cast<const float4*>(x + row * DD)[tid];

    float s = v.x + v.y + v.z + v.w;
#pragma unroll
    for (int o = 16; o; o >>= 1) s += __shfl_xor_sync(0xffffffffu, s, o);
    if (lane == 0) sh[wid] = s;
    __syncthreads();
    float tot = 0.f;
#pragma unroll
    for (int i = 0; i < 8; i++) tot += sh[i];
    float mean = tot * (1.0f / DD);

    float dx = v.x - mean, dy = v.y - mean, dz = v.z - mean, dw = v.w - mean;
    float s2 = dx*dx + dy*dy + dz*dz + dw*dw;
#pragma unroll
    for (int o = 16; o; o >>= 1) s2 += __shfl_xor_sync(0xffffffffu, s2, o);
    __syncthreads();
    if (lane == 0) sh[wid] = s2;
    __syncthreads();
    float tot2 = 0.f;
#pragma unroll
    for (int i = 0; i < 8; i++) tot2 += sh[i];
    float rstd = rsqrtf(tot2 * (1.0f / DD) + 1e-5f);

    float4 gv = reinterpret_cast<const float4*>(g)[tid];
    float4 bv = reinterpret_cast<const float4*>(be)[tid];
    float4 o4;
    o4.x = dx * rstd * gv.x + bv.x;
    o4.y = dy * rstd * gv.y + bv.y;
    o4.z = dz * rstd * gv.z + bv.z;
    o4.w = dw * rstd * gv.w + bv.w;
    reinterpret_cast<float4*>(out + row * DD)[tid] = o4;
    if (outHi) {
        size_t i = row * DD + tid * 4;
        __nv_bfloat162 h0, h1, l0, l1;
        bf16_split2(o4.x, o4.y, h0, l0);
        bf16_split2(o4.z, o4.w, h1, l1);
        *reinterpret_cast<__nv_bfloat162*>(outHi + i)     = h0;
        *reinterpret_cast<__nv_bfloat162*>(outHi + i + 2) = h1;
        *reinterpret_cast<__nv_bfloat162*>(outLo + i)     = l0;
        *reinterpret_cast<__nv_bfloat162*>(outLo + i + 2) = l1;
    }
}

// ---------------- QKV projection (3-way parallel) ----------------
__global__ void qkv_kernel(const float* __restrict__ xn,
                           const float* __restrict__ Wq, const float* __restrict__ Wk,
                           const float* __restrict__ Wv,
                           __nv_bfloat16* __restrict__ qhi, __nv_bfloat16* __restrict__ qlo,
                           __nv_bfloat16* __restrict__ khi, __nv_bfloat16* __restrict__ klo,
                           float* __restrict__ ab, __nv_bfloat16* __restrict__ abX)
{
    __shared__ float sx[64][65];
    __shared__ float sw[64][65];
    int bh = blockIdx.y, b = bh >> 4, h = bh & 15;
    int wsel = blockIdx.z;
    int s0 = blockIdx.x * 64;
    int tid = threadIdx.x;

    const float* W = (wsel == 0 ? Wq : (wsel == 1 ? Wk : Wv)) + h * 4096;
    for (int idx = tid; idx < 4096; idx += 256) {
        int r = idx >> 6, d = idx & 63;
        sx[r][d] = xn[((size_t)(b * SS + s0 + r)) * DD + h * 64 + d];
        sw[r][d] = W[idx];
    }
    __syncthreads();
    int e = tid & 63, rq = tid >> 6;
    __half* Xp = reinterpret_cast<__half*>(abX);
#pragma unroll
    for (int i = 0; i < 16; i++) {
        int r = rq * 16 + i;
        float acc = 0.f;
#pragma unroll
        for (int d = 0; d < 64; d++) acc = fmaf(sx[r][d], sw[d][e], acc);
        size_t srow = (size_t)bh * SS + s0 + r;
        if (wsel == 0) {
            __nv_bfloat16 hi = __float2bfloat16(acc);
            qhi[srow * 64 + e] = hi;
            qlo[srow * 64 + e] = __float2bfloat16(acc - __bfloat162float(hi));
        } else if (wsel == 1) {
            __nv_bfloat16 hi = __float2bfloat16(acc);
            khi[srow * 64 + e] = hi;
            klo[srow * 64 + e] = __float2bfloat16(acc - __bfloat162float(hi));
        } else {
            ab[srow * 128 + e] = acc; ab[srow * 128 + 64 + e] = 0.f;
            Xp[srow * 128 + e] = __float2half(acc);
            Xp[srow * 128 + 64 + e] = __float2half(0.f);
        }
    }
}

// ---------------- fused softmax + scaled fp16 split ----------------
__global__ void softmax_split_kernel(const float* __restrict__ S,
                                     __nv_bfloat16* __restrict__ Ahi,
                                     __nv_bfloat16* __restrict__ Alo)
{
    __shared__ float sh[8];
    size_t row = blockIdx.x;
    const float* p = S + row * (size_t)SS;
    int tid = threadIdx.x, lane = tid & 31, wid = tid >> 5;

    float4 v0 = reinterpret_cast<const float4*>(p)[tid];
    float4 v1 = reinterpret_cast<const float4*>(p)[tid + 256];
    const float sc = 0.125f;
    v0.x *= sc; v0.y *= sc; v0.z *= sc; v0.w *= sc;
    v1.x *= sc; v1.y *= sc; v1.z *= sc; v1.w *= sc;

    float mx = fmaxf(fmaxf(fmaxf(v0.x, v0.y), fmaxf(v0.z, v0.w)),
                     fmaxf(fmaxf(v1.x, v1.y), fmaxf(v1.z, v1.w)));
#pragma unroll
    for (int o = 16; o; o >>= 1) mx = fmaxf(mx, __shfl_xor_sync(0xffffffffu, mx, o));
    if (lane == 0) sh[wid] = mx;
    __syncthreads();
    float m = sh[0];
#pragma unroll
    for (int i = 1; i < 8; i++) m = fmaxf(m, sh[i]);

    v0.x = expf(v0.x - m); v0.y = expf(v0.y - m);
    v0.z = expf(v0.z - m); v0.w = expf(v0.w - m);
    v1.x = expf(v1.x - m); v1.y = expf(v1.y - m);
    v1.z = expf(v1.z - m); v1.w = expf(v1.w - m);

    float s = v0.x + v0.y + v0.z + v0.w + v1.x + v1.y + v1.z + v1.w;
#pragma unroll
    for (int o = 16; o; o >>= 1) s += __shfl_xor_sync(0xffffffffu, s, o);
    __syncthreads();
    if (lane == 0) sh[wid] = s;
    __syncthreads();
    float tot = 0.f;
#pragma unroll
    for (int i = 0; i < 8; i++) tot += sh[i];
    float inv = ASCALE / tot;        // fold x2048 scale into normalization

    v0.x *= inv; v0.y *= inv; v0.z *= inv; v0.w *= inv;
    v1.x *= inv; v1.y *= inv; v1.z *= inv; v1.w *= inv;

    size_t ob = row * (size_t)SS;
    __half* Ah = reinterpret_cast<__half*>(Ahi);
    __half* Al = reinterpret_cast<__half*>(Alo);
    auto emit = [&](size_t off, float a, float b) {
        __half ha = __float2half(a), hb = __float2half(b);
        __half la = __float2half(a - __half2float(ha));
        __half lb = __float2half(b - __half2float(hb));
        *reinterpret_cast<__half2*>(Ah + ob + off) = __halves2half2(ha, hb);
        *reinterpret_cast<__half2*>(Al + ob + off) = __halves2half2(la, lb);
    };
    emit(tid * 4 + 0, v0.x, v0.y);
    emit(tid * 4 + 2, v0.z, v0.w);
    emit((tid + 256) * 4 + 0, v1.x, v1.y);
    emit((tid + 256) * 4 + 2, v1.z, v1.w);
}

// ---------------- head projection + residual ----------------
__global__ void headout_kernel(const float* __restrict__ mix, const float* __restrict__ Wo,
                               const float* __restrict__ x, float* __restrict__ x1)
{
    __shared__ float sx[64][65];
    __shared__ float sw[64][65];
    int bh = blockIdx.y, b = bh >> 4, h = bh & 15;
    int s0 = blockIdx.x * 64;
    int tid = threadIdx.x;

    for (int idx = tid; idx < 4096; idx += 256) {
        int r = idx >> 6, d = idx & 63;
        sx[r][d] = mix[((size_t)bh * SS + s0 + r) * 64 + d];
        sw[r][d] = Wo[h * 4096 + idx];
    }
    __syncthreads();
    int e = tid & 63, rq = tid >> 6;
#pragma unroll
    for (int i = 0; i < 16; i++) {
        int r = rq * 16 + i;
        float acc = 0.f;
#pragma unroll
        for (int d = 0; d < 64; d++) acc = fmaf(sx[r][d], sw[d][e], acc);
        size_t o = ((size_t)(b * SS + s0 + r)) * DD + h * 64 + e;
        x1[o] = x[o] + acc;
    }
}

// ---------------- host side ----------------
extern "C" void kernel_launch(void* const* d_in, const int* in_sizes, int n_in,
                              void* d_out, int out_size)
{
    const float* x   = (const float*)d_in[0];
    const float* Wq  = (const float*)d_in[1];
    const float* Wk  = (const float*)d_in[2];
    const float* Wv  = (const float*)d_in[3];
    const float* Wo  = (const float*)d_in[4];
    const float* om  = (const float*)d_in[5];
    const float* g1  = (const float*)d_in[6];
    const float* be1 = (const float*)d_in[7];
    const float* g2  = (const float*)d_in[8];
    const float* be2 = (const float*)d_in[9];
    const float* W1  = (const float*)d_in[10];
    const float* bf1 = (const float*)d_in[11];
    const float* W2  = (const float*)d_in[12];
    const float* bf2 = (const float*)d_in[13];
    float* out = (float*)d_out;
    (void)in_sizes; (void)n_in; (void)out_size;

    float *S_, *xn, *ab, *d1, *attnv, *mixb, *x1;
    __nv_bfloat16 *Ahi, *Alo, *xnhi, *xnlo, *qhi, *qlo, *khi, *klo;
    __nv_bfloat16 *abX, *pX, *ffhi, *fflo;
    __nv_bfloat16 *W1hi, *W1lo, *W2hi, *W2lo;
    cudaGetSymbolAddress((void**)&S_,    g_S);
    cudaGetSymbolAddress((void**)&Ahi,   g_Ahi);
    cudaGetSymbolAddress((void**)&Alo,   g_Alo);
    cudaGetSymbolAddress((void**)&xn,    g_xn);
    cudaGetSymbolAddress((void**)&xnhi,  g_xnhi);
    cudaGetSymbolAddress((void**)&xnlo,  g_xnlo);
    cudaGetSymbolAddress((void**)&qhi,   g_qhi);
    cudaGetSymbolAddress((void**)&qlo,   g_qlo);
    cudaGetSymbolAddress((void**)&khi,   g_khi);
    cudaGetSymbolAddress((void**)&klo,   g_klo);
    cudaGetSymbolAddress((void**)&ab,    g_ab);
    cudaGetSymbolAddress((void**)&d1,    g_d1);
    cudaGetSymbolAddress((void**)&abX,   g_abX);
    cudaGetSymbolAddress((void**)&pX,    g_pX);
    cudaGetSymbolAddress((void**)&attnv, g_attnv);
    cudaGetSymbolAddress((void**)&mixb,  g_mix);
    cudaGetSymbolAddress((void**)&x1,    g_x1);
    cudaGetSymbolAddress((void**)&ffhi,  g_ffhi);
    cudaGetSymbolAddress((void**)&fflo,  g_fflo);
    cudaGetSymbolAddress((void**)&W1hi,  g_W1hi);
    cudaGetSymbolAddress((void**)&W1lo,  g_W1lo);
    cudaGetSymbolAddress((void**)&W2hi,  g_W2hi);
    cudaGetSymbolAddress((void**)&W2lo,  g_W2lo);

    cudaFuncSetAttribute(hgemm_kernel<true, 0, 3>,
                         cudaFuncAttributeMaxDynamicSharedMemorySize, HSMEM3);
    cudaFuncSetAttribute(hgemm_kernel<false, 0, 3>,
                         cudaFuncAttributeMaxDynamicSharedMemorySize, HSMEM3);
    cudaFuncSetAttribute(hgemm_kernel<true, 1, 2>,
                         cudaFuncAttributeMaxDynamicSharedMemorySize, HSMEM2);
    cudaFuncSetAttribute(hgemm_kernel<true, 2, 2>,
                         cudaFuncAttributeMaxDynamicSharedMemorySize, HSMEM2);

    const long long sQK = (long long)SS * 64;
    const long long sAA = (long long)SS * SS;
    const long long sAB = (long long)SS * 128;

    splitW_kernel<<<(unsigned)((size_t)DD * DFFC / 1024), 256>>>(W1, W1hi, W1lo);
    splitW_kernel<<<(unsigned)((size_t)DFFC * DD / 1024), 256>>>(W2, W2hi, W2lo);

    // 1. LN1
    ln_kernel<<<NTOK, 256>>>(x, g1, be1, xn, nullptr, nullptr);
    // 2. QKV (3-way parallel); v -> fp32 ab + fp16 X
    qkv_kernel<<<dim3(SS / 64, BH, 3), 256>>>(xn, Wq, Wk, Wv, qhi, qlo, khi, klo,
                                              ab, abX);
    // 3. scores (bf16 3-product)
    hgemm_kernel<false, 0, 3><<<dim3(16, 16, BH), 256, HSMEM3>>>(
        qhi, qlo, khi, klo, 64, 64, 64, SS, sQK, sQK, sAA,
        S_, nullptr, nullptr, nullptr, nullptr, 0,
        nullptr, nullptr, nullptr, nullptr, nullptr, 0);
    // 4. softmax + scaled fp16 split
    softmax_split_kernel<<<BH * SS, 256>>>(S_, Ahi, Alo);
    // 5. Heun loop: fp16 2-product GEMM + fused ODE epilogues
    for (int st = 0; st < 5; st++) {
        hgemm_kernel<true, 1, 2><<<dim3(1, 16, BH), 256, HSMEM2>>>(
            Ahi, Alo, abX, nullptr, SS, SS, 128, 128, sAA, sAB, sAB,
            nullptr, pX, nullptr, nullptr, nullptr, 0,
            om, ab, d1, attnv, nullptr, st == 0 ? 1 : 0);
        hgemm_kernel<true, 2, 2><<<dim3(1, 16, BH), 256, HSMEM2>>>(
            Ahi, Alo, pX, nullptr, SS, SS, 128, 128, sAA, sAB, sAB,
            nullptr, abX, nullptr, nullptr, nullptr, 0,
            om, ab, d1, attnv, mixb, st == 4 ? 1 : 0);
    }
    // 6. head projection + residual
    headout_kernel<<<dim3(SS / 64, BH), 256>>>(mixb, Wo, x, x1);
    // 7. LN2
    ln_kernel<<<NTOK, 256>>>(x1, g2, be2, xn, xnhi, xnlo);
    // 8. FFN1 (bf16 3-product)
    hgemm_kernel<true, 0, 3><<<dim3(16, 32, 1), 256, HSMEM3>>>(
        xnhi, xnlo, W1hi, W1lo, DD, DD, DFFC, DFFC, 0, 0, 0,
        nullptr, ffhi, fflo, bf1, nullptr, 1,
        nullptr, nullptr, nullptr, nullptr, nullptr, 0);
    // 9. FFN2 (bf16 3-product)
    hgemm_kernel<true, 0, 3><<<dim3(8, 32, 1), 256, HSMEM3>>>(
        ffhi, fflo, W2hi, W2lo, DFFC, DFFC, DD, DD, 0, 0, 0,
        out, nullptr, nullptr, bf2, x1, 0,
        nullptr, nullptr, nullptr, nullptr, nullptr, 0);
}

// round 10
// speedup vs baseline: 2.2387x; 1.5438x over previous
#include <cuda_runtime.h>
#include <cuda_bf16.h>
#include <cuda_fp16.h>
#include <math.h>
#include <stddef.h>
#include <stdint.h>

// ---------------- problem constants ----------------
#define BB   2
#define SS   2048
#define DD   1024
#define HH   16
#define HDIM 64
#define DFFC 2048
#define BH   (BB*HH)
#define NTOK (BB*SS)

#define MU_C   1.0f
#define K_C    3.0f
#define DT_C   0.02f
#define MIX_C  0.3f
#define CA_C   0.9950041652780258f
#define SA_C   0.09983341664682815f
#define ASCALE 2048.0f
#define AINV   (1.0f / 2048.0f)

// ---------------- scratch ----------------
__device__ float g_S [(size_t)BH * SS * SS];
__device__ __nv_bfloat16 g_Ahi[(size_t)BH * SS * SS];   // fp16 bits (scaled A)
__device__ __nv_bfloat16 g_Alo[(size_t)BH * SS * SS];   // unused in PROD1 path
__device__ float g_xn  [(size_t)NTOK * DD];
__device__ __nv_bfloat16 g_xnhi[(size_t)NTOK * DD];
__device__ __nv_bfloat16 g_xnlo[(size_t)NTOK * DD];
__device__ __nv_bfloat16 g_qhi[(size_t)BH * SS * 64];
__device__ __nv_bfloat16 g_qlo[(size_t)BH * SS * 64];
__device__ __nv_bfloat16 g_khi[(size_t)BH * SS * 64];
__device__ __nv_bfloat16 g_klo[(size_t)BH * SS * 64];
__device__ float g_ab  [(size_t)BH * SS * 128];
__device__ float g_d1  [(size_t)BH * SS * 128];
__device__ __nv_bfloat16 g_abX[(size_t)BH * SS * 128];  // fp16 bits (X state)
__device__ __nv_bfloat16 g_pX [(size_t)BH * SS * 128];  // fp16 bits (X predictor)
__device__ float g_attnv[(size_t)BH * SS * 64];
__device__ float g_mix  [(size_t)BH * SS * 64];
__device__ float g_x1   [(size_t)NTOK * DD];
__device__ __nv_bfloat16 g_ffhi[(size_t)NTOK * DFFC];
__device__ __nv_bfloat16 g_fflo[(size_t)NTOK * DFFC];
__device__ __nv_bfloat16 g_W1hi[(size_t)DD * DFFC];
__device__ __nv_bfloat16 g_W1lo[(size_t)DD * DFFC];
__device__ __nv_bfloat16 g_W2hi[(size_t)DFFC * DD];
__device__ __nv_bfloat16 g_W2lo[(size_t)DFFC * DD];

// ---------------- low-level helpers ----------------
__device__ __forceinline__ uint32_t smem_u32(const void* p) {
    uint32_t a;
    asm("{ .reg .u64 t; cvta.to.shared.u64 t, %1; cvt.u32.u64 %0, t; }" : "=r"(a) : "l"(p));
    return a;
}
__device__ __forceinline__ void cp16(uint32_t s, const void* g) {
    asm volatile("cp.async.cg.shared.global [%0], [%1], 16;" :: "r"(s), "l"(g));
}
__device__ __forceinline__ void cp_commit() {
    asm volatile("cp.async.commit_group;" ::: "memory");
}
template <int N>
__device__ __forceinline__ void cp_wait() {
    asm volatile("cp.async.wait_group %0;" :: "n"(N) : "memory");
}
__device__ __forceinline__ void ldm_x4(uint32_t* r, uint32_t addr) {
    asm volatile("ldmatrix.sync.aligned.m8n8.x4.shared.b16 {%0,%1,%2,%3}, [%4];"
        : "=r"(r[0]), "=r"(r[1]), "=r"(r[2]), "=r"(r[3]) : "r"(addr));
}
__device__ __forceinline__ void ldm_x4t(uint32_t* r, uint32_t addr) {
    asm volatile("ldmatrix.sync.aligned.m8n8.x4.trans.shared.b16 {%0,%1,%2,%3}, [%4];"
        : "=r"(r[0]), "=r"(r[1]), "=r"(r[2]), "=r"(r[3]) : "r"(addr));
}
__device__ __forceinline__ void mma_bf16(float* c, const uint32_t* a, const uint32_t* b) {
    asm volatile("mma.sync.aligned.m16n8k16.row.col.f32.bf16.bf16.f32 "
        "{%0,%1,%2,%3}, {%4,%5,%6,%7}, {%8,%9}, {%0,%1,%2,%3};"
        : "+f"(c[0]), "+f"(c[1]), "+f"(c[2]), "+f"(c[3])
        : "r"(a[0]), "r"(a[1]), "r"(a[2]), "r"(a[3]), "r"(b[0]), "r"(b[1]));
}
__device__ __forceinline__ void mma_f16(float* c, const uint32_t* a, const uint32_t* b) {
    asm volatile("mma.sync.aligned.m16n8k16.row.col.f32.f16.f16.f32 "
        "{%0,%1,%2,%3}, {%4,%5,%6,%7}, {%8,%9}, {%0,%1,%2,%3};"
        : "+f"(c[0]), "+f"(c[1]), "+f"(c[2]), "+f"(c[3])
        : "r"(a[0]), "r"(a[1]), "r"(a[2]), "r"(a[3]), "r"(b[0]), "r"(b[1]));
}
__device__ __forceinline__ float gelu_tanh(float x) {
    float x3 = x * x * x;
    float t  = tanhf(0.7978845608028654f * (x + 0.044715f * x3));
    return 0.5f * x * (1.0f + t);
}
__device__ __forceinline__ void bf16_split2(float a, float b,
                                            __nv_bfloat162& h, __nv_bfloat162& l) {
    h.x = __float2bfloat16(a); h.y = __float2bfloat16(b);
    l.x = __float2bfloat16(a - __bfloat162float(h.x));
    l.y = __float2bfloat16(b - __bfloat162float(h.y));
}

// ---------------- unified split-precision HMMA GEMM, fusable ODE epilogue ----------------
// EPI: 0 = plain C output; 1 = fused ode_ew1; 2 = fused ode_ew2.
// PROD: 3 = bf16 3-product (A hi/lo x B hi/lo).
//       2 = fp16 2-product (A hi+lo, B hi).
//       1 = fp16 1-product (A hi, B hi) — relies on scaled-A fp16 accuracy.
#define AST 72
#define BSTN 72
#define BSTT 136
#define STG3 73728
#define STG2 55296
#define STG1 36864
#define HSMEM3 (2 * STG3)     // 147456, 1 CTA/SM
#define HSMEM2 (3 * STG2)     // 165888, 1 CTA/SM
#define HSMEM1 (2 * STG1)     // 73728,  2 CTA/SM

template<bool TRANSB, int EPI, int PROD>
__global__ void __launch_bounds__(256)
hgemm_kernel(const __nv_bfloat16* __restrict__ Ahi, const __nv_bfloat16* __restrict__ Alo,
             const __nv_bfloat16* __restrict__ Bhi, const __nv_bfloat16* __restrict__ Blo,
             int K, int lda, int ldb, int ldc,
             long long sA, long long sB, long long sC,
             float* __restrict__ outF,
             __nv_bfloat16* __restrict__ outHi, __nv_bfloat16* __restrict__ outLo,
             const float* __restrict__ bias, const float* __restrict__ addsrc, int do_gelu,
             const float* __restrict__ omg, float* __restrict__ abf,
             float* __restrict__ d1f, float* __restrict__ attnv,
             float* __restrict__ mixed, int flag)
{
    constexpr int STGB  = (PROD == 3) ? STG3 : (PROD == 2) ? STG2 : STG1;
    constexpr int OFFAL = 18432;                         // A-lo (PROD >= 2)
    constexpr int OFFBH = (PROD == 1) ? 18432 : 36864;   // B-hi
    constexpr int OFFBL = 55296;                         // B-lo (PROD == 3)
    extern __shared__ char smem[];
    const uint32_t sb = smem_u32(smem);
    const int tid = threadIdx.x;
    const int lane = tid & 31, w = tid >> 5;
    const int wm = w >> 2, wn = w & 3;
    const int n0 = blockIdx.x * 128;
    const int m0 = blockIdx.y * 128;
    const long long bz = blockIdx.z;

    Ahi += bz * sA;
    if (PROD >= 2) Alo += bz * sA;
    Bhi += bz * sB;
    if (PROD == 3) Blo += bz * sB;

    float acc[4][4][4];
#pragma unroll
    for (int i = 0; i < 4; i++)
#pragma unroll
        for (int j = 0; j < 4; j++)
#pragma unroll
            for (int r = 0; r < 4; r++) acc[i][j][r] = 0.f;

    auto issue = [&](int chunk, int buf) {
        const int k0 = chunk << 6;
        const uint32_t st = sb + buf * STGB;
        {
            const int row = tid >> 3, col = (tid & 7) * 8;
            const __nv_bfloat16* gH = Ahi + (size_t)(m0 + row) * lda + k0 + col;
            uint32_t s = st + (row * AST + col) * 2;
#pragma unroll
            for (int j = 0; j < 4; j++)
                cp16(s + j * 32 * (AST * 2), gH + (size_t)j * 32 * lda);
            if (PROD >= 2) {
                const __nv_bfloat16* gL = Alo + (size_t)(m0 + row) * lda + k0 + col;
#pragma unroll
                for (int j = 0; j < 4; j++)
                    cp16(s + OFFAL + j * 32 * (AST * 2), gL + (size_t)j * 32 * lda);
            }
        }
        if (TRANSB) {
            const int rk = tid >> 2, col = (tid & 3) * 8;
            const __nv_bfloat16* gH = Bhi + (size_t)(k0 + rk) * ldb + n0 + col;
            uint32_t s = st + OFFBH + (rk * BSTT + col) * 2;
#pragma unroll
            for (int j = 0; j < 4; j++)
                cp16(s + j * 64, gH + j * 32);
            if (PROD == 3) {
                const __nv_bfloat16* gL = Blo + (size_t)(k0 + rk) * ldb + n0 + col;
#pragma unroll
                for (int j = 0; j < 4; j++)
                    cp16(s + (OFFBL - OFFBH) + j * 64, gL + j * 32);
            }
        } else {
            const int rn = tid >> 3, col = (tid & 7) * 8;
            const __nv_bfloat16* gH = Bhi + (size_t)(n0 + rn) * ldb + k0 + col;
            uint32_t s = st + OFFBH + (rn * BSTN + col) * 2;
#pragma unroll
            for (int j = 0; j < 4; j++)
                cp16(s + j * 32 * (BSTN * 2), gH + (size_t)j * 32 * ldb);
            if (PROD == 3) {
                const __nv_bfloat16* gL = Blo + (size_t)(n0 + rn) * ldb + k0 + col;
#pragma unroll
                for (int j = 0; j < 4; j++)
                    cp16(s + (OFFBL - OFFBH) + j * 32 * (BSTN * 2),
                         gL + (size_t)j * 32 * ldb);
            }
        }
        cp_commit();
    };

    auto compute = [&](int buf) {
        const uint32_t st = sb + buf * STGB;
#pragma unroll
        for (int k16 = 0; k16 < 4; k16++) {
            uint32_t afrH[4][4], afrL[4][4], bfrH[4][2], bfrL[4][2];
#pragma unroll
            for (int ms = 0; ms < 4; ms++) {
                int row = wm * 64 + ms * 16 + (lane & 15);
                int col = k16 * 16 + (lane >> 4) * 8;
                ldm_x4(afrH[ms], st + (row * AST + col) * 2);
                if (PROD >= 2)
                    ldm_x4(afrL[ms], st + OFFAL + (row * AST + col) * 2);
            }
            if (TRANSB) {
                const int mat = lane >> 3, rr = lane & 7;
#pragma unroll
                for (int p = 0; p < 2; p++) {
                    int rk = k16 * 16 + (mat & 1) * 8 + rr;
                    int cn = wn * 32 + p * 16 + (mat >> 1) * 8;
                    ldm_x4t(&bfrH[p * 2][0], st + OFFBH + (rk * BSTT + cn) * 2);
                    if (PROD == 3)
                        ldm_x4t(&bfrL[p * 2][0], st + OFFBL + (rk * BSTT + cn) * 2);
                }
            } else {
                const int mat = lane >> 3, rr = lane & 7;
#pragma unroll
                for (int p = 0; p < 2; p++) {
                    int rn = wn * 32 + p * 16 + (mat >> 1) * 8 + rr;
                    int ck = k16 * 16 + (mat & 1) * 8;
                    ldm_x4(&bfrH[p * 2][0], st + OFFBH + (rn * BSTN + ck) * 2);
                    if (PROD == 3)
                        ldm_x4(&bfrL[p * 2][0], st + OFFBH + (STG3 - STG3) + OFFBL - OFFBH
                               + (rn * BSTN + ck) * 2 + OFFBH - OFFBH);
                }
            }
            // (non-trans B-lo path above simplified below for PROD3 correctness)
            if (!TRANSB && PROD == 3) {
                const int mat = lane >> 3, rr = lane & 7;
#pragma unroll
                for (int p = 0; p < 2; p++) {
                    int rn = wn * 32 + p * 16 + (mat >> 1) * 8 + rr;
                    int ck = k16 * 16 + (mat & 1) * 8;
                    ldm_x4(&bfrL[p * 2][0], st + OFFBL + (rn * BSTN + ck) * 2);
                }
            }
#pragma unroll
            for (int ms = 0; ms < 4; ms++)
#pragma unroll
                for (int ns = 0; ns < 4; ns++) {
                    if (PROD == 3) {
                        mma_bf16(acc[ms][ns], afrH[ms], bfrH[ns]);
                        mma_bf16(acc[ms][ns], afrH[ms], bfrL[ns]);
                        mma_bf16(acc[ms][ns], afrL[ms], bfrH[ns]);
                    } else if (PROD == 2) {
                        mma_f16(acc[ms][ns], afrH[ms], bfrH[ns]);
                        mma_f16(acc[ms][ns], afrL[ms], bfrH[ns]);
                    } else {
                        mma_f16(acc[ms][ns], afrH[ms], bfrH[ns]);
                    }
                }
        }
    };

    const int nchunk = K >> 6;
    if (PROD == 2) {
        issue(0, 0);
        if (nchunk > 1) issue(1, 1);
#pragma unroll 1
        for (int i = 0; i < nchunk; i++) {
            if (i + 2 < nchunk)      { issue(i + 2, (i + 2) % 3); cp_wait<2>(); }
            else if (i + 1 < nchunk) { cp_wait<1>(); }
            else                     { cp_wait<0>(); }
            __syncthreads();
            compute(i % 3);
            __syncthreads();
        }
    } else {
        issue(0, 0);
#pragma unroll 1
        for (int i = 0; i < nchunk; i++) {
            if (i + 1 < nchunk) { issue(i + 1, (i + 1) & 1); cp_wait<1>(); }
            else                { cp_wait<0>(); }
            __syncthreads();
            compute(i & 1);
            __syncthreads();
        }
    }

    if (EPI == 0) {
        const long long cb = bz * sC;
#pragma unroll
        for (int ms = 0; ms < 4; ms++) {
#pragma unroll
            for (int ns = 0; ns < 4; ns++) {
                int r0 = wm * 64 + ms * 16 + (lane >> 2);
                int c0 = n0 + wn * 32 + ns * 8 + (lane & 3) * 2;
#pragma unroll
                for (int half = 0; half < 2; half++) {
                    long long r = m0 + r0 + half * 8;
                    float vx = acc[ms][ns][half * 2 + 0];
                    float vy = acc[ms][ns][half * 2 + 1];
                    if (bias)   { vx += bias[c0]; vy += bias[c0 + 1]; }
                    if (addsrc) {
                        float2 s = *reinterpret_cast<const float2*>(addsrc + r * ldc + c0);
                        vx += s.x; vy += s.y;
                    }
                    if (do_gelu) { vx = gelu_tanh(vx); vy = gelu_tanh(vy); }
                    long long o = cb + r * ldc + c0;
                    if (outF)
                        *reinterpret_cast<float2*>(outF + o) = make_float2(vx, vy);
                    if (outHi) {
                        __nv_bfloat162 h, l;
                        bf16_split2(vx, vy, h, l);
                        *reinterpret_cast<__nv_bfloat162*>(outHi + o) = h;
                        *reinterpret_cast<__nv_bfloat162*>(outLo + o) = l;
                    }
                }
            }
        }
    } else {
        // stage z tile into smem (unscaling for scaled-A paths), batched ODE elementwise
        float* zsm = reinterpret_cast<float*>(smem);
        const float zs = (PROD == 3) ? 1.0f : AINV;
#pragma unroll
        for (int ms = 0; ms < 4; ms++)
#pragma unroll
            for (int ns = 0; ns < 4; ns++) {
                int r0 = wm * 64 + ms * 16 + (lane >> 2);
                int c0 = wn * 32 + ns * 8 + (lane & 3) * 2;
                zsm[r0 * 132 + c0]     = acc[ms][ns][0] * zs;
                zsm[r0 * 132 + c0 + 1] = acc[ms][ns][1] * zs;
                zsm[(r0 + 8) * 132 + c0]     = acc[ms][ns][2] * zs;
                zsm[(r0 + 8) * 132 + c0 + 1] = acc[ms][ns][3] * zs;
            }
        __syncthreads();
        const int h = (int)(bz & 15);
        __half* Xout = reinterpret_cast<__half*>(outHi);
#pragma unroll 1
        for (int ib = 0; ib < 2; ib++) {
            float2 a2[8], b2[8], d1a[8], d1b[8];
            int r8[8], cp8[8];
            size_t base8[8];
#pragma unroll
            for (int j = 0; j < 8; j++) {
                int lin = (ib * 8 + j) * 256 + tid;
                int r = lin >> 5, cp = (lin & 31) * 2;
                r8[j] = r; cp8[j] = cp;
                size_t base = ((size_t)bz * SS + m0 + r) * 128 + cp;
                base8[j] = base;
                a2[j] = *reinterpret_cast<const float2*>(abf + base);
                b2[j] = *reinterpret_cast<const float2*>(abf + base + 64);
                if (EPI == 2) {
                    d1a[j] = *reinterpret_cast<const float2*>(d1f + base);
                    d1b[j] = *reinterpret_cast<const float2*>(d1f + base + 64);
                }
            }
#pragma unroll
            for (int j = 0; j < 8; j++) {
                int r = r8[j], cp = cp8[j];
                size_t base = base8[j];
                size_t row = (size_t)bz * SS + m0 + r;
                float2 om2 = *reinterpret_cast<const float2*>(omg + h * 64 + cp);
                float za0 = zsm[r * 132 + cp],     za1 = zsm[r * 132 + cp + 1];
                float zb0 = zsm[r * 132 + cp + 64], zb1 = zsm[r * 132 + cp + 65];
                float ra0 = za0 * CA_C + zb0 * SA_C, rb0 = zb0 * CA_C - za0 * SA_C;
                float ra1 = za1 * CA_C + zb1 * SA_C, rb1 = zb1 * CA_C - za1 * SA_C;
                if (EPI == 1) {
                    if (flag)
                        *reinterpret_cast<float2*>(attnv + row * 64 + cp) =
                            make_float2(za0, za1);
                    float r20 = a2[j].x * a2[j].x + b2[j].x * b2[j].x;
                    float r21 = a2[j].y * a2[j].y + b2[j].y * b2[j].y;
                    float da0 = (MU_C - r20) * a2[j].x - om2.x * b2[j].x + K_C * (ra0 - a2[j].x);
                    float db0 = (MU_C - r20) * b2[j].x + om2.x * a2[j].x + K_C * (rb0 - b2[j].x);
                    float da1 = (MU_C - r21) * a2[j].y - om2.y * b2[j].y + K_C * (ra1 - a2[j].y);
                    float db1 = (MU_C - r21) * b2[j].y + om2.y * a2[j].y + K_C * (rb1 - b2[j].y);
                    *reinterpret_cast<float2*>(d1f + base)      = make_float2(da0, da1);
                    *reinterpret_cast<float2*>(d1f + base + 64) = make_float2(db0, db1);
                    float ap0 = a2[j].x + DT_C * da0, ap1 = a2[j].y + DT_C * da1;
                    float bp0 = b2[j].x + DT_C * db0, bp1 = b2[j].y + DT_C * db1;
                    *reinterpret_cast<__half2*>(Xout + base) = __floats2half2_rn(ap0, ap1);
                    *reinterpret_cast<__half2*>(Xout + base + 64) = __floats2half2_rn(bp0, bp1);
                } else {
                    float ap0 = a2[j].x + DT_C * d1a[j].x, ap1 = a2[j].y + DT_C * d1a[j].y;
                    float bp0 = b2[j].x + DT_C * d1b[j].x, bp1 = b2[j].y + DT_C * d1b[j].y;
                    float r20 = ap0 * ap0 + bp0 * bp0;
                    float r21 = ap1 * ap1 + bp1 * bp1;
                    float da20 = (MU_C - r20) * ap0 - om2.x * bp0 + K_C * (ra0 - ap0);
                    float db20 = (MU_C - r20) * bp0 + om2.x * ap0 + K_C * (rb0 - bp0);
                    float da21 = (MU_C - r21) * ap1 - om2.y * bp1 + K_C * (ra1 - ap1);
                    float db21 = (MU_C - r21) * bp1 + om2.y * ap1 + K_C * (rb1 - bp1);
                    float an0 = a2[j].x + 0.5f * DT_C * (d1a[j].x + da20);
                    float an1 = a2[j].y + 0.5f * DT_C * (d1a[j].y + da21);
                    float bn0 = b2[j].x + 0.5f * DT_C * (d1b[j].x + db20);
                    float bn1 = b2[j].y + 0.5f * DT_C * (d1b[j].y + db21);
                    *reinterpret_cast<float2*>(abf + base)      = make_float2(an0, an1);
                    *reinterpret_cast<float2*>(abf + base + 64) = make_float2(bn0, bn1);
                    if (flag) {
                        float2 av = *reinterpret_cast<const float2*>(attnv + row * 64 + cp);
                        *reinterpret_cast<float2*>(mixed + row * 64 + cp) =
                            make_float2(MIX_C * av.x + (1.0f - MIX_C) * an0,
                                        MIX_C * av.y + (1.0f - MIX_C) * an1);
                    } else {
                        *reinterpret_cast<__half2*>(Xout + base) = __floats2half2_rn(an0, an1);
                        *reinterpret_cast<__half2*>(Xout + base + 64) = __floats2half2_rn(bn0, bn1);
                    }
                }
            }
        }
    }
}

// ---------------- fp32 -> bf16 hi/lo split ----------------
__global__ void splitW_kernel(const float* __restrict__ A,
                              __nv_bfloat16* __restrict__ hi, __nv_bfloat16* __restrict__ lo)
{
    size_t i = ((size_t)blockIdx.x * blockDim.x + threadIdx.x) * 4;
    float4 v = *reinterpret_cast<const float4*>(A + i);
    __nv_bfloat162 h0, h1, l0, l1;
    bf16_split2(v.x, v.y, h0, l0);
    bf16_split2(v.z, v.w, h1, l1);
    *reinterpret_cast<__nv_bfloat162*>(hi + i)     = h0;
    *reinterpret_cast<__nv_bfloat162*>(hi + i + 2) = h1;
    *reinterpret_cast<__nv_bfloat162*>(lo + i)     = l0;
    *reinterpret_cast<__nv_bfloat162*>(lo + i + 2) = l1;
}

// ---------------- LayerNorm ----------------
__global__ void ln_kernel(const float* __restrict__ x, const float* __restrict__ g,
                          const float* __restrict__ be, float* __restrict__ out,
                          __nv_bfloat16* __restrict__ outHi, __nv_bfloat16* __restrict__ outLo)
{
    __shared__ float sh[8];
    size_t row = blockIdx.x;
    int tid = threadIdx.x, lane = tid & 31, wid = tid >> 5;
    float4 v = reinterpret_cast<const float4*>(x + row * DD)[tid];

    float s = v.x + v.y + v.z + v.w;
#pragma unroll
    for (int o = 16; o; o >>= 1) s += __shfl_xor_sync(0xffffffffu, s, o);
    if (lane == 0) sh[wid] = s;
    __syncthreads();
    float tot = 0.f;
#pragma unroll
    for (int i = 0; i < 8; i++) tot += sh[i];
    float mean = tot * (1.0f / DD);

    float dx = v.x - mean, dy = v.y - mean, dz = v.z - mean, dw = v.w - mean;
    float s2 = dx*dx + dy*dy + dz*dz + dw*dw;
#pragma unroll
    for (int o = 16; o; o >>= 1) s2 += __shfl_xor_sync(0xffffffffu, s2, o);
    __syncthreads();
    if (lane == 0) sh[wid] = s2;
    __syncthreads();
    float tot2 = 0.f;
#pragma unroll
    for (int i = 0; i < 8; i++) tot2 += sh[i];
    float rstd = rsqrtf(tot2 * (1.0f / DD) + 1e-5f);

    float4 gv = reinterpret_cast<const float4*>(g)[tid];
    float4 bv = reinterpret_cast<const float4*>(be)[tid];
    float4 o4;
    o4.x = dx * rstd * gv.x + bv.x;
    o4.y = dy * rstd * gv.y + bv.y;
    o4.z = dz * rstd * gv.z + bv.z;
    o4.w = dw * rstd * gv.w + bv.w;
    reinterpret_cast<float4*>(out + row * DD)[tid] = o4;
    if (outHi) {
        size_t i = row * DD + tid * 4;
        __nv_bfloat162 h0, h1, l0, l1;
        bf16_split2(o4.x, o4.y, h0, l0);
        bf16_split2(o4.z, o4.w, h1, l1);
        *reinterpret_cast<__nv_bfloat162*>(outHi + i)     = h0;
        *reinterpret_cast<__nv_bfloat162*>(outHi + i + 2) = h1;
        *reinterpret_cast<__nv_bfloat162*>(outLo + i)     = l0;
        *reinterpret_cast<__nv_bfloat162*>(outLo + i + 2) = l1;
    }
}

// ---------------- QKV projection (3-way parallel) ----------------
__global__ void qkv_kernel(const float* __restrict__ xn,
                           const float* __restrict__ Wq, const float* __restrict__ Wk,
                           const float* __restrict__ Wv,
                           __nv_bfloat16* __restrict__ qhi, __nv_bfloat16* __restrict__ qlo,
                           __nv_bfloat16* __restrict__ khi, __nv_bfloat16* __restrict__ klo,
                           float* __restrict__ ab, __nv_bfloat16* __restrict__ abX)
{
    __shared__ float sx[64][65];
    __shared__ float sw[64][65];
    int bh = blockIdx.y, b = bh >> 4, h = bh & 15;
    int wsel = blockIdx.z;
    int s0 = blockIdx.x * 64;
    int tid = threadIdx.x;

    const float* W = (wsel == 0 ? Wq : (wsel == 1 ? Wk : Wv)) + h * 4096;
    for (int idx = tid; idx < 4096; idx += 256) {
        int r = idx >> 6, d = idx & 63;
        sx[r][d] = xn[((size_t)(b * SS + s0 + r)) * DD + h * 64 + d];
        sw[r][d] = W[idx];
    }
    __syncthreads();
    int e = tid & 63, rq = tid >> 6;
    __half* Xp = reinterpret_cast<__half*>(abX);
#pragma unroll
    for (int i = 0; i < 16; i++) {
        int r = rq * 16 + i;
        float acc = 0.f;
#pragma unroll
        for (int d = 0; d < 64; d++) acc = fmaf(sx[r][d], sw[d][e], acc);
        size_t srow = (size_t)bh * SS + s0 + r;
        if (wsel == 0) {
            __nv_bfloat16 hi = __float2bfloat16(acc);
            qhi[srow * 64 + e] = hi;
            qlo[srow * 64 + e] = __float2bfloat16(acc - __bfloat162float(hi));
        } else if (wsel == 1) {
            __nv_bfloat16 hi = __float2bfloat16(acc);
            khi[srow * 64 + e] = hi;
            klo[srow * 64 + e] = __float2bfloat16(acc - __bfloat162float(hi));
        } else {
            ab[srow * 128 + e] = acc; ab[srow * 128 + 64 + e] = 0.f;
            Xp[srow * 128 + e] = __float2half(acc);
            Xp[srow * 128 + 64 + e] = __float2half(0.f);
        }
    }
}

// ---------------- fused softmax + scaled fp16 emit (hi only) ----------------
__global__ void softmax_split_kernel(const float* __restrict__ S,
                                     __nv_bfloat16* __restrict__ Ahi)
{
    __shared__ float sh[8];
    size_t row = blockIdx.x;
    const float* p = S + row * (size_t)SS;
    int tid = threadIdx.x, lane = tid & 31, wid = tid >> 5;

    float4 v0 = reinterpret_cast<const float4*>(p)[tid];
    float4 v1 = reinterpret_cast<const float4*>(p)[tid + 256];
    const float sc = 0.125f;
    v0.x *= sc; v0.y *= sc; v0.z *= sc; v0.w *= sc;
    v1.x *= sc; v1.y *= sc; v1.z *= sc; v1.w *= sc;

    float mx = fmaxf(fmaxf(fmaxf(v0.x, v0.y), fmaxf(v0.z, v0.w)),
                     fmaxf(fmaxf(v1.x, v1.y), fmaxf(v1.z, v1.w)));
#pragma unroll
    for (int o = 16; o; o >>= 1) mx = fmaxf(mx, __shfl_xor_sync(0xffffffffu, mx, o));
    if (lane == 0) sh[wid] = mx;
    __syncthreads();
    float m = sh[0];
#pragma unroll
    for (int i = 1; i < 8; i++) m = fmaxf(m, sh[i]);

    v0.x = expf(v0.x - m); v0.y = expf(v0.y - m);
    v0.z = expf(v0.z - m); v0.w = expf(v0.w - m);
    v1.x = expf(v1.x - m); v1.y = expf(v1.y - m);
    v1.z = expf(v1.z - m); v1.w = expf(v1.w - m);

    float s = v0.x + v0.y + v0.z + v0.w + v1.x + v1.y + v1.z + v1.w;
#pragma unroll
    for (int o = 16; o; o >>= 1) s += __shfl_xor_sync(0xffffffffu, s, o);
    __syncthreads();
    if (lane == 0) sh[wid] = s;
    __syncthreads();
    float tot = 0.f;
#pragma unroll
    for (int i = 0; i < 8; i++) tot += sh[i];
    float inv = ASCALE / tot;        // fold x2048 scale into normalization

    size_t ob = row * (size_t)SS;
    __half* Ah = reinterpret_cast<__half*>(Ahi);
    *reinterpret_cast<__half2*>(Ah + ob + tid * 4)     = __floats2half2_rn(v0.x * inv, v0.y * inv);
    *reinterpret_cast<__half2*>(Ah + ob + tid * 4 + 2) = __floats2half2_rn(v0.z * inv, v0.w * inv);
    *reinterpret_cast<__half2*>(Ah + ob + (tid + 256) * 4)     = __floats2half2_rn(v1.x * inv, v1.y * inv);
    *reinterpret_cast<__half2*>(Ah + ob + (tid + 256) * 4 + 2) = __floats2half2_rn(v1.z * inv, v1.w * inv);
}

// ---------------- head projection + residual ----------------
__global__ void headout_kernel(const float* __restrict__ mix, const float* __restrict__ Wo,
                               const float* __restrict__ x, float* __restrict__ x1)
{
    __shared__ float sx[64][65];
    __shared__ float sw[64][65];
    int bh = blockIdx.y, b = bh >> 4, h = bh & 15;
    int s0 = blockIdx.x * 64;
    int tid = threadIdx.x;

    for (int idx = tid; idx < 4096; idx += 256) {
        int r = idx >> 6, d = idx & 63;
        sx[r][d] = mix[((size_t)bh * SS + s0 + r) * 64 + d];
        sw[r][d] = Wo[h * 4096 + idx];
    }
    __syncthreads();
    int e = tid & 63, rq = tid >> 6;
#pragma unroll
    for (int i = 0; i < 16; i++) {
        int r = rq * 16 + i;
        float acc = 0.f;
#pragma unroll
        for (int d = 0; d < 64; d++) acc = fmaf(sx[r][d], sw[d][e], acc);
        size_t o = ((size_t)(b * SS + s0 + r)) * DD + h * 64 + e;
        x1[o] = x[o] + acc;
    }
}

// ---------------- host side ----------------
extern "C" void kernel_launch(void* const* d_in, const int* in_sizes, int n_in,
                              void* d_out, int out_size)
{
    const float* x   = (const float*)d_in[0];
    const float* Wq  = (const float*)d_in[1];
    const float* Wk  = (const float*)d_in[2];
    const float* Wv  = (const float*)d_in[3];
    const float* Wo  = (const float*)d_in[4];
    const float* om  = (const float*)d_in[5];
    const float* g1  = (const float*)d_in[6];
    const float* be1 = (const float*)d_in[7];
    const float* g2  = (const float*)d_in[8];
    const float* be2 = (const float*)d_in[9];
    const float* W1  = (const float*)d_in[10];
    const float* bf1 = (const float*)d_in[11];
    const float* W2  = (const float*)d_in[12];
    const float* bf2 = (const float*)d_in[13];
    float* out = (float*)d_out;
    (void)in_sizes; (void)n_in; (void)out_size;

    float *S_, *xn, *ab, *d1, *attnv, *mixb, *x1;
    __nv_bfloat16 *Ahi, *xnhi, *xnlo, *qhi, *qlo, *khi, *klo;
    __nv_bfloat16 *abX, *pX, *ffhi, *fflo;
    __nv_bfloat16 *W1hi, *W1lo, *W2hi, *W2lo;
    cudaGetSymbolAddress((void**)&S_,    g_S);
    cudaGetSymbolAddress((void**)&Ahi,   g_Ahi);
    cudaGetSymbolAddress((void**)&xn,    g_xn);
    cudaGetSymbolAddress((void**)&xnhi,  g_xnhi);
    cudaGetSymbolAddress((void**)&xnlo,  g_xnlo);
    cudaGetSymbolAddress((void**)&qhi,   g_qhi);
    cudaGetSymbolAddress((void**)&qlo,   g_qlo);
    cudaGetSymbolAddress((void**)&khi,   g_khi);
    cudaGetSymbolAddress((void**)&klo,   g_klo);
    cudaGetSymbolAddress((void**)&ab,    g_ab);
    cudaGetSymbolAddress((void**)&d1,    g_d1);
    cudaGetSymbolAddress((void**)&abX,   g_abX);
    cudaGetSymbolAddress((void**)&pX,    g_pX);
    cudaGetSymbolAddress((void**)&attnv, g_attnv);
    cudaGetSymbolAddress((void**)&mixb,  g_mix);
    cudaGetSymbolAddress((void**)&x1,    g_x1);
    cudaGetSymbolAddress((void**)&ffhi,  g_ffhi);
    cudaGetSymbolAddress((void**)&fflo,  g_fflo);
    cudaGetSymbolAddress((void**)&W1hi,  g_W1hi);
    cudaGetSymbolAddress((void**)&W1lo,  g_W1lo);
    cudaGetSymbolAddress((void**)&W2hi,  g_W2hi);
    cudaGetSymbolAddress((void**)&W2lo,  g_W2lo);

    cudaFuncSetAttribute(hgemm_kernel<true, 0, 3>,
                         cudaFuncAttributeMaxDynamicSharedMemorySize, HSMEM3);
    cudaFuncSetAttribute(hgemm_kernel<false, 0, 3>,
                         cudaFuncAttributeMaxDynamicSharedMemorySize, HSMEM3);
    cudaFuncSetAttribute(hgemm_kernel<true, 1, 1>,
                         cudaFuncAttributeMaxDynamicSharedMemorySize, HSMEM1);
    cudaFuncSetAttribute(hgemm_kernel<true, 2, 1>,
                         cudaFuncAttributeMaxDynamicSharedMemorySize, HSMEM1);

    const long long sQK = (long long)SS * 64;
    const long long sAA = (long long)SS * SS;
    const long long sAB = (long long)SS * 128;

    splitW_kernel<<<(unsigned)((size_t)DD * DFFC / 1024), 256>>>(W1, W1hi, W1lo);
    splitW_kernel<<<(unsigned)((size_t)DFFC * DD / 1024), 256>>>(W2, W2hi, W2lo);

    // 1. LN1
    ln_kernel<<<NTOK, 256>>>(x, g1, be1, xn, nullptr, nullptr);
    // 2. QKV (3-way parallel); v -> fp32 ab + fp16 X
    qkv_kernel<<<dim3(SS / 64, BH, 3), 256>>>(xn, Wq, Wk, Wv, qhi, qlo, khi, klo,
                                              ab, abX);
    // 3. scores (bf16 3-product)
    hgemm_kernel<false, 0, 3><<<dim3(16, 16, BH), 256, HSMEM3>>>(
        qhi, qlo, khi, klo, 64, 64, 64, SS, sQK, sQK, sAA,
        S_, nullptr, nullptr, nullptr, nullptr, 0,
        nullptr, nullptr, nullptr, nullptr, nullptr, 0);
    // 4. softmax + scaled fp16 emit (hi only)
    softmax_split_kernel<<<BH * SS, 256>>>(S_, Ahi);
    // 5. Heun loop: fp16 1-product GEMM (2 CTAs/SM) + fused ODE epilogues
    for (int st = 0; st < 5; st++) {
        hgemm_kernel<true, 1, 1><<<dim3(1, 16, BH), 256, HSMEM1>>>(
            Ahi, nullptr, abX, nullptr, SS, SS, 128, 128, sAA, sAB, sAB,
            nullptr, pX, nullptr, nullptr, nullptr, 0,
            om, ab, d1, attnv, nullptr, st == 0 ? 1 : 0);
        hgemm_kernel<true, 2, 1><<<dim3(1, 16, BH), 256, HSMEM1>>>(
            Ahi, nullptr, pX, nullptr, SS, SS, 128, 128, sAA, sAB, sAB,
            nullptr, abX, nullptr, nullptr, nullptr, 0,
            om, ab, d1, attnv, mixb, st == 4 ? 1 : 0);
    }
    // 6. head projection + residual
    headout_kernel<<<dim3(SS / 64, BH), 256>>>(mixb, Wo, x, x1);
    // 7. LN2
    ln_kernel<<<NTOK, 256>>>(x1, g2, be2, xn, xnhi, xnlo);
    // 8. FFN1 (bf16 3-product)
    hgemm_kernel<true, 0, 3><<<dim3(16, 32, 1), 256, HSMEM3>>>(
        xnhi, xnlo, W1hi, W1lo, DD, DD, DFFC, DFFC, 0, 0, 0,
        nullptr, ffhi, fflo, bf1, nullptr, 1,
        nullptr, nullptr, nullptr, nullptr, nullptr, 0);
    // 9. FFN2 (bf16 3-product)
    hgemm_kernel<true, 0, 3><<<dim3(8, 32, 1), 256, HSMEM3>>>(
        ffhi, fflo, W2hi, W2lo, DFFC, DFFC, DD, DD, 0, 0, 0,
        out, nullptr, nullptr, bf2, x1, 0,
        nullptr, nullptr, nullptr, nullptr, nullptr, 0);
}

// round 11
// speedup vs baseline: 2.2641x; 1.0113x over previous
#include <cuda_runtime.h>
#include <cuda_bf16.h>
#include <cuda_fp16.h>
#include <math.h>
#include <stddef.h>
#include <stdint.h>

// ---------------- problem constants ----------------
#define BB   2
#define SS   2048
#define DD   1024
#define HH   16
#define HDIM 64
#define DFFC 2048
#define BH   (BB*HH)
#define NTOK (BB*SS)

#define MU_C   1.0f
#define K_C    3.0f
#define DT_C   0.02f
#define MIX_C  0.3f
#define CA_C   0.9950041652780258f
#define SA_C   0.09983341664682815f
#define ASCALE 2048.0f
#define AINV   (1.0f / 2048.0f)

// ---------------- scratch ----------------
__device__ __half g_S [(size_t)BH * SS * SS];           // fp16 raw scores
__device__ __half g_Ahi[(size_t)BH * SS * SS];          // fp16 scaled A
__device__ float g_xn  [(size_t)NTOK * DD];
__device__ __half g_xnhi[(size_t)NTOK * DD];
__device__ __half g_xnlo[(size_t)NTOK * DD];
__device__ __half g_qhi[(size_t)BH * SS * 64];
__device__ __half g_qlo[(size_t)BH * SS * 64];
__device__ __half g_khi[(size_t)BH * SS * 64];
__device__ float g_ab  [(size_t)BH * SS * 128];
__device__ float g_d1  [(size_t)BH * SS * 128];
__device__ __half g_abX[(size_t)BH * SS * 128];         // fp16 X state
__device__ __half g_pX [(size_t)BH * SS * 128];         // fp16 X predictor
__device__ float g_attnv[(size_t)BH * SS * 64];
__device__ float g_mix  [(size_t)BH * SS * 64];
__device__ float g_x1   [(size_t)NTOK * DD];
__device__ __half g_ffhi[(size_t)NTOK * DFFC];
__device__ __half g_fflo[(size_t)NTOK * DFFC];
__device__ __half g_W1h[(size_t)DD * DFFC];
__device__ __half g_W2h[(size_t)DFFC * DD];

// ---------------- low-level helpers ----------------
__device__ __forceinline__ uint32_t smem_u32(const void* p) {
    uint32_t a;
    asm("{ .reg .u64 t; cvta.to.shared.u64 t, %1; cvt.u32.u64 %0, t; }" : "=r"(a) : "l"(p));
    return a;
}
__device__ __forceinline__ void cp16(uint32_t s, const void* g) {
    asm volatile("cp.async.cg.shared.global [%0], [%1], 16;" :: "r"(s), "l"(g));
}
__device__ __forceinline__ void cp_commit() {
    asm volatile("cp.async.commit_group;" ::: "memory");
}
template <int N>
__device__ __forceinline__ void cp_wait() {
    asm volatile("cp.async.wait_group %0;" :: "n"(N) : "memory");
}
__device__ __forceinline__ void ldm_x4(uint32_t* r, uint32_t addr) {
    asm volatile("ldmatrix.sync.aligned.m8n8.x4.shared.b16 {%0,%1,%2,%3}, [%4];"
        : "=r"(r[0]), "=r"(r[1]), "=r"(r[2]), "=r"(r[3]) : "r"(addr));
}
__device__ __forceinline__ void ldm_x4t(uint32_t* r, uint32_t addr) {
    asm volatile("ldmatrix.sync.aligned.m8n8.x4.trans.shared.b16 {%0,%1,%2,%3}, [%4];"
        : "=r"(r[0]), "=r"(r[1]), "=r"(r[2]), "=r"(r[3]) : "r"(addr));
}
__device__ __forceinline__ void mma_f16(float* c, const uint32_t* a, const uint32_t* b) {
    asm volatile("mma.sync.aligned.m16n8k16.row.col.f32.f16.f16.f32 "
        "{%0,%1,%2,%3}, {%4,%5,%6,%7}, {%8,%9}, {%0,%1,%2,%3};"
        : "+f"(c[0]), "+f"(c[1]), "+f"(c[2]), "+f"(c[3])
        : "r"(a[0]), "r"(a[1]), "r"(a[2]), "r"(a[3]), "r"(b[0]), "r"(b[1]));
}
__device__ __forceinline__ float gelu_tanh(float x) {
    float x3 = x * x * x;
    float t  = tanhf(0.7978845608028654f * (x + 0.044715f * x3));
    return 0.5f * x * (1.0f + t);
}

// ---------------- unified fp16 HMMA GEMM, fusable ODE epilogue ----------------
// EPI: 0 = plain C output; 1 = fused ode_ew1; 2 = fused ode_ew2.
// PROD: 2 = fp16 2-product ((Ahi+Alo) @ Bhi).  1 = fp16 1-product (Ahi @ Bhi).
// EPI0 outputs: outF!=0 && flag==0 -> fp32; flag==1 -> fp16 into outF.
//               outHi/outLo !=0 -> fp16 hi/lo pair.
#define AST 72
#define BSTN 72
#define BSTT 136
#define STG2 55296
#define STG1 36864
#define HSMEM2 (3 * STG2)     // 165888, 1 CTA/SM
#define HSMEM1 (2 * STG1)     // 73728,  2 CTA/SM

template<bool TRANSB, int EPI, int PROD>
__global__ void __launch_bounds__(256)
hgemm_kernel(const __half* __restrict__ Ahi, const __half* __restrict__ Alo,
             const __half* __restrict__ Bhi,
             int K, int lda, int ldb, int ldc,
             long long sA, long long sB, long long sC,
             float* __restrict__ outF,
             __half* __restrict__ outHi, __half* __restrict__ outLo,
             const float* __restrict__ bias, const float* __restrict__ addsrc, int do_gelu,
             const float* __restrict__ omg, float* __restrict__ abf,
             float* __restrict__ d1f, float* __restrict__ attnv,
             float* __restrict__ mixed, int flag)
{
    constexpr int STGB  = (PROD == 2) ? STG2 : STG1;
    constexpr int OFFAL = 18432;                         // A-lo (PROD == 2)
    constexpr int OFFBH = (PROD == 1) ? 18432 : 36864;   // B-hi
    extern __shared__ char smem[];
    const uint32_t sb = smem_u32(smem);
    const int tid = threadIdx.x;
    const int lane = tid & 31, w = tid >> 5;
    const int wm = w >> 2, wn = w & 3;
    const int n0 = blockIdx.x * 128;
    const int m0 = blockIdx.y * 128;
    const long long bz = blockIdx.z;

    Ahi += bz * sA;
    if (PROD == 2) Alo += bz * sA;
    Bhi += bz * sB;

    float acc[4][4][4];
#pragma unroll
    for (int i = 0; i < 4; i++)
#pragma unroll
        for (int j = 0; j < 4; j++)
#pragma unroll
            for (int r = 0; r < 4; r++) acc[i][j][r] = 0.f;

    auto issue = [&](int chunk, int buf) {
        const int k0 = chunk << 6;
        const uint32_t st = sb + buf * STGB;
        {
            const int row = tid >> 3, col = (tid & 7) * 8;
            const __half* gH = Ahi + (size_t)(m0 + row) * lda + k0 + col;
            uint32_t s = st + (row * AST + col) * 2;
#pragma unroll
            for (int j = 0; j < 4; j++)
                cp16(s + j * 32 * (AST * 2), gH + (size_t)j * 32 * lda);
            if (PROD == 2) {
                const __half* gL = Alo + (size_t)(m0 + row) * lda + k0 + col;
#pragma unroll
                for (int j = 0; j < 4; j++)
                    cp16(s + OFFAL + j * 32 * (AST * 2), gL + (size_t)j * 32 * lda);
            }
        }
        if (TRANSB) {
            const int rk = tid >> 2, col = (tid & 3) * 8;
            const __half* gH = Bhi + (size_t)(k0 + rk) * ldb + n0 + col;
            uint32_t s = st + OFFBH + (rk * BSTT + col) * 2;
#pragma unroll
            for (int j = 0; j < 4; j++)
                cp16(s + j * 64, gH + j * 32);
        } else {
            const int rn = tid >> 3, col = (tid & 7) * 8;
            const __half* gH = Bhi + (size_t)(n0 + rn) * ldb + k0 + col;
            uint32_t s = st + OFFBH + (rn * BSTN + col) * 2;
#pragma unroll
            for (int j = 0; j < 4; j++)
                cp16(s + j * 32 * (BSTN * 2), gH + (size_t)j * 32 * ldb);
        }
        cp_commit();
    };

    auto compute = [&](int buf) {
        const uint32_t st = sb + buf * STGB;
#pragma unroll
        for (int k16 = 0; k16 < 4; k16++) {
            uint32_t afrH[4][4], afrL[4][4], bfrH[4][2];
#pragma unroll
            for (int ms = 0; ms < 4; ms++) {
                int row = wm * 64 + ms * 16 + (lane & 15);
                int col = k16 * 16 + (lane >> 4) * 8;
                ldm_x4(afrH[ms], st + (row * AST + col) * 2);
                if (PROD == 2)
                    ldm_x4(afrL[ms], st + OFFAL + (row * AST + col) * 2);
            }
            if (TRANSB) {
                const int mat = lane >> 3, rr = lane & 7;
#pragma unroll
                for (int p = 0; p < 2; p++) {
                    int rk = k16 * 16 + (mat & 1) * 8 + rr;
                    int cn = wn * 32 + p * 16 + (mat >> 1) * 8;
                    ldm_x4t(&bfrH[p * 2][0], st + OFFBH + (rk * BSTT + cn) * 2);
                }
            } else {
                const int mat = lane >> 3, rr = lane & 7;
#pragma unroll
                for (int p = 0; p < 2; p++) {
                    int rn = wn * 32 + p * 16 + (mat >> 1) * 8 + rr;
                    int ck = k16 * 16 + (mat & 1) * 8;
                    ldm_x4(&bfrH[p * 2][0], st + OFFBH + (rn * BSTN + ck) * 2);
                }
            }
#pragma unroll
            for (int ms = 0; ms < 4; ms++)
#pragma unroll
                for (int ns = 0; ns < 4; ns++) {
                    mma_f16(acc[ms][ns], afrH[ms], bfrH[ns]);
                    if (PROD == 2)
                        mma_f16(acc[ms][ns], afrL[ms], bfrH[ns]);
                }
        }
    };

    const int nchunk = K >> 6;
    if (PROD == 2) {
        issue(0, 0);
        if (nchunk > 1) issue(1, 1);
#pragma unroll 1
        for (int i = 0; i < nchunk; i++) {
            if (i + 2 < nchunk)      { issue(i + 2, (i + 2) % 3); cp_wait<2>(); }
            else if (i + 1 < nchunk) { cp_wait<1>(); }
            else                     { cp_wait<0>(); }
            __syncthreads();
            compute(i % 3);
            __syncthreads();
        }
    } else {
        issue(0, 0);
#pragma unroll 1
        for (int i = 0; i < nchunk; i++) {
            if (i + 1 < nchunk) { issue(i + 1, (i + 1) & 1); cp_wait<1>(); }
            else                { cp_wait<0>(); }
            __syncthreads();
            compute(i & 1);
            __syncthreads();
        }
    }

    if (EPI == 0) {
        const long long cb = bz * sC;
#pragma unroll
        for (int ms = 0; ms < 4; ms++) {
#pragma unroll
            for (int ns = 0; ns < 4; ns++) {
                int r0 = wm * 64 + ms * 16 + (lane >> 2);
                int c0 = n0 + wn * 32 + ns * 8 + (lane & 3) * 2;
#pragma unroll
                for (int half = 0; half < 2; half++) {
                    long long r = m0 + r0 + half * 8;
                    float vx = acc[ms][ns][half * 2 + 0];
                    float vy = acc[ms][ns][half * 2 + 1];
                    if (bias)   { vx += bias[c0]; vy += bias[c0 + 1]; }
                    if (addsrc) {
                        float2 s = *reinterpret_cast<const float2*>(addsrc + r * ldc + c0);
                        vx += s.x; vy += s.y;
                    }
                    if (do_gelu) { vx = gelu_tanh(vx); vy = gelu_tanh(vy); }
                    long long o = cb + r * ldc + c0;
                    if (outF) {
                        if (flag)   // fp16 output
                            *reinterpret_cast<__half2*>(
                                reinterpret_cast<__half*>(outF) + o) =
                                __floats2half2_rn(vx, vy);
                        else
                            *reinterpret_cast<float2*>(outF + o) = make_float2(vx, vy);
                    }
                    if (outHi) {
                        __half2 h = __floats2half2_rn(vx, vy);
                        float2 hf = __half22float2(h);
                        *reinterpret_cast<__half2*>(outHi + o) = h;
                        *reinterpret_cast<__half2*>(outLo + o) =
                            __floats2half2_rn(vx - hf.x, vy - hf.y);
                    }
                }
            }
        }
    } else {
        // stage z tile into smem (unscale by AINV), then batched ODE elementwise
        float* zsm = reinterpret_cast<float*>(smem);
#pragma unroll
        for (int ms = 0; ms < 4; ms++)
#pragma unroll
            for (int ns = 0; ns < 4; ns++) {
                int r0 = wm * 64 + ms * 16 + (lane >> 2);
                int c0 = wn * 32 + ns * 8 + (lane & 3) * 2;
                zsm[r0 * 132 + c0]     = acc[ms][ns][0] * AINV;
                zsm[r0 * 132 + c0 + 1] = acc[ms][ns][1] * AINV;
                zsm[(r0 + 8) * 132 + c0]     = acc[ms][ns][2] * AINV;
                zsm[(r0 + 8) * 132 + c0 + 1] = acc[ms][ns][3] * AINV;
            }
        __syncthreads();
        const int h = (int)(bz & 15);
        __half* Xout = outHi;
#pragma unroll 1
        for (int ib = 0; ib < 2; ib++) {
            float2 a2[8], b2[8], d1a[8], d1b[8];
            int r8[8], cp8[8];
            size_t base8[8];
#pragma unroll
            for (int j = 0; j < 8; j++) {
                int lin = (ib * 8 + j) * 256 + tid;
                int r = lin >> 5, cp = (lin & 31) * 2;
                r8[j] = r; cp8[j] = cp;
                size_t base = ((size_t)bz * SS + m0 + r) * 128 + cp;
                base8[j] = base;
                a2[j] = *reinterpret_cast<const float2*>(abf + base);
                b2[j] = *reinterpret_cast<const float2*>(abf + base + 64);
                if (EPI == 2) {
                    d1a[j] = *reinterpret_cast<const float2*>(d1f + base);
                    d1b[j] = *reinterpret_cast<const float2*>(d1f + base + 64);
                }
            }
#pragma unroll
            for (int j = 0; j < 8; j++) {
                int r = r8[j], cp = cp8[j];
                size_t base = base8[j];
                size_t row = (size_t)bz * SS + m0 + r;
                float2 om2 = *reinterpret_cast<const float2*>(omg + h * 64 + cp);
                float za0 = zsm[r * 132 + cp],     za1 = zsm[r * 132 + cp + 1];
                float zb0 = zsm[r * 132 + cp + 64], zb1 = zsm[r * 132 + cp + 65];
                float ra0 = za0 * CA_C + zb0 * SA_C, rb0 = zb0 * CA_C - za0 * SA_C;
                float ra1 = za1 * CA_C + zb1 * SA_C, rb1 = zb1 * CA_C - za1 * SA_C;
                if (EPI == 1) {
                    if (flag)
                        *reinterpret_cast<float2*>(attnv + row * 64 + cp) =
                            make_float2(za0, za1);
                    float r20 = a2[j].x * a2[j].x + b2[j].x * b2[j].x;
                    float r21 = a2[j].y * a2[j].y + b2[j].y * b2[j].y;
                    float da0 = (MU_C - r20) * a2[j].x - om2.x * b2[j].x + K_C * (ra0 - a2[j].x);
                    float db0 = (MU_C - r20) * b2[j].x + om2.x * a2[j].x + K_C * (rb0 - b2[j].x);
                    float da1 = (MU_C - r21) * a2[j].y - om2.y * b2[j].y + K_C * (ra1 - a2[j].y);
                    float db1 = (MU_C - r21) * b2[j].y + om2.y * a2[j].y + K_C * (rb1 - b2[j].y);
                    *reinterpret_cast<float2*>(d1f + base)      = make_float2(da0, da1);
                    *reinterpret_cast<float2*>(d1f + base + 64) = make_float2(db0, db1);
                    float ap0 = a2[j].x + DT_C * da0, ap1 = a2[j].y + DT_C * da1;
                    float bp0 = b2[j].x + DT_C * db0, bp1 = b2[j].y + DT_C * db1;
                    *reinterpret_cast<__half2*>(Xout + base) = __floats2half2_rn(ap0, ap1);
                    *reinterpret_cast<__half2*>(Xout + base + 64) = __floats2half2_rn(bp0, bp1);
                } else {
                    float ap0 = a2[j].x + DT_C * d1a[j].x, ap1 = a2[j].y + DT_C * d1a[j].y;
                    float bp0 = b2[j].x + DT_C * d1b[j].x, bp1 = b2[j].y + DT_C * d1b[j].y;
                    float r20 = ap0 * ap0 + bp0 * bp0;
                    float r21 = ap1 * ap1 + bp1 * bp1;
                    float da20 = (MU_C - r20) * ap0 - om2.x * bp0 + K_C * (ra0 - ap0);
                    float db20 = (MU_C - r20) * bp0 + om2.x * ap0 + K_C * (rb0 - bp0);
                    float da21 = (MU_C - r21) * ap1 - om2.y * bp1 + K_C * (ra1 - ap1);
                    float db21 = (MU_C - r21) * bp1 + om2.y * ap1 + K_C * (rb1 - bp1);
                    float an0 = a2[j].x + 0.5f * DT_C * (d1a[j].x + da20);
                    float an1 = a2[j].y + 0.5f * DT_C * (d1a[j].y + da21);
                    float bn0 = b2[j].x + 0.5f * DT_C * (d1b[j].x + db20);
                    float bn1 = b2[j].y + 0.5f * DT_C * (d1b[j].y + db21);
                    *reinterpret_cast<float2*>(abf + base)      = make_float2(an0, an1);
                    *reinterpret_cast<float2*>(abf + base + 64) = make_float2(bn0, bn1);
                    if (flag) {
                        float2 av = *reinterpret_cast<const float2*>(attnv + row * 64 + cp);
                        *reinterpret_cast<float2*>(mixed + row * 64 + cp) =
                            make_float2(MIX_C * av.x + (1.0f - MIX_C) * an0,
                                        MIX_C * av.y + (1.0f - MIX_C) * an1);
                    } else {
                        *reinterpret_cast<__half2*>(Xout + base) = __floats2half2_rn(an0, an1);
                        *reinterpret_cast<__half2*>(Xout + base + 64) = __floats2half2_rn(bn0, bn1);
                    }
                }
            }
        }
    }
}

// ---------------- fp32 -> fp16 (hi only) weight convert ----------------
__global__ void splitWh_kernel(const float* __restrict__ A, __half* __restrict__ h)
{
    size_t i = ((size_t)blockIdx.x * blockDim.x + threadIdx.x) * 4;
    float4 v = *reinterpret_cast<const float4*>(A + i);
    *reinterpret_cast<__half2*>(h + i)     = __floats2half2_rn(v.x, v.y);
    *reinterpret_cast<__half2*>(h + i + 2) = __floats2half2_rn(v.z, v.w);
}

// ---------------- LayerNorm (optional fp16 hi/lo outputs) ----------------
__global__ void ln_kernel(const float* __restrict__ x, const float* __restrict__ g,
                          const float* __restrict__ be, float* __restrict__ out,
                          __half* __restrict__ outHi, __half* __restrict__ outLo)
{
    __shared__ float sh[8];
    size_t row = blockIdx.x;
    int tid = threadIdx.x, lane = tid & 31, wid = tid >> 5;
    float4 v = reinterpret_cast<const float4*>(x + row * DD)[tid];

    float s = v.x + v.y + v.z + v.w;
#pragma unroll
    for (int o = 16; o; o >>= 1) s += __shfl_xor_sync(0xffffffffu, s, o);
    if (lane == 0) sh[wid] = s;
    __syncthreads();
    float tot = 0.f;
#pragma unroll
    for (int i = 0; i < 8; i++) tot += sh[i];
    float mean = tot * (1.0f / DD);

    float dx = v.x - mean, dy = v.y - mean, dz = v.z - mean, dw = v.w - mean;
    float s2 = dx*dx + dy*dy + dz*dz + dw*dw;
#pragma unroll
    for (int o = 16; o; o >>= 1) s2 += __shfl_xor_sync(0xffffffffu, s2, o);
    __syncthreads();
    if (lane == 0) sh[wid] = s2;
    __syncthreads();
    float tot2 = 0.f;
#pragma unroll
    for (int i = 0; i < 8; i++) tot2 += sh[i];
    float rstd = rsqrtf(tot2 * (1.0f / DD) + 1e-5f);

    float4 gv = reinterpret_cast<const float4*>(g)[tid];
    float4 bv = reinterpret_cast<const float4*>(be)[tid];
    float4 o4;
    o4.x = dx * rstd * gv.x + bv.x;
    o4.y = dy * rstd * gv.y + bv.y;
    o4.z = dz * rstd * gv.z + bv.z;
    o4.w = dw * rstd * gv.w + bv.w;
    reinterpret_cast<float4*>(out + row * DD)[tid] = o4;
    if (outHi) {
        size_t i = row * DD + tid * 4;
        __half2 h0 = __floats2half2_rn(o4.x, o4.y);
        __half2 h1 = __floats2half2_rn(o4.z, o4.w);
        float2 f0 = __half22float2(h0), f1 = __half22float2(h1);
        *reinterpret_cast<__half2*>(outHi + i)     = h0;
        *reinterpret_cast<__half2*>(outHi + i + 2) = h1;
        *reinterpret_cast<__half2*>(outLo + i)     = __floats2half2_rn(o4.x - f0.x, o4.y - f0.y);
        *reinterpret_cast<__half2*>(outLo + i + 2) = __floats2half2_rn(o4.z - f1.x, o4.w - f1.y);
    }
}

// ---------------- QKV projection (3-way parallel, 32 rows/block) ----------------
__global__ void qkv_kernel(const float* __restrict__ xn,
                           const float* __restrict__ Wq, const float* __restrict__ Wk,
                           const float* __restrict__ Wv,
                           __half* __restrict__ qhi, __half* __restrict__ qlo,
                           __half* __restrict__ khi,
                           float* __restrict__ ab, __half* __restrict__ abX)
{
    __shared__ float sx[32][65];
    __shared__ float sw[64][65];
    int bh = blockIdx.y, b = bh >> 4, h = bh & 15;
    int wsel = blockIdx.z;
    int s0 = blockIdx.x * 32;
    int tid = threadIdx.x;

    const float* W = (wsel == 0 ? Wq : (wsel == 1 ? Wk : Wv)) + h * 4096;
    for (int idx = tid; idx < 2048; idx += 256) {
        int r = idx >> 6, d = idx & 63;
        sx[r][d] = xn[((size_t)(b * SS + s0 + r)) * DD + h * 64 + d];
    }
    for (int idx = tid; idx < 4096; idx += 256)
        sw[idx >> 6][idx & 63] = W[idx];
    __syncthreads();
    int e = tid & 63, rq = tid >> 6;
#pragma unroll
    for (int i = 0; i < 8; i++) {
        int r = rq * 8 + i;
        float acc = 0.f;
#pragma unroll
        for (int d = 0; d < 64; d++) acc = fmaf(sx[r][d], sw[d][e], acc);
        size_t srow = (size_t)bh * SS + s0 + r;
        if (wsel == 0) {
            __half hi = __float2half(acc);
            qhi[srow * 64 + e] = hi;
            qlo[srow * 64 + e] = __float2half(acc - __half2float(hi));
        } else if (wsel == 1) {
            khi[srow * 64 + e] = __float2half(acc);
        } else {
            ab[srow * 128 + e] = acc; ab[srow * 128 + 64 + e] = 0.f;
            abX[srow * 128 + e] = __float2half(acc);
            abX[srow * 128 + 64 + e] = __float2half(0.f);
        }
    }
}

// ---------------- fused softmax (fp16 in) + scaled fp16 emit ----------------
__global__ void softmax_split_kernel(const __half* __restrict__ S,
                                     __half* __restrict__ Ahi)
{
    __shared__ float sh[8];
    size_t row = blockIdx.x;
    const __half* p = S + row * (size_t)SS;
    int tid = threadIdx.x, lane = tid & 31, wid = tid >> 5;

    float4 raw = reinterpret_cast<const float4*>(p)[tid];   // 8 halves
    const __half2* hp = reinterpret_cast<const __half2*>(&raw);
    float v[8];
#pragma unroll
    for (int i = 0; i < 4; i++) {
        float2 f = __half22float2(hp[i]);
        v[i * 2] = f.x * 0.125f; v[i * 2 + 1] = f.y * 0.125f;
    }

    float mx = v[0];
#pragma unroll
    for (int i = 1; i < 8; i++) mx = fmaxf(mx, v[i]);
#pragma unroll
    for (int o = 16; o; o >>= 1) mx = fmaxf(mx, __shfl_xor_sync(0xffffffffu, mx, o));
    if (lane == 0) sh[wid] = mx;
    __syncthreads();
    float m = sh[0];
#pragma unroll
    for (int i = 1; i < 8; i++) m = fmaxf(m, sh[i]);

    float s = 0.f;
#pragma unroll
    for (int i = 0; i < 8; i++) { v[i] = expf(v[i] - m); s += v[i]; }
#pragma unroll
    for (int o = 16; o; o >>= 1) s += __shfl_xor_sync(0xffffffffu, s, o);
    __syncthreads();
    if (lane == 0) sh[wid] = s;
    __syncthreads();
    float tot = 0.f;
#pragma unroll
    for (int i = 0; i < 8; i++) tot += sh[i];
    float inv = ASCALE / tot;

    size_t ob = row * (size_t)SS + tid * 8;
#pragma unroll
    for (int i = 0; i < 4; i++)
        *reinterpret_cast<__half2*>(Ahi + ob + i * 2) =
            __floats2half2_rn(v[i * 2] * inv, v[i * 2 + 1] * inv);
}

// ---------------- head projection + residual (32 rows/block) ----------------
__global__ void headout_kernel(const float* __restrict__ mix, const float* __restrict__ Wo,
                               const float* __restrict__ x, float* __restrict__ x1)
{
    __shared__ float sx[32][65];
    __shared__ float sw[64][65];
    int bh = blockIdx.y, b = bh >> 4, h = bh & 15;
    int s0 = blockIdx.x * 32;
    int tid = threadIdx.x;

    for (int idx = tid; idx < 2048; idx += 256) {
        int r = idx >> 6, d = idx & 63;
        sx[r][d] = mix[((size_t)bh * SS + s0 + r) * 64 + d];
    }
    for (int idx = tid; idx < 4096; idx += 256)
        sw[idx >> 6][idx & 63] = Wo[h * 4096 + idx];
    __syncthreads();
    int e = tid & 63, rq = tid >> 6;
#pragma unroll
    for (int i = 0; i < 8; i++) {
        int r = rq * 8 + i;
        float acc = 0.f;
#pragma unroll
        for (int d = 0; d < 64; d++) acc = fmaf(sx[r][d], sw[d][e], acc);
        size_t o = ((size_t)(b * SS + s0 + r)) * DD + h * 64 + e;
        x1[o] = x[o] + acc;
    }
}

// ---------------- host side ----------------
extern "C" void kernel_launch(void* const* d_in, const int* in_sizes, int n_in,
                              void* d_out, int out_size)
{
    const float* x   = (const float*)d_in[0];
    const float* Wq  = (const float*)d_in[1];
    const float* Wk  = (const float*)d_in[2];
    const float* Wv  = (const float*)d_in[3];
    const float* Wo  = (const float*)d_in[4];
    const float* om  = (const float*)d_in[5];
    const float* g1  = (const float*)d_in[6];
    const float* be1 = (const float*)d_in[7];
    const float* g2  = (const float*)d_in[8];
    const float* be2 = (const float*)d_in[9];
    const float* W1  = (const float*)d_in[10];
    const float* bf1 = (const float*)d_in[11];
    const float* W2  = (const float*)d_in[12];
    const float* bf2 = (const float*)d_in[13];
    float* out = (float*)d_out;
    (void)in_sizes; (void)n_in; (void)out_size;

    float *xn, *ab, *d1, *attnv, *mixb, *x1;
    __half *S_, *Ahi, *xnhi, *xnlo, *qhi, *qlo, *khi;
    __half *abX, *pX, *ffhi, *fflo, *W1h, *W2h;
    cudaGetSymbolAddress((void**)&S_,    g_S);
    cudaGetSymbolAddress((void**)&Ahi,   g_Ahi);
    cudaGetSymbolAddress((void**)&xn,    g_xn);
    cudaGetSymbolAddress((void**)&xnhi,  g_xnhi);
    cudaGetSymbolAddress((void**)&xnlo,  g_xnlo);
    cudaGetSymbolAddress((void**)&qhi,   g_qhi);
    cudaGetSymbolAddress((void**)&qlo,   g_qlo);
    cudaGetSymbolAddress((void**)&khi,   g_khi);
    cudaGetSymbolAddress((void**)&ab,    g_ab);
    cudaGetSymbolAddress((void**)&d1,    g_d1);
    cudaGetSymbolAddress((void**)&abX,   g_abX);
    cudaGetSymbolAddress((void**)&pX,    g_pX);
    cudaGetSymbolAddress((void**)&attnv, g_attnv);
    cudaGetSymbolAddress((void**)&mixb,  g_mix);
    cudaGetSymbolAddress((void**)&x1,    g_x1);
    cudaGetSymbolAddress((void**)&ffhi,  g_ffhi);
    cudaGetSymbolAddress((void**)&fflo,  g_fflo);
    cudaGetSymbolAddress((void**)&W1h,   g_W1h);
    cudaGetSymbolAddress((void**)&W2h,   g_W2h);

    cudaFuncSetAttribute(hgemm_kernel<true, 0, 2>,
                         cudaFuncAttributeMaxDynamicSharedMemorySize, HSMEM2);
    cudaFuncSetAttribute(hgemm_kernel<false, 0, 2>,
                         cudaFuncAttributeMaxDynamicSharedMemorySize, HSMEM2);
    cudaFuncSetAttribute(hgemm_kernel<true, 1, 1>,
                         cudaFuncAttributeMaxDynamicSharedMemorySize, HSMEM1);
    cudaFuncSetAttribute(hgemm_kernel<true, 2, 1>,
                         cudaFuncAttributeMaxDynamicSharedMemorySize, HSMEM1);

    const long long sQK = (long long)SS * 64;
    const long long sAA = (long long)SS * SS;
    const long long sAB = (long long)SS * 128;

    splitWh_kernel<<<(unsigned)((size_t)DD * DFFC / 1024), 256>>>(W1, W1h);
    splitWh_kernel<<<(unsigned)((size_t)DFFC * DD / 1024), 256>>>(W2, W2h);

    // 1. LN1
    ln_kernel<<<NTOK, 256>>>(x, g1, be1, xn, nullptr, nullptr);
    // 2. QKV (3-way parallel, 32 rows/block)
    qkv_kernel<<<dim3(SS / 32, BH, 3), 256>>>(xn, Wq, Wk, Wv, qhi, qlo, khi, ab, abX);
    // 3. scores (fp16 2-product) -> fp16 S
    hgemm_kernel<false, 0, 2><<<dim3(16, 16, BH), 256, HSMEM2>>>(
        qhi, qlo, khi, 64, 64, 64, SS, sQK, sQK, sAA,
        reinterpret_cast<float*>(S_), nullptr, nullptr, nullptr, nullptr, 0,
        nullptr, nullptr, nullptr, nullptr, nullptr, 1);
    // 4. softmax (fp16 in) + scaled fp16 A
    softmax_split_kernel<<<BH * SS, 256>>>(S_, Ahi);
    // 5. Heun loop: fp16 1-product GEMM (2 CTAs/SM) + fused ODE epilogues
    for (int st = 0; st < 5; st++) {
        hgemm_kernel<true, 1, 1><<<dim3(1, 16, BH), 256, HSMEM1>>>(
            Ahi, nullptr, abX, SS, SS, 128, 128, sAA, sAB, sAB,
            nullptr, pX, nullptr, nullptr, nullptr, 0,
            om, ab, d1, attnv, nullptr, st == 0 ? 1 : 0);
        hgemm_kernel<true, 2, 1><<<dim3(1, 16, BH), 256, HSMEM1>>>(
            Ahi, nullptr, pX, SS, SS, 128, 128, sAA, sAB, sAB,
            nullptr, abX, nullptr, nullptr, nullptr, 0,
            om, ab, d1, attnv, mixb, st == 4 ? 1 : 0);
    }
    // 6. head projection + residual (32 rows/block)
    headout_kernel<<<dim3(SS / 32, BH), 256>>>(mixb, Wo, x, x1);
    // 7. LN2 -> fp32 + fp16 hi/lo
    ln_kernel<<<NTOK, 256>>>(x1, g2, be2, xn, xnhi, xnlo);
    // 8. FFN1 (fp16 2-product): gelu(xn @ W1 + bf1) -> ff fp16 hi/lo
    hgemm_kernel<true, 0, 2><<<dim3(16, 32, 1), 256, HSMEM2>>>(
        xnhi, xnlo, W1h, DD, DD, DFFC, DFFC, 0, 0, 0,
        nullptr, ffhi, fflo, bf1, nullptr, 1,
        nullptr, nullptr, nullptr, nullptr, nullptr, 0);
    // 9. FFN2 (fp16 2-product): out = x1 + ff @ W2 + bf2 (fp32 out)
    hgemm_kernel<true, 0, 2><<<dim3(8, 32, 1), 256, HSMEM2>>>(
        ffhi, fflo, W2h, DFFC, DFFC, DD, DD, 0, 0, 0,
        out, nullptr, nullptr, bf2, x1, 0,
        nullptr, nullptr, nullptr, nullptr, nullptr, 0);
}

// round 12
// speedup vs baseline: 2.2862x; 1.0098x over previous
#include <cuda_runtime.h>
#include <cuda_bf16.h>
#include <cuda_fp16.h>
#include <math.h>
#include <stddef.h>
#include <stdint.h>

// ---------------- problem constants ----------------
#define BB   2
#define SS   2048
#define DD   1024
#define HH   16
#define HDIM 64
#define DFFC 2048
#define BH   (BB*HH)
#define NTOK (BB*SS)

#define MU_C   1.0f
#define K_C    3.0f
#define DT_C   0.02f
#define MIX_C  0.3f
#define CA_C   0.9950041652780258f
#define SA_C   0.09983341664682815f
#define ASCALE 2048.0f
#define AINV   (1.0f / 2048.0f)

// ---------------- scratch ----------------
__device__ __half g_S [(size_t)BH * SS * SS];           // fp16 raw scores
__device__ __half g_Ahi[(size_t)BH * SS * SS];          // fp16 scaled A
__device__ float g_xn  [(size_t)NTOK * DD];
__device__ __half g_xnhi[(size_t)NTOK * DD];
__device__ __half g_xnlo[(size_t)NTOK * DD];
__device__ __half g_qhi[(size_t)BH * SS * 64];
__device__ __half g_qlo[(size_t)BH * SS * 64];
__device__ __half g_khi[(size_t)BH * SS * 64];
__device__ float g_ab  [(size_t)BH * SS * 128];
__device__ float g_d1  [(size_t)BH * SS * 128];
__device__ __half g_abX[(size_t)BH * SS * 128];         // fp16 X state
__device__ __half g_pX [(size_t)BH * SS * 128];         // fp16 X predictor
__device__ float g_attnv[(size_t)BH * SS * 64];
__device__ float g_mix  [(size_t)BH * SS * 64];
__device__ float g_x1   [(size_t)NTOK * DD];
__device__ __half g_ffhi[(size_t)NTOK * DFFC];
__device__ __half g_fflo[(size_t)NTOK * DFFC];
__device__ __half g_W1h[(size_t)DD * DFFC];
__device__ __half g_W2h[(size_t)DFFC * DD];

// ---------------- low-level helpers ----------------
__device__ __forceinline__ uint32_t smem_u32(const void* p) {
    uint32_t a;
    asm("{ .reg .u64 t; cvta.to.shared.u64 t, %1; cvt.u32.u64 %0, t; }" : "=r"(a) : "l"(p));
    return a;
}
__device__ __forceinline__ void cp16(uint32_t s, const void* g) {
    asm volatile("cp.async.cg.shared.global [%0], [%1], 16;" :: "r"(s), "l"(g));
}
__device__ __forceinline__ void cp_commit() {
    asm volatile("cp.async.commit_group;" ::: "memory");
}
template <int N>
__device__ __forceinline__ void cp_wait() {
    asm volatile("cp.async.wait_group %0;" :: "n"(N) : "memory");
}
__device__ __forceinline__ void ldm_x4(uint32_t* r, uint32_t addr) {
    asm volatile("ldmatrix.sync.aligned.m8n8.x4.shared.b16 {%0,%1,%2,%3}, [%4];"
        : "=r"(r[0]), "=r"(r[1]), "=r"(r[2]), "=r"(r[3]) : "r"(addr));
}
__device__ __forceinline__ void ldm_x4t(uint32_t* r, uint32_t addr) {
    asm volatile("ldmatrix.sync.aligned.m8n8.x4.trans.shared.b16 {%0,%1,%2,%3}, [%4];"
        : "=r"(r[0]), "=r"(r[1]), "=r"(r[2]), "=r"(r[3]) : "r"(addr));
}
__device__ __forceinline__ void mma_f16(float* c, const uint32_t* a, const uint32_t* b) {
    asm volatile("mma.sync.aligned.m16n8k16.row.col.f32.f16.f16.f32 "
        "{%0,%1,%2,%3}, {%4,%5,%6,%7}, {%8,%9}, {%0,%1,%2,%3};"
        : "+f"(c[0]), "+f"(c[1]), "+f"(c[2]), "+f"(c[3])
        : "r"(a[0]), "r"(a[1]), "r"(a[2]), "r"(a[3]), "r"(b[0]), "r"(b[1]));
}
__device__ __forceinline__ float gelu_tanh(float x) {
    float x3 = x * x * x;
    float t  = tanhf(0.7978845608028654f * (x + 0.044715f * x3));
    return 0.5f * x * (1.0f + t);
}

// ---------------- unified fp16 HMMA GEMM, fusable ODE epilogue ----------------
// EPI: 0 = plain C output; 1 = fused ode_ew1; 2 = fused ode_ew2.
// PROD: 2 = fp16 2-product ((Ahi+Alo) @ Bhi).  1 = fp16 1-product (Ahi @ Bhi).
// EPI0 outputs: outF!=0 && flag==0 -> fp32; flag==1 -> fp16 into outF.
//               outHi/outLo !=0 -> fp16 hi/lo pair.
#define AST 72
#define BSTN 72
#define BSTT 136
#define STG2 55296
#define STG1 36864
#define HSMEM2 (3 * STG2)     // 165888, 1 CTA/SM
#define HSMEM1 (3 * STG1)     // 110592, 2 CTA/SM (221184 <= 227KB)

template<bool TRANSB, int EPI, int PROD>
__global__ void __launch_bounds__(256)
hgemm_kernel(const __half* __restrict__ Ahi, const __half* __restrict__ Alo,
             const __half* __restrict__ Bhi,
             int K, int lda, int ldb, int ldc,
             long long sA, long long sB, long long sC,
             float* __restrict__ outF,
             __half* __restrict__ outHi, __half* __restrict__ outLo,
             const float* __restrict__ bias, const float* __restrict__ addsrc, int do_gelu,
             const float* __restrict__ omg, float* __restrict__ abf,
             float* __restrict__ d1f, float* __restrict__ attnv,
             float* __restrict__ mixed, int flag)
{
    constexpr int STGB  = (PROD == 2) ? STG2 : STG1;
    constexpr int OFFAL = 18432;                         // A-lo (PROD == 2)
    constexpr int OFFBH = (PROD == 1) ? 18432 : 36864;   // B-hi
    extern __shared__ char smem[];
    const uint32_t sb = smem_u32(smem);
    const int tid = threadIdx.x;
    const int lane = tid & 31, w = tid >> 5;
    const int wm = w >> 2, wn = w & 3;
    const int n0 = blockIdx.x * 128;
    const int m0 = blockIdx.y * 128;
    const long long bz = blockIdx.z;

    Ahi += bz * sA;
    if (PROD == 2) Alo += bz * sA;
    Bhi += bz * sB;

    float acc[4][4][4];
#pragma unroll
    for (int i = 0; i < 4; i++)
#pragma unroll
        for (int j = 0; j < 4; j++)
#pragma unroll
            for (int r = 0; r < 4; r++) acc[i][j][r] = 0.f;

    auto issue = [&](int chunk, int buf) {
        const int k0 = chunk << 6;
        const uint32_t st = sb + buf * STGB;
        {
            const int row = tid >> 3, col = (tid & 7) * 8;
            const __half* gH = Ahi + (size_t)(m0 + row) * lda + k0 + col;
            uint32_t s = st + (row * AST + col) * 2;
#pragma unroll
            for (int j = 0; j < 4; j++)
                cp16(s + j * 32 * (AST * 2), gH + (size_t)j * 32 * lda);
            if (PROD == 2) {
                const __half* gL = Alo + (size_t)(m0 + row) * lda + k0 + col;
#pragma unroll
                for (int j = 0; j < 4; j++)
                    cp16(s + OFFAL + j * 32 * (AST * 2), gL + (size_t)j * 32 * lda);
            }
        }
        if (TRANSB) {
            const int rk = tid >> 2, col = (tid & 3) * 8;
            const __half* gH = Bhi + (size_t)(k0 + rk) * ldb + n0 + col;
            uint32_t s = st + OFFBH + (rk * BSTT + col) * 2;
#pragma unroll
            for (int j = 0; j < 4; j++)
                cp16(s + j * 64, gH + j * 32);
        } else {
            const int rn = tid >> 3, col = (tid & 7) * 8;
            const __half* gH = Bhi + (size_t)(n0 + rn) * ldb + k0 + col;
            uint32_t s = st + OFFBH + (rn * BSTN + col) * 2;
#pragma unroll
            for (int j = 0; j < 4; j++)
                cp16(s + j * 32 * (BSTN * 2), gH + (size_t)j * 32 * ldb);
        }
        cp_commit();
    };

    auto compute = [&](int buf) {
        const uint32_t st = sb + buf * STGB;
#pragma unroll
        for (int k16 = 0; k16 < 4; k16++) {
            uint32_t afrH[4][4], afrL[4][4], bfrH[4][2];
#pragma unroll
            for (int ms = 0; ms < 4; ms++) {
                int row = wm * 64 + ms * 16 + (lane & 15);
                int col = k16 * 16 + (lane >> 4) * 8;
                ldm_x4(afrH[ms], st + (row * AST + col) * 2);
                if (PROD == 2)
                    ldm_x4(afrL[ms], st + OFFAL + (row * AST + col) * 2);
            }
            if (TRANSB) {
                const int mat = lane >> 3, rr = lane & 7;
#pragma unroll
                for (int p = 0; p < 2; p++) {
                    int rk = k16 * 16 + (mat & 1) * 8 + rr;
                    int cn = wn * 32 + p * 16 + (mat >> 1) * 8;
                    ldm_x4t(&bfrH[p * 2][0], st + OFFBH + (rk * BSTT + cn) * 2);
                }
            } else {
                const int mat = lane >> 3, rr = lane & 7;
#pragma unroll
                for (int p = 0; p < 2; p++) {
                    int rn = wn * 32 + p * 16 + (mat >> 1) * 8 + rr;
                    int ck = k16 * 16 + (mat & 1) * 8;
                    ldm_x4(&bfrH[p * 2][0], st + OFFBH + (rn * BSTN + ck) * 2);
                }
            }
#pragma unroll
            for (int ms = 0; ms < 4; ms++)
#pragma unroll
                for (int ns = 0; ns < 4; ns++) {
                    mma_f16(acc[ms][ns], afrH[ms], bfrH[ns]);
                    if (PROD == 2)
                        mma_f16(acc[ms][ns], afrL[ms], bfrH[ns]);
                }
        }
    };

    const int nchunk = K >> 6;
    issue(0, 0);
    if (nchunk > 1) issue(1, 1);
#pragma unroll 1
    for (int i = 0; i < nchunk; i++) {
        if (i + 2 < nchunk)      { issue(i + 2, (i + 2) % 3); cp_wait<2>(); }
        else if (i + 1 < nchunk) { cp_wait<1>(); }
        else                     { cp_wait<0>(); }
        __syncthreads();
        compute(i % 3);
        __syncthreads();
    }

    if (EPI == 0) {
        const long long cb = bz * sC;
#pragma unroll
        for (int ms = 0; ms < 4; ms++) {
#pragma unroll
            for (int ns = 0; ns < 4; ns++) {
                int r0 = wm * 64 + ms * 16 + (lane >> 2);
                int c0 = n0 + wn * 32 + ns * 8 + (lane & 3) * 2;
#pragma unroll
                for (int half = 0; half < 2; half++) {
                    long long r = m0 + r0 + half * 8;
                    float vx = acc[ms][ns][half * 2 + 0];
                    float vy = acc[ms][ns][half * 2 + 1];
                    if (bias)   { vx += bias[c0]; vy += bias[c0 + 1]; }
                    if (addsrc) {
                        float2 s = *reinterpret_cast<const float2*>(addsrc + r * ldc + c0);
                        vx += s.x; vy += s.y;
                    }
                    if (do_gelu) { vx = gelu_tanh(vx); vy = gelu_tanh(vy); }
                    long long o = cb + r * ldc + c0;
                    if (outF) {
                        if (flag)   // fp16 output
                            *reinterpret_cast<__half2*>(
                                reinterpret_cast<__half*>(outF) + o) =
                                __floats2half2_rn(vx, vy);
                        else
                            *reinterpret_cast<float2*>(outF + o) = make_float2(vx, vy);
                    }
                    if (outHi) {
                        __half2 h = __floats2half2_rn(vx, vy);
                        float2 hf = __half22float2(h);
                        *reinterpret_cast<__half2*>(outHi + o) = h;
                        *reinterpret_cast<__half2*>(outLo + o) =
                            __floats2half2_rn(vx - hf.x, vy - hf.y);
                    }
                }
            }
        }
    } else {
        // stage z tile into smem (unscale by AINV), then batched ODE elementwise
        float* zsm = reinterpret_cast<float*>(smem);
#pragma unroll
        for (int ms = 0; ms < 4; ms++)
#pragma unroll
            for (int ns = 0; ns < 4; ns++) {
                int r0 = wm * 64 + ms * 16 + (lane >> 2);
                int c0 = wn * 32 + ns * 8 + (lane & 3) * 2;
                zsm[r0 * 132 + c0]     = acc[ms][ns][0] * AINV;
                zsm[r0 * 132 + c0 + 1] = acc[ms][ns][1] * AINV;
                zsm[(r0 + 8) * 132 + c0]     = acc[ms][ns][2] * AINV;
                zsm[(r0 + 8) * 132 + c0 + 1] = acc[ms][ns][3] * AINV;
            }
        __syncthreads();
        const int h = (int)(bz & 15);
        __half* Xout = outHi;
#pragma unroll 1
        for (int ib = 0; ib < 2; ib++) {
            float2 a2[8], b2[8], d1a[8], d1b[8];
            int r8[8], cp8[8];
            size_t base8[8];
#pragma unroll
            for (int j = 0; j < 8; j++) {
                int lin = (ib * 8 + j) * 256 + tid;
                int r = lin >> 5, cp = (lin & 31) * 2;
                r8[j] = r; cp8[j] = cp;
                size_t base = ((size_t)bz * SS + m0 + r) * 128 + cp;
                base8[j] = base;
                a2[j] = *reinterpret_cast<const float2*>(abf + base);
                b2[j] = *reinterpret_cast<const float2*>(abf + base + 64);
                if (EPI == 2) {
                    d1a[j] = *reinterpret_cast<const float2*>(d1f + base);
                    d1b[j] = *reinterpret_cast<const float2*>(d1f + base + 64);
                }
            }
#pragma unroll
            for (int j = 0; j < 8; j++) {
                int r = r8[j], cp = cp8[j];
                size_t base = base8[j];
                size_t row = (size_t)bz * SS + m0 + r;
                float2 om2 = *reinterpret_cast<const float2*>(omg + h * 64 + cp);
                float za0 = zsm[r * 132 + cp],     za1 = zsm[r * 132 + cp + 1];
                float zb0 = zsm[r * 132 + cp + 64], zb1 = zsm[r * 132 + cp + 65];
                float ra0 = za0 * CA_C + zb0 * SA_C, rb0 = zb0 * CA_C - za0 * SA_C;
                float ra1 = za1 * CA_C + zb1 * SA_C, rb1 = zb1 * CA_C - za1 * SA_C;
                if (EPI == 1) {
                    if (flag)
                        *reinterpret_cast<float2*>(attnv + row * 64 + cp) =
                            make_float2(za0, za1);
                    float r20 = a2[j].x * a2[j].x + b2[j].x * b2[j].x;
                    float r21 = a2[j].y * a2[j].y + b2[j].y * b2[j].y;
                    float da0 = (MU_C - r20) * a2[j].x - om2.x * b2[j].x + K_C * (ra0 - a2[j].x);
                    float db0 = (MU_C - r20) * b2[j].x + om2.x * a2[j].x + K_C * (rb0 - b2[j].x);
                    float da1 = (MU_C - r21) * a2[j].y - om2.y * b2[j].y + K_C * (ra1 - a2[j].y);
                    float db1 = (MU_C - r21) * b2[j].y + om2.y * a2[j].y + K_C * (rb1 - b2[j].y);
                    *reinterpret_cast<float2*>(d1f + base)      = make_float2(da0, da1);
                    *reinterpret_cast<float2*>(d1f + base + 64) = make_float2(db0, db1);
                    float ap0 = a2[j].x + DT_C * da0, ap1 = a2[j].y + DT_C * da1;
                    float bp0 = b2[j].x + DT_C * db0, bp1 = b2[j].y + DT_C * db1;
                    *reinterpret_cast<__half2*>(Xout + base) = __floats2half2_rn(ap0, ap1);
                    *reinterpret_cast<__half2*>(Xout + base + 64) = __floats2half2_rn(bp0, bp1);
                } else {
                    float ap0 = a2[j].x + DT_C * d1a[j].x, ap1 = a2[j].y + DT_C * d1a[j].y;
                    float bp0 = b2[j].x + DT_C * d1b[j].x, bp1 = b2[j].y + DT_C * d1b[j].y;
                    float r20 = ap0 * ap0 + bp0 * bp0;
                    float r21 = ap1 * ap1 + bp1 * bp1;
                    float da20 = (MU_C - r20) * ap0 - om2.x * bp0 + K_C * (ra0 - ap0);
                    float db20 = (MU_C - r20) * bp0 + om2.x * ap0 + K_C * (rb0 - bp0);
                    float da21 = (MU_C - r21) * ap1 - om2.y * bp1 + K_C * (ra1 - ap1);
                    float db21 = (MU_C - r21) * bp1 + om2.y * ap1 + K_C * (rb1 - bp1);
                    float an0 = a2[j].x + 0.5f * DT_C * (d1a[j].x + da20);
                    float an1 = a2[j].y + 0.5f * DT_C * (d1a[j].y + da21);
                    float bn0 = b2[j].x + 0.5f * DT_C * (d1b[j].x + db20);
                    float bn1 = b2[j].y + 0.5f * DT_C * (d1b[j].y + db21);
                    *reinterpret_cast<float2*>(abf + base)      = make_float2(an0, an1);
                    *reinterpret_cast<float2*>(abf + base + 64) = make_float2(bn0, bn1);
                    if (flag) {
                        float2 av = *reinterpret_cast<const float2*>(attnv + row * 64 + cp);
                        *reinterpret_cast<float2*>(mixed + row * 64 + cp) =
                            make_float2(MIX_C * av.x + (1.0f - MIX_C) * an0,
                                        MIX_C * av.y + (1.0f - MIX_C) * an1);
                    } else {
                        *reinterpret_cast<__half2*>(Xout + base) = __floats2half2_rn(an0, an1);
                        *reinterpret_cast<__half2*>(Xout + base + 64) = __floats2half2_rn(bn0, bn1);
                    }
                }
            }
        }
    }
}

// ---------------- fp32 -> fp16 (hi only) weight convert ----------------
__global__ void splitWh_kernel(const float* __restrict__ A, __half* __restrict__ h)
{
    size_t i = ((size_t)blockIdx.x * blockDim.x + threadIdx.x) * 4;
    float4 v = *reinterpret_cast<const float4*>(A + i);
    *reinterpret_cast<__half2*>(h + i)     = __floats2half2_rn(v.x, v.y);
    *reinterpret_cast<__half2*>(h + i + 2) = __floats2half2_rn(v.z, v.w);
}

// ---------------- LayerNorm (optional fp16 hi/lo outputs) ----------------
__global__ void ln_kernel(const float* __restrict__ x, const float* __restrict__ g,
                          const float* __restrict__ be, float* __restrict__ out,
                          __half* __restrict__ outHi, __half* __restrict__ outLo)
{
    __shared__ float sh[8];
    size_t row = blockIdx.x;
    int tid = threadIdx.x, lane = tid & 31, wid = tid >> 5;
    float4 v = reinterpret_cast<const float4*>(x + row * DD)[tid];

    float s = v.x + v.y + v.z + v.w;
#pragma unroll
    for (int o = 16; o; o >>= 1) s += __shfl_xor_sync(0xffffffffu, s, o);
    if (lane == 0) sh[wid] = s;
    __syncthreads();
    float tot = 0.f;
#pragma unroll
    for (int i = 0; i < 8; i++) tot += sh[i];
    float mean = tot * (1.0f / DD);

    float dx = v.x - mean, dy = v.y - mean, dz = v.z - mean, dw = v.w - mean;
    float s2 = dx*dx + dy*dy + dz*dz + dw*dw;
#pragma unroll
    for (int o = 16; o; o >>= 1) s2 += __shfl_xor_sync(0xffffffffu, s2, o);
    __syncthreads();
    if (lane == 0) sh[wid] = s2;
    __syncthreads();
    float tot2 = 0.f;
#pragma unroll
    for (int i = 0; i < 8; i++) tot2 += sh[i];
    float rstd = rsqrtf(tot2 * (1.0f / DD) + 1e-5f);

    float4 gv = reinterpret_cast<const float4*>(g)[tid];
    float4 bv = reinterpret_cast<const float4*>(be)[tid];
    float4 o4;
    o4.x = dx * rstd * gv.x + bv.x;
    o4.y = dy * rstd * gv.y + bv.y;
    o4.z = dz * rstd * gv.z + bv.z;
    o4.w = dw * rstd * gv.w + bv.w;
    reinterpret_cast<float4*>(out + row * DD)[tid] = o4;
    if (outHi) {
        size_t i = row * DD + tid * 4;
        __half2 h0 = __floats2half2_rn(o4.x, o4.y);
        __half2 h1 = __floats2half2_rn(o4.z, o4.w);
        float2 f0 = __half22float2(h0), f1 = __half22float2(h1);
        *reinterpret_cast<__half2*>(outHi + i)     = h0;
        *reinterpret_cast<__half2*>(outHi + i + 2) = h1;
        *reinterpret_cast<__half2*>(outLo + i)     = __floats2half2_rn(o4.x - f0.x, o4.y - f0.y);
        *reinterpret_cast<__half2*>(outLo + i + 2) = __floats2half2_rn(o4.z - f1.x, o4.w - f1.y);
    }
}

// ---------------- QKV projection (3-way parallel, 64 rows/block — R10 shape) ----------------
__global__ void qkv_kernel(const float* __restrict__ xn,
                           const float* __restrict__ Wq, const float* __restrict__ Wk,
                           const float* __restrict__ Wv,
                           __half* __restrict__ qhi, __half* __restrict__ qlo,
                           __half* __restrict__ khi,
                           float* __restrict__ ab, __half* __restrict__ abX)
{
    __shared__ float sx[64][65];
    __shared__ float sw[64][65];
    int bh = blockIdx.y, b = bh >> 4, h = bh & 15;
    int wsel = blockIdx.z;
    int s0 = blockIdx.x * 64;
    int tid = threadIdx.x;

    const float* W = (wsel == 0 ? Wq : (wsel == 1 ? Wk : Wv)) + h * 4096;
    for (int idx = tid; idx < 4096; idx += 256) {
        int r = idx >> 6, d = idx & 63;
        sx[r][d] = xn[((size_t)(b * SS + s0 + r)) * DD + h * 64 + d];
        sw[r][d] = W[idx];
    }
    __syncthreads();
    int e = tid & 63, rq = tid >> 6;
#pragma unroll
    for (int i = 0; i < 16; i++) {
        int r = rq * 16 + i;
        float acc = 0.f;
#pragma unroll
        for (int d = 0; d < 64; d++) acc = fmaf(sx[r][d], sw[d][e], acc);
        size_t srow = (size_t)bh * SS + s0 + r;
        if (wsel == 0) {
            __half hi = __float2half(acc);
            qhi[srow * 64 + e] = hi;
            qlo[srow * 64 + e] = __float2half(acc - __half2float(hi));
        } else if (wsel == 1) {
            khi[srow * 64 + e] = __float2half(acc);
        } else {
            ab[srow * 128 + e] = acc; ab[srow * 128 + 64 + e] = 0.f;
            abX[srow * 128 + e] = __float2half(acc);
            abX[srow * 128 + 64 + e] = __float2half(0.f);
        }
    }
}

// ---------------- fused softmax (fp16 in) + scaled fp16 emit ----------------
__global__ void softmax_split_kernel(const __half* __restrict__ S,
                                     __half* __restrict__ Ahi)
{
    __shared__ float sh[8];
    size_t row = blockIdx.x;
    const __half* p = S + row * (size_t)SS;
    int tid = threadIdx.x, lane = tid & 31, wid = tid >> 5;

    float4 raw = reinterpret_cast<const float4*>(p)[tid];   // 8 halves
    const __half2* hp = reinterpret_cast<const __half2*>(&raw);
    float v[8];
#pragma unroll
    for (int i = 0; i < 4; i++) {
        float2 f = __half22float2(hp[i]);
        v[i * 2] = f.x * 0.125f; v[i * 2 + 1] = f.y * 0.125f;
    }

    float mx = v[0];
#pragma unroll
    for (int i = 1; i < 8; i++) mx = fmaxf(mx, v[i]);
#pragma unroll
    for (int o = 16; o; o >>= 1) mx = fmaxf(mx, __shfl_xor_sync(0xffffffffu, mx, o));
    if (lane == 0) sh[wid] = mx;
    __syncthreads();
    float m = sh[0];
#pragma unroll
    for (int i = 1; i < 8; i++) m = fmaxf(m, sh[i]);

    float s = 0.f;
#pragma unroll
    for (int i = 0; i < 8; i++) { v[i] = expf(v[i] - m); s += v[i]; }
#pragma unroll
    for (int o = 16; o; o >>= 1) s += __shfl_xor_sync(0xffffffffu, s, o);
    __syncthreads();
    if (lane == 0) sh[wid] = s;
    __syncthreads();
    float tot = 0.f;
#pragma unroll
    for (int i = 0; i < 8; i++) tot += sh[i];
    float inv = ASCALE / tot;

    size_t ob = row * (size_t)SS + tid * 8;
#pragma unroll
    for (int i = 0; i < 4; i++)
        *reinterpret_cast<__half2*>(Ahi + ob + i * 2) =
            __floats2half2_rn(v[i * 2] * inv, v[i * 2 + 1] * inv);
}

// ---------------- head projection + residual (64 rows/block — R10 shape) ----------------
__global__ void headout_kernel(const float* __restrict__ mix, const float* __restrict__ Wo,
                               const float* __restrict__ x, float* __restrict__ x1)
{
    __shared__ float sx[64][65];
    __shared__ float sw[64][65];
    int bh = blockIdx.y, b = bh >> 4, h = bh & 15;
    int s0 = blockIdx.x * 64;
    int tid = threadIdx.x;

    for (int idx = tid; idx < 4096; idx += 256) {
        int r = idx >> 6, d = idx & 63;
        sx[r][d] = mix[((size_t)bh * SS + s0 + r) * 64 + d];
        sw[r][d] = Wo[h * 4096 + idx];
    }
    __syncthreads();
    int e = tid & 63, rq = tid >> 6;
#pragma unroll
    for (int i = 0; i < 16; i++) {
        int r = rq * 16 + i;
        float acc = 0.f;
#pragma unroll
        for (int d = 0; d < 64; d++) acc = fmaf(sx[r][d], sw[d][e], acc);
        size_t o = ((size_t)(b * SS + s0 + r)) * DD + h * 64 + e;
        x1[o] = x[o] + acc;
    }
}

// ---------------- host side ----------------
extern "C" void kernel_launch(void* const* d_in, const int* in_sizes, int n_in,
                              void* d_out, int out_size)
{
    const float* x   = (const float*)d_in[0];
    const float* Wq  = (const float*)d_in[1];
    const float* Wk  = (const float*)d_in[2];
    const float* Wv  = (const float*)d_in[3];
    const float* Wo  = (const float*)d_in[4];
    const float* om  = (const float*)d_in[5];
    const float* g1  = (const float*)d_in[6];
    const float* be1 = (const float*)d_in[7];
    const float* g2  = (const float*)d_in[8];
    const float* be2 = (const float*)d_in[9];
    const float* W1  = (const float*)d_in[10];
    const float* bf1 = (const float*)d_in[11];
    const float* W2  = (const float*)d_in[12];
    const float* bf2 = (const float*)d_in[13];
    float* out = (float*)d_out;
    (void)in_sizes; (void)n_in; (void)out_size;

    float *xn, *ab, *d1, *attnv, *mixb, *x1;
    __half *S_, *Ahi, *xnhi, *xnlo, *qhi, *qlo, *khi;
    __half *abX, *pX, *ffhi, *fflo, *W1h, *W2h;
    cudaGetSymbolAddress((void**)&S_,    g_S);
    cudaGetSymbolAddress((void**)&Ahi,   g_Ahi);
    cudaGetSymbolAddress((void**)&xn,    g_xn);
    cudaGetSymbolAddress((void**)&xnhi,  g_xnhi);
    cudaGetSymbolAddress((void**)&xnlo,  g_xnlo);
    cudaGetSymbolAddress((void**)&qhi,   g_qhi);
    cudaGetSymbolAddress((void**)&qlo,   g_qlo);
    cudaGetSymbolAddress((void**)&khi,   g_khi);
    cudaGetSymbolAddress((void**)&ab,    g_ab);
    cudaGetSymbolAddress((void**)&d1,    g_d1);
    cudaGetSymbolAddress((void**)&abX,   g_abX);
    cudaGetSymbolAddress((void**)&pX,    g_pX);
    cudaGetSymbolAddress((void**)&attnv, g_attnv);
    cudaGetSymbolAddress((void**)&mixb,  g_mix);
    cudaGetSymbolAddress((void**)&x1,    g_x1);
    cudaGetSymbolAddress((void**)&ffhi,  g_ffhi);
    cudaGetSymbolAddress((void**)&fflo,  g_fflo);
    cudaGetSymbolAddress((void**)&W1h,   g_W1h);
    cudaGetSymbolAddress((void**)&W2h,   g_W2h);

    cudaFuncSetAttribute(hgemm_kernel<true, 0, 2>,
                         cudaFuncAttributeMaxDynamicSharedMemorySize, HSMEM2);
    cudaFuncSetAttribute(hgemm_kernel<false, 0, 2>,
                         cudaFuncAttributeMaxDynamicSharedMemorySize, HSMEM2);
    cudaFuncSetAttribute(hgemm_kernel<true, 1, 1>,
                         cudaFuncAttributeMaxDynamicSharedMemorySize, HSMEM1);
    cudaFuncSetAttribute(hgemm_kernel<true, 2, 1>,
                         cudaFuncAttributeMaxDynamicSharedMemorySize, HSMEM1);

    const long long sQK = (long long)SS * 64;
    const long long sAA = (long long)SS * SS;
    const long long sAB = (long long)SS * 128;

    splitWh_kernel<<<(unsigned)((size_t)DD * DFFC / 1024), 256>>>(W1, W1h);
    splitWh_kernel<<<(unsigned)((size_t)DFFC * DD / 1024), 256>>>(W2, W2h);

    // 1. LN1
    ln_kernel<<<NTOK, 256>>>(x, g1, be1, xn, nullptr, nullptr);
    // 2. QKV (3-way parallel, 64 rows/block)
    qkv_kernel<<<dim3(SS / 64, BH, 3), 256>>>(xn, Wq, Wk, Wv, qhi, qlo, khi, ab, abX);
    // 3. scores (fp16 2-product) -> fp16 S
    hgemm_kernel<false, 0, 2><<<dim3(16, 16, BH), 256, HSMEM2>>>(
        qhi, qlo, khi, 64, 64, 64, SS, sQK, sQK, sAA,
        reinterpret_cast<float*>(S_), nullptr, nullptr, nullptr, nullptr, 0,
        nullptr, nullptr, nullptr, nullptr, nullptr, 1);
    // 4. softmax (fp16 in) + scaled fp16 A
    softmax_split_kernel<<<BH * SS, 256>>>(S_, Ahi);
    // 5. Heun loop: fp16 1-product GEMM (3-stage, 2 CTAs/SM) + fused ODE epilogues
    for (int st = 0; st < 5; st++) {
        hgemm_kernel<true, 1, 1><<<dim3(1, 16, BH), 256, HSMEM1>>>(
            Ahi, nullptr, abX, SS, SS, 128, 128, sAA, sAB, sAB,
            nullptr, pX, nullptr, nullptr, nullptr, 0,
            om, ab, d1, attnv, nullptr, st == 0 ? 1 : 0);
        hgemm_kernel<true, 2, 1><<<dim3(1, 16, BH), 256, HSMEM1>>>(
            Ahi, nullptr, pX, SS, SS, 128, 128, sAA, sAB, sAB,
            nullptr, abX, nullptr, nullptr, nullptr, 0,
            om, ab, d1, attnv, mixb, st == 4 ? 1 : 0);
    }
    // 6. head projection + residual (64 rows/block)
    headout_kernel<<<dim3(SS / 64, BH), 256>>>(mixb, Wo, x, x1);
    // 7. LN2 -> fp32 + fp16 hi/lo
    ln_kernel<<<NTOK, 256>>>(x1, g2, be2, xn, xnhi, xnlo);
    // 8. FFN1 (fp16 2-product): gelu(xn @ W1 + bf1) -> ff fp16 hi/lo
    hgemm_kernel<true, 0, 2><<<dim3(16, 32, 1), 256, HSMEM2>>>(
        xnhi, xnlo, W1h, DD, DD, DFFC, DFFC, 0, 0, 0,
        nullptr, ffhi, fflo, bf1, nullptr, 1,
        nullptr, nullptr, nullptr, nullptr, nullptr, 0);
    // 9. FFN2 (fp16 2-product): out = x1 + ff @ W2 + bf2 (fp32 out)
    hgemm_kernel<true, 0, 2><<<dim3(8, 32, 1), 256, HSMEM2>>>(
        ffhi, fflo, W2h, DFFC, DFFC, DD, DD, 0, 0, 0,
        out, nullptr, nullptr, bf2, x1, 0,
        nullptr, nullptr, nullptr, nullptr, nullptr, 0);
}

// round 13
// speedup vs baseline: 2.3576x; 1.0312x over previous
#include <cuda_runtime.h>
#include <cuda_bf16.h>
#include <cuda_fp16.h>
#include <math.h>
#include <stddef.h>
#include <stdint.h>

// ---------------- problem constants ----------------
#define BB   2
#define SS   2048
#define DD   1024
#define HH   16
#define HDIM 64
#define DFFC 2048
#define BH   (BB*HH)
#define NTOK (BB*SS)

#define MU_C   1.0f
#define K_C    3.0f
#define DT_C   0.02f
#define MIX_C  0.3f
#define CA_C   0.9950041652780258f
#define SA_C   0.09983341664682815f
#define ASCALE 2048.0f
#define AINV   (1.0f / 2048.0f)

// ---------------- scratch ----------------
__device__ __half g_S [(size_t)BH * SS * SS];           // fp16 raw scores
__device__ __half g_Ahi[(size_t)BH * SS * SS];          // fp16 scaled A
__device__ float g_xn  [(size_t)NTOK * DD];
__device__ __half g_xnhi[(size_t)NTOK * DD];
__device__ __half g_xnlo[(size_t)NTOK * DD];
__device__ __half g_qhi[(size_t)BH * SS * 64];
__device__ __half g_qlo[(size_t)BH * SS * 64];
__device__ __half g_khi[(size_t)BH * SS * 64];
__device__ float g_ab  [(size_t)BH * SS * 128];
__device__ float g_d1  [(size_t)BH * SS * 128];
__device__ __half g_abX[(size_t)BH * SS * 128];         // fp16 X state
__device__ __half g_pX [(size_t)BH * SS * 128];         // fp16 X predictor
__device__ float g_attnv[(size_t)BH * SS * 64];
__device__ float g_mix  [(size_t)BH * SS * 64];
__device__ float g_x1   [(size_t)NTOK * DD];
__device__ __half g_ffhi[(size_t)NTOK * DFFC];
__device__ __half g_fflo[(size_t)NTOK * DFFC];
__device__ __half g_W1h[(size_t)DD * DFFC];
__device__ __half g_W2h[(size_t)DFFC * DD];

// ---------------- low-level helpers ----------------
__device__ __forceinline__ uint32_t smem_u32(const void* p) {
    uint32_t a;
    asm("{ .reg .u64 t; cvta.to.shared.u64 t, %1; cvt.u32.u64 %0, t; }" : "=r"(a) : "l"(p));
    return a;
}
__device__ __forceinline__ void cp16(uint32_t s, const void* g) {
    asm volatile("cp.async.cg.shared.global [%0], [%1], 16;" :: "r"(s), "l"(g));
}
__device__ __forceinline__ void cp_commit() {
    asm volatile("cp.async.commit_group;" ::: "memory");
}
template <int N>
__device__ __forceinline__ void cp_wait() {
    asm volatile("cp.async.wait_group %0;" :: "n"(N) : "memory");
}
__device__ __forceinline__ void ldm_x4(uint32_t* r, uint32_t addr) {
    asm volatile("ldmatrix.sync.aligned.m8n8.x4.shared.b16 {%0,%1,%2,%3}, [%4];"
        : "=r"(r[0]), "=r"(r[1]), "=r"(r[2]), "=r"(r[3]) : "r"(addr));
}
__device__ __forceinline__ void ldm_x4t(uint32_t* r, uint32_t addr) {
    asm volatile("ldmatrix.sync.aligned.m8n8.x4.trans.shared.b16 {%0,%1,%2,%3}, [%4];"
        : "=r"(r[0]), "=r"(r[1]), "=r"(r[2]), "=r"(r[3]) : "r"(addr));
}
__device__ __forceinline__ void mma_f16(float* c, const uint32_t* a, const uint32_t* b) {
    asm volatile("mma.sync.aligned.m16n8k16.row.col.f32.f16.f16.f32 "
        "{%0,%1,%2,%3}, {%4,%5,%6,%7}, {%8,%9}, {%0,%1,%2,%3};"
        : "+f"(c[0]), "+f"(c[1]), "+f"(c[2]), "+f"(c[3])
        : "r"(a[0]), "r"(a[1]), "r"(a[2]), "r"(a[3]), "r"(b[0]), "r"(b[1]));
}
__device__ __forceinline__ float gelu_tanh(float x) {
    float x3 = x * x * x;
    float t  = tanhf(0.7978845608028654f * (x + 0.044715f * x3));
    return 0.5f * x * (1.0f + t);
}

// ---------------- unified fp16 HMMA GEMM, fusable ODE epilogue ----------------
// EPI: 0 = plain C output; 1 = fused ode_ew1; 2 = fused ode_ew2.
// PROD: 2 = fp16 2-product ((Ahi+Alo) @ Bhi).  1 = fp16 1-product (Ahi @ Bhi).
// EPI0 outputs: outF!=0 && flag==0 -> fp32; flag==1 -> fp16 into outF.
//               outHi/outLo !=0 -> fp16 hi/lo pair.
#define AST 72
#define BSTN 72
#define BSTT 136
#define STG2 55296
#define STG1 36864
#define HSMEM2 (3 * STG2)     // 165888, 1 CTA/SM
#define HSMEM1 (2 * STG1)     // 73728,  2 CTA/SM (R10-proven config)

template<bool TRANSB, int EPI, int PROD>
__global__ void __launch_bounds__(256)
hgemm_kernel(const __half* __restrict__ Ahi, const __half* __restrict__ Alo,
             const __half* __restrict__ Bhi,
             int K, int lda, int ldb, int ldc,
             long long sA, long long sB, long long sC,
             float* __restrict__ outF,
             __half* __restrict__ outHi, __half* __restrict__ outLo,
             const float* __restrict__ bias, const float* __restrict__ addsrc, int do_gelu,
             const float* __restrict__ omg, float* __restrict__ abf,
             float* __restrict__ d1f, float* __restrict__ attnv,
             float* __restrict__ mixed, int flag)
{
    constexpr int STGB  = (PROD == 2) ? STG2 : STG1;
    constexpr int OFFAL = 18432;                         // A-lo (PROD == 2)
    constexpr int OFFBH = (PROD == 1) ? 18432 : 36864;   // B-hi
    extern __shared__ char smem[];
    const uint32_t sb = smem_u32(smem);
    const int tid = threadIdx.x;
    const int lane = tid & 31, w = tid >> 5;
    const int wm = w >> 2, wn = w & 3;
    const int n0 = blockIdx.x * 128;
    const int m0 = blockIdx.y * 128;
    const long long bz = blockIdx.z;

    Ahi += bz * sA;
    if (PROD == 2) Alo += bz * sA;
    Bhi += bz * sB;

    float acc[4][4][4];
#pragma unroll
    for (int i = 0; i < 4; i++)
#pragma unroll
        for (int j = 0; j < 4; j++)
#pragma unroll
            for (int r = 0; r < 4; r++) acc[i][j][r] = 0.f;

    auto issue = [&](int chunk, int buf) {
        const int k0 = chunk << 6;
        const uint32_t st = sb + buf * STGB;
        {
            const int row = tid >> 3, col = (tid & 7) * 8;
            const __half* gH = Ahi + (size_t)(m0 + row) * lda + k0 + col;
            uint32_t s = st + (row * AST + col) * 2;
#pragma unroll
            for (int j = 0; j < 4; j++)
                cp16(s + j * 32 * (AST * 2), gH + (size_t)j * 32 * lda);
            if (PROD == 2) {
                const __half* gL = Alo + (size_t)(m0 + row) * lda + k0 + col;
#pragma unroll
                for (int j = 0; j < 4; j++)
                    cp16(s + OFFAL + j * 32 * (AST * 2), gL + (size_t)j * 32 * lda);
            }
        }
        if (TRANSB) {
            const int rk = tid >> 2, col = (tid & 3) * 8;
            const __half* gH = Bhi + (size_t)(k0 + rk) * ldb + n0 + col;
            uint32_t s = st + OFFBH + (rk * BSTT + col) * 2;
#pragma unroll
            for (int j = 0; j < 4; j++)
                cp16(s + j * 64, gH + j * 32);
        } else {
            const int rn = tid >> 3, col = (tid & 7) * 8;
            const __half* gH = Bhi + (size_t)(n0 + rn) * ldb + k0 + col;
            uint32_t s = st + OFFBH + (rn * BSTN + col) * 2;
#pragma unroll
            for (int j = 0; j < 4; j++)
                cp16(s + j * 32 * (BSTN * 2), gH + (size_t)j * 32 * ldb);
        }
        cp_commit();
    };

    auto compute = [&](int buf) {
        const uint32_t st = sb + buf * STGB;
#pragma unroll
        for (int k16 = 0; k16 < 4; k16++) {
            uint32_t afrH[4][4], afrL[4][4], bfrH[4][2];
#pragma unroll
            for (int ms = 0; ms < 4; ms++) {
                int row = wm * 64 + ms * 16 + (lane & 15);
                int col = k16 * 16 + (lane >> 4) * 8;
                ldm_x4(afrH[ms], st + (row * AST + col) * 2);
                if (PROD == 2)
                    ldm_x4(afrL[ms], st + OFFAL + (row * AST + col) * 2);
            }
            if (TRANSB) {
                const int mat = lane >> 3, rr = lane & 7;
#pragma unroll
                for (int p = 0; p < 2; p++) {
                    int rk = k16 * 16 + (mat & 1) * 8 + rr;
                    int cn = wn * 32 + p * 16 + (mat >> 1) * 8;
                    ldm_x4t(&bfrH[p * 2][0], st + OFFBH + (rk * BSTT + cn) * 2);
                }
            } else {
                const int mat = lane >> 3, rr = lane & 7;
#pragma unroll
                for (int p = 0; p < 2; p++) {
                    int rn = wn * 32 + p * 16 + (mat >> 1) * 8 + rr;
                    int ck = k16 * 16 + (mat & 1) * 8;
                    ldm_x4(&bfrH[p * 2][0], st + OFFBH + (rn * BSTN + ck) * 2);
                }
            }
#pragma unroll
            for (int ms = 0; ms < 4; ms++)
#pragma unroll
                for (int ns = 0; ns < 4; ns++) {
                    mma_f16(acc[ms][ns], afrH[ms], bfrH[ns]);
                    if (PROD == 2)
                        mma_f16(acc[ms][ns], afrL[ms], bfrH[ns]);
                }
        }
    };

    const int nchunk = K >> 6;
    if (PROD == 2) {
        issue(0, 0);
        if (nchunk > 1) issue(1, 1);
#pragma unroll 1
        for (int i = 0; i < nchunk; i++) {
            if (i + 2 < nchunk)      { issue(i + 2, (i + 2) % 3); cp_wait<2>(); }
            else if (i + 1 < nchunk) { cp_wait<1>(); }
            else                     { cp_wait<0>(); }
            __syncthreads();
            compute(i % 3);
            __syncthreads();
        }
    } else {
        issue(0, 0);
#pragma unroll 1
        for (int i = 0; i < nchunk; i++) {
            if (i + 1 < nchunk) { issue(i + 1, (i + 1) & 1); cp_wait<1>(); }
            else                { cp_wait<0>(); }
            __syncthreads();
            compute(i & 1);
            __syncthreads();
        }
    }

    if (EPI == 0) {
        const long long cb = bz * sC;
#pragma unroll
        for (int ms = 0; ms < 4; ms++) {
#pragma unroll
            for (int ns = 0; ns < 4; ns++) {
                int r0 = wm * 64 + ms * 16 + (lane >> 2);
                int c0 = n0 + wn * 32 + ns * 8 + (lane & 3) * 2;
#pragma unroll
                for (int half = 0; half < 2; half++) {
                    long long r = m0 + r0 + half * 8;
                    float vx = acc[ms][ns][half * 2 + 0];
                    float vy = acc[ms][ns][half * 2 + 1];
                    if (bias)   { vx += bias[c0]; vy += bias[c0 + 1]; }
                    if (addsrc) {
                        float2 s = *reinterpret_cast<const float2*>(addsrc + r * ldc + c0);
                        vx += s.x; vy += s.y;
                    }
                    if (do_gelu) { vx = gelu_tanh(vx); vy = gelu_tanh(vy); }
                    long long o = cb + r * ldc + c0;
                    if (outF) {
                        if (flag)   // fp16 output
                            *reinterpret_cast<__half2*>(
                                reinterpret_cast<__half*>(outF) + o) =
                                __floats2half2_rn(vx, vy);
                        else
                            *reinterpret_cast<float2*>(outF + o) = make_float2(vx, vy);
                    }
                    if (outHi) {
                        __half2 h = __floats2half2_rn(vx, vy);
                        float2 hf = __half22float2(h);
                        *reinterpret_cast<__half2*>(outHi + o) = h;
                        *reinterpret_cast<__half2*>(outLo + o) =
                            __floats2half2_rn(vx - hf.x, vy - hf.y);
                    }
                }
            }
        }
    } else {
        // stage z tile into smem (unscale by AINV), then batched ODE elementwise
        float* zsm = reinterpret_cast<float*>(smem);
#pragma unroll
        for (int ms = 0; ms < 4; ms++)
#pragma unroll
            for (int ns = 0; ns < 4; ns++) {
                int r0 = wm * 64 + ms * 16 + (lane >> 2);
                int c0 = wn * 32 + ns * 8 + (lane & 3) * 2;
                zsm[r0 * 132 + c0]     = acc[ms][ns][0] * AINV;
                zsm[r0 * 132 + c0 + 1] = acc[ms][ns][1] * AINV;
                zsm[(r0 + 8) * 132 + c0]     = acc[ms][ns][2] * AINV;
                zsm[(r0 + 8) * 132 + c0 + 1] = acc[ms][ns][3] * AINV;
            }
        __syncthreads();
        const int h = (int)(bz & 15);
        __half* Xout = outHi;
#pragma unroll 1
        for (int ib = 0; ib < 2; ib++) {
            float2 a2[8], b2[8], d1a[8], d1b[8];
            int r8[8], cp8[8];
            size_t base8[8];
#pragma unroll
            for (int j = 0; j < 8; j++) {
                int lin = (ib * 8 + j) * 256 + tid;
                int r = lin >> 5, cp = (lin & 31) * 2;
                r8[j] = r; cp8[j] = cp;
                size_t base = ((size_t)bz * SS + m0 + r) * 128 + cp;
                base8[j] = base;
                a2[j] = *reinterpret_cast<const float2*>(abf + base);
                b2[j] = *reinterpret_cast<const float2*>(abf + base + 64);
                if (EPI == 2) {
                    d1a[j] = *reinterpret_cast<const float2*>(d1f + base);
                    d1b[j] = *reinterpret_cast<const float2*>(d1f + base + 64);
                }
            }
#pragma unroll
            for (int j = 0; j < 8; j++) {
                int r = r8[j], cp = cp8[j];
                size_t base = base8[j];
                size_t row = (size_t)bz * SS + m0 + r;
                float2 om2 = *reinterpret_cast<const float2*>(omg + h * 64 + cp);
                float za0 = zsm[r * 132 + cp],     za1 = zsm[r * 132 + cp + 1];
                float zb0 = zsm[r * 132 + cp + 64], zb1 = zsm[r * 132 + cp + 65];
                float ra0 = za0 * CA_C + zb0 * SA_C, rb0 = zb0 * CA_C - za0 * SA_C;
                float ra1 = za1 * CA_C + zb1 * SA_C, rb1 = zb1 * CA_C - za1 * SA_C;
                if (EPI == 1) {
                    if (flag)
                        *reinterpret_cast<float2*>(attnv + row * 64 + cp) =
                            make_float2(za0, za1);
                    float r20 = a2[j].x * a2[j].x + b2[j].x * b2[j].x;
                    float r21 = a2[j].y * a2[j].y + b2[j].y * b2[j].y;
                    float da0 = (MU_C - r20) * a2[j].x - om2.x * b2[j].x + K_C * (ra0 - a2[j].x);
                    float db0 = (MU_C - r20) * b2[j].x + om2.x * a2[j].x + K_C * (rb0 - b2[j].x);
                    float da1 = (MU_C - r21) * a2[j].y - om2.y * b2[j].y + K_C * (ra1 - a2[j].y);
                    float db1 = (MU_C - r21) * b2[j].y + om2.y * a2[j].y + K_C * (rb1 - b2[j].y);
                    *reinterpret_cast<float2*>(d1f + base)      = make_float2(da0, da1);
                    *reinterpret_cast<float2*>(d1f + base + 64) = make_float2(db0, db1);
                    float ap0 = a2[j].x + DT_C * da0, ap1 = a2[j].y + DT_C * da1;
                    float bp0 = b2[j].x + DT_C * db0, bp1 = b2[j].y + DT_C * db1;
                    *reinterpret_cast<__half2*>(Xout + base) = __floats2half2_rn(ap0, ap1);
                    *reinterpret_cast<__half2*>(Xout + base + 64) = __floats2half2_rn(bp0, bp1);
                } else {
                    float ap0 = a2[j].x + DT_C * d1a[j].x, ap1 = a2[j].y + DT_C * d1a[j].y;
                    float bp0 = b2[j].x + DT_C * d1b[j].x, bp1 = b2[j].y + DT_C * d1b[j].y;
                    float r20 = ap0 * ap0 + bp0 * bp0;
                    float r21 = ap1 * ap1 + bp1 * bp1;
                    float da20 = (MU_C - r20) * ap0 - om2.x * bp0 + K_C * (ra0 - ap0);
                    float db20 = (MU_C - r20) * bp0 + om2.x * ap0 + K_C * (rb0 - bp0);
                    float da21 = (MU_C - r21) * ap1 - om2.y * bp1 + K_C * (ra1 - ap1);
                    float db21 = (MU_C - r21) * bp1 + om2.y * ap1 + K_C * (rb1 - bp1);
                    float an0 = a2[j].x + 0.5f * DT_C * (d1a[j].x + da20);
                    float an1 = a2[j].y + 0.5f * DT_C * (d1a[j].y + da21);
                    float bn0 = b2[j].x + 0.5f * DT_C * (d1b[j].x + db20);
                    float bn1 = b2[j].y + 0.5f * DT_C * (d1b[j].y + db21);
                    *reinterpret_cast<float2*>(abf + base)      = make_float2(an0, an1);
                    *reinterpret_cast<float2*>(abf + base + 64) = make_float2(bn0, bn1);
                    if (flag) {
                        float2 av = *reinterpret_cast<const float2*>(attnv + row * 64 + cp);
                        *reinterpret_cast<float2*>(mixed + row * 64 + cp) =
                            make_float2(MIX_C * av.x + (1.0f - MIX_C) * an0,
                                        MIX_C * av.y + (1.0f - MIX_C) * an1);
                    } else {
                        *reinterpret_cast<__half2*>(Xout + base) = __floats2half2_rn(an0, an1);
                        *reinterpret_cast<__half2*>(Xout + base + 64) = __floats2half2_rn(bn0, bn1);
                    }
                }
            }
        }
    }
}

// ---------------- fp32 -> fp16 (hi only) weight convert ----------------
__global__ void splitWh_kernel(const float* __restrict__ A, __half* __restrict__ h)
{
    size_t i = ((size_t)blockIdx.x * blockDim.x + threadIdx.x) * 4;
    float4 v = *reinterpret_cast<const float4*>(A + i);
    *reinterpret_cast<__half2*>(h + i)     = __floats2half2_rn(v.x, v.y);
    *reinterpret_cast<__half2*>(h + i + 2) = __floats2half2_rn(v.z, v.w);
}

// ---------------- LayerNorm (optional fp16 hi/lo outputs) ----------------
__global__ void ln_kernel(const float* __restrict__ x, const float* __restrict__ g,
                          const float* __restrict__ be, float* __restrict__ out,
                          __half* __restrict__ outHi, __half* __restrict__ outLo)
{
    __shared__ float sh[8];
    size_t row = blockIdx.x;
    int tid = threadIdx.x, lane = tid & 31, wid = tid >> 5;
    float4 v = reinterpret_cast<const float4*>(x + row * DD)[tid];

    float s = v.x + v.y + v.z + v.w;
#pragma unroll
    for (int o = 16; o; o >>= 1) s += __shfl_xor_sync(0xffffffffu, s, o);
    if (lane == 0) sh[wid] = s;
    __syncthreads();
    float tot = 0.f;
#pragma unroll
    for (int i = 0; i < 8; i++) tot += sh[i];
    float mean = tot * (1.0f / DD);

    float dx = v.x - mean, dy = v.y - mean, dz = v.z - mean, dw = v.w - mean;
    float s2 = dx*dx + dy*dy + dz*dz + dw*dw;
#pragma unroll
    for (int o = 16; o; o >>= 1) s2 += __shfl_xor_sync(0xffffffffu, s2, o);
    __syncthreads();
    if (lane == 0) sh[wid] = s2;
    __syncthreads();
    float tot2 = 0.f;
#pragma unroll
    for (int i = 0; i < 8; i++) tot2 += sh[i];
    float rstd = rsqrtf(tot2 * (1.0f / DD) + 1e-5f);

    float4 gv = reinterpret_cast<const float4*>(g)[tid];
    float4 bv = reinterpret_cast<const float4*>(be)[tid];
    float4 o4;
    o4.x = dx * rstd * gv.x + bv.x;
    o4.y = dy * rstd * gv.y + bv.y;
    o4.z = dz * rstd * gv.z + bv.z;
    o4.w = dw * rstd * gv.w + bv.w;
    reinterpret_cast<float4*>(out + row * DD)[tid] = o4;
    if (outHi) {
        size_t i = row * DD + tid * 4;
        __half2 h0 = __floats2half2_rn(o4.x, o4.y);
        __half2 h1 = __floats2half2_rn(o4.z, o4.w);
        float2 f0 = __half22float2(h0), f1 = __half22float2(h1);
        *reinterpret_cast<__half2*>(outHi + i)     = h0;
        *reinterpret_cast<__half2*>(outHi + i + 2) = h1;
        *reinterpret_cast<__half2*>(outLo + i)     = __floats2half2_rn(o4.x - f0.x, o4.y - f0.y);
        *reinterpret_cast<__half2*>(outLo + i + 2) = __floats2half2_rn(o4.z - f1.x, o4.w - f1.y);
    }
}

// ---------------- QKV projection (3-way parallel, 64 rows/block) ----------------
__global__ void qkv_kernel(const float* __restrict__ xn,
                           const float* __restrict__ Wq, const float* __restrict__ Wk,
                           const float* __restrict__ Wv,
                           __half* __restrict__ qhi, __half* __restrict__ qlo,
                           __half* __restrict__ khi,
                           float* __restrict__ ab, __half* __restrict__ abX)
{
    __shared__ float sx[64][65];
    __shared__ float sw[64][65];
    int bh = blockIdx.y, b = bh >> 4, h = bh & 15;
    int wsel = blockIdx.z;
    int s0 = blockIdx.x * 64;
    int tid = threadIdx.x;

    const float* W = (wsel == 0 ? Wq : (wsel == 1 ? Wk : Wv)) + h * 4096;
    for (int idx = tid; idx < 4096; idx += 256) {
        int r = idx >> 6, d = idx & 63;
        sx[r][d] = xn[((size_t)(b * SS + s0 + r)) * DD + h * 64 + d];
        sw[r][d] = W[idx];
    }
    __syncthreads();
    int e = tid & 63, rq = tid >> 6;
#pragma unroll
    for (int i = 0; i < 16; i++) {
        int r = rq * 16 + i;
        float acc = 0.f;
#pragma unroll
        for (int d = 0; d < 64; d++) acc = fmaf(sx[r][d], sw[d][e], acc);
        size_t srow = (size_t)bh * SS + s0 + r;
        if (wsel == 0) {
            __half hi = __float2half(acc);
            qhi[srow * 64 + e] = hi;
            qlo[srow * 64 + e] = __float2half(acc - __half2float(hi));
        } else if (wsel == 1) {
            khi[srow * 64 + e] = __float2half(acc);
        } else {
            ab[srow * 128 + e] = acc; ab[srow * 128 + 64 + e] = 0.f;
            abX[srow * 128 + e] = __float2half(acc);
            abX[srow * 128 + 64 + e] = __float2half(0.f);
        }
    }
}

// ---------------- fused softmax (fp16 in) + scaled fp16 emit ----------------
__global__ void softmax_split_kernel(const __half* __restrict__ S,
                                     __half* __restrict__ Ahi)
{
    __shared__ float sh[8];
    size_t row = blockIdx.x;
    const __half* p = S + row * (size_t)SS;
    int tid = threadIdx.x, lane = tid & 31, wid = tid >> 5;

    float4 raw = reinterpret_cast<const float4*>(p)[tid];   // 8 halves
    const __half2* hp = reinterpret_cast<const __half2*>(&raw);
    float v[8];
#pragma unroll
    for (int i = 0; i < 4; i++) {
        float2 f = __half22float2(hp[i]);
        v[i * 2] = f.x * 0.125f; v[i * 2 + 1] = f.y * 0.125f;
    }

    float mx = v[0];
#pragma unroll
    for (int i = 1; i < 8; i++) mx = fmaxf(mx, v[i]);
#pragma unroll
    for (int o = 16; o; o >>= 1) mx = fmaxf(mx, __shfl_xor_sync(0xffffffffu, mx, o));
    if (lane == 0) sh[wid] = mx;
    __syncthreads();
    float m = sh[0];
#pragma unroll
    for (int i = 1; i < 8; i++) m = fmaxf(m, sh[i]);

    float s = 0.f;
#pragma unroll
    for (int i = 0; i < 8; i++) { v[i] = expf(v[i] - m); s += v[i]; }
#pragma unroll
    for (int o = 16; o; o >>= 1) s += __shfl_xor_sync(0xffffffffu, s, o);
    __syncthreads();
    if (lane == 0) sh[wid] = s;
    __syncthreads();
    float tot = 0.f;
#pragma unroll
    for (int i = 0; i < 8; i++) tot += sh[i];
    float inv = ASCALE / tot;

    size_t ob = row * (size_t)SS + tid * 8;
#pragma unroll
    for (int i = 0; i < 4; i++)
        *reinterpret_cast<__half2*>(Ahi + ob + i * 2) =
            __floats2half2_rn(v[i * 2] * inv, v[i * 2 + 1] * inv);
}

// ---------------- head projection + residual (64 rows/block) ----------------
__global__ void headout_kernel(const float* __restrict__ mix, const float* __restrict__ Wo,
                               const float* __restrict__ x, float* __restrict__ x1)
{
    __shared__ float sx[64][65];
    __shared__ float sw[64][65];
    int bh = blockIdx.y, b = bh >> 4, h = bh & 15;
    int s0 = blockIdx.x * 64;
    int tid = threadIdx.x;

    for (int idx = tid; idx < 4096; idx += 256) {
        int r = idx >> 6, d = idx & 63;
        sx[r][d] = mix[((size_t)bh * SS + s0 + r) * 64 + d];
        sw[r][d] = Wo[h * 4096 + idx];
    }
    __syncthreads();
    int e = tid & 63, rq = tid >> 6;
#pragma unroll
    for (int i = 0; i < 16; i++) {
        int r = rq * 16 + i;
        float acc = 0.f;
#pragma unroll
        for (int d = 0; d < 64; d++) acc = fmaf(sx[r][d], sw[d][e], acc);
        size_t o = ((size_t)(b * SS + s0 + r)) * DD + h * 64 + e;
        x1[o] = x[o] + acc;
    }
}

// ---------------- host side ----------------
extern "C" void kernel_launch(void* const* d_in, const int* in_sizes, int n_in,
                              void* d_out, int out_size)
{
    const float* x   = (const float*)d_in[0];
    const float* Wq  = (const float*)d_in[1];
    const float* Wk  = (const float*)d_in[2];
    const float* Wv  = (const float*)d_in[3];
    const float* Wo  = (const float*)d_in[4];
    const float* om  = (const float*)d_in[5];
    const float* g1  = (const float*)d_in[6];
    const float* be1 = (const float*)d_in[7];
    const float* g2  = (const float*)d_in[8];
    const float* be2 = (const float*)d_in[9];
    const float* W1  = (const float*)d_in[10];
    const float* bf1 = (const float*)d_in[11];
    const float* W2  = (const float*)d_in[12];
    const float* bf2 = (const float*)d_in[13];
    float* out = (float*)d_out;
    (void)in_sizes; (void)n_in; (void)out_size;

    float *xn, *ab, *d1, *attnv, *mixb, *x1;
    __half *S_, *Ahi, *xnhi, *xnlo, *qhi, *qlo, *khi;
    __half *abX, *pX, *ffhi, *fflo, *W1h, *W2h;
    cudaGetSymbolAddress((void**)&S_,    g_S);
    cudaGetSymbolAddress((void**)&Ahi,   g_Ahi);
    cudaGetSymbolAddress((void**)&xn,    g_xn);
    cudaGetSymbolAddress((void**)&xnhi,  g_xnhi);
    cudaGetSymbolAddress((void**)&xnlo,  g_xnlo);
    cudaGetSymbolAddress((void**)&qhi,   g_qhi);
    cudaGetSymbolAddress((void**)&qlo,   g_qlo);
    cudaGetSymbolAddress((void**)&khi,   g_khi);
    cudaGetSymbolAddress((void**)&ab,    g_ab);
    cudaGetSymbolAddress((void**)&d1,    g_d1);
    cudaGetSymbolAddress((void**)&abX,   g_abX);
    cudaGetSymbolAddress((void**)&pX,    g_pX);
    cudaGetSymbolAddress((void**)&attnv, g_attnv);
    cudaGetSymbolAddress((void**)&mixb,  g_mix);
    cudaGetSymbolAddress((void**)&x1,    g_x1);
    cudaGetSymbolAddress((void**)&ffhi,  g_ffhi);
    cudaGetSymbolAddress((void**)&fflo,  g_fflo);
    cudaGetSymbolAddress((void**)&W1h,   g_W1h);
    cudaGetSymbolAddress((void**)&W2h,   g_W2h);

    cudaFuncSetAttribute(hgemm_kernel<true, 0, 2>,
                         cudaFuncAttributeMaxDynamicSharedMemorySize, HSMEM2);
    cudaFuncSetAttribute(hgemm_kernel<false, 0, 2>,
                         cudaFuncAttributeMaxDynamicSharedMemorySize, HSMEM2);
    cudaFuncSetAttribute(hgemm_kernel<true, 1, 1>,
                         cudaFuncAttributeMaxDynamicSharedMemorySize, HSMEM1);
    cudaFuncSetAttribute(hgemm_kernel<true, 2, 1>,
                         cudaFuncAttributeMaxDynamicSharedMemorySize, HSMEM1);

    const long long sQK = (long long)SS * 64;
    const long long sAA = (long long)SS * SS;
    const long long sAB = (long long)SS * 128;

    splitWh_kernel<<<(unsigned)((size_t)DD * DFFC / 1024), 256>>>(W1, W1h);
    splitWh_kernel<<<(unsigned)((size_t)DFFC * DD / 1024), 256>>>(W2, W2h);

    // 1. LN1
    ln_kernel<<<NTOK, 256>>>(x, g1, be1, xn, nullptr, nullptr);
    // 2. QKV (3-way parallel, 64 rows/block)
    qkv_kernel<<<dim3(SS / 64, BH, 3), 256>>>(xn, Wq, Wk, Wv, qhi, qlo, khi, ab, abX);
    // 3. scores (fp16 2-product) -> fp16 S
    hgemm_kernel<false, 0, 2><<<dim3(16, 16, BH), 256, HSMEM2>>>(
        qhi, qlo, khi, 64, 64, 64, SS, sQK, sQK, sAA,
        reinterpret_cast<float*>(S_), nullptr, nullptr, nullptr, nullptr, 0,
        nullptr, nullptr, nullptr, nullptr, nullptr, 1);
    // 4. softmax (fp16 in) + scaled fp16 A
    softmax_split_kernel<<<BH * SS, 256>>>(S_, Ahi);
    // 5. Heun loop: fp16 1-product GEMM (2-stage, 2 CTAs/SM) + fused ODE epilogues
    for (int st = 0; st < 5; st++) {
        hgemm_kernel<true, 1, 1><<<dim3(1, 16, BH), 256, HSMEM1>>>(
            Ahi, nullptr, abX, SS, SS, 128, 128, sAA, sAB, sAB,
            nullptr, pX, nullptr, nullptr, nullptr, 0,
            om, ab, d1, attnv, nullptr, st == 0 ? 1 : 0);
        hgemm_kernel<true, 2, 1><<<dim3(1, 16, BH), 256, HSMEM1>>>(
            Ahi, nullptr, pX, SS, SS, 128, 128, sAA, sAB, sAB,
            nullptr, abX, nullptr, nullptr, nullptr, 0,
            om, ab, d1, attnv, mixb, st == 4 ? 1 : 0);
    }
    // 6. head projection + residual (64 rows/block)
    headout_kernel<<<dim3(SS / 64, BH), 256>>>(mixb, Wo, x, x1);
    // 7. LN2 -> fp32 + fp16 hi/lo
    ln_kernel<<<NTOK, 256>>>(x1, g2, be2, xn, xnhi, xnlo);
    // 8. FFN1 (fp16 2-product): gelu(xn @ W1 + bf1) -> ff fp16 hi/lo
    hgemm_kernel<true, 0, 2><<<dim3(16, 32, 1), 256, HSMEM2>>>(
        xnhi, xnlo, W1h, DD, DD, DFFC, DFFC, 0, 0, 0,
        nullptr, ffhi, fflo, bf1, nullptr, 1,
        nullptr, nullptr, nullptr, nullptr, nullptr, 0);
    // 9. FFN2 (fp16 2-product): out = x1 + ff @ W2 + bf2 (fp32 out)
    hgemm_kernel<true, 0, 2><<<dim3(8, 32, 1), 256, HSMEM2>>>(
        ffhi, fflo, W2h, DFFC, DFFC, DD, DD, 0, 0, 0,
        out, nullptr, nullptr, bf2, x1, 0,
        nullptr, nullptr, nullptr, nullptr, nullptr, 0);
}

// round 15
// speedup vs baseline: 2.6688x; 1.1320x over previous
#include <cuda_runtime.h>
#include <cuda_bf16.h>
#include <cuda_fp16.h>
#include <math.h>
#include <stddef.h>
#include <stdint.h>

// ---------------- problem constants ----------------
#define BB   2
#define SS   2048
#define DD   1024
#define HH   16
#define HDIM 64
#define DFFC 2048
#define BH   (BB*HH)
#define NTOK (BB*SS)

#define MU_C   1.0f
#define K_C    3.0f
#define DT_C   0.02f
#define MIX_C  0.3f
#define CA_C   0.9950041652780258f
#define SA_C   0.09983341664682815f
#define ASCALE 2048.0f
#define AINV   (1.0f / 2048.0f)

// ---------------- scratch ----------------
__device__ __half g_S [(size_t)BH * SS * SS];           // fp16 raw scores
__device__ __half g_Ahi[(size_t)BH * SS * SS];          // fp16 scaled A
__device__ float g_xn  [(size_t)NTOK * DD];
__device__ __half g_xnhi[(size_t)NTOK * DD];
__device__ __half g_qhi[(size_t)BH * SS * 64];
__device__ __half g_khi[(size_t)BH * SS * 64];
__device__ float g_ab  [(size_t)BH * SS * 128];
__device__ float g_d1  [(size_t)BH * SS * 128];
__device__ __half g_abX[(size_t)BH * SS * 128];         // fp16 X state
__device__ __half g_pX [(size_t)BH * SS * 128];         // fp16 X predictor
__device__ float g_attnv[(size_t)BH * SS * 64];
__device__ float g_mix  [(size_t)BH * SS * 64];
__device__ float g_x1   [(size_t)NTOK * DD];
__device__ __half g_ffhi[(size_t)NTOK * DFFC];
__device__ __half g_W1h[(size_t)DD * DFFC];
__device__ __half g_W2h[(size_t)DFFC * DD];

// ---------------- low-level helpers ----------------
__device__ __forceinline__ uint32_t smem_u32(const void* p) {
    uint32_t a;
    asm("{ .reg .u64 t; cvta.to.shared.u64 t, %1; cvt.u32.u64 %0, t; }" : "=r"(a) : "l"(p));
    return a;
}
__device__ __forceinline__ void cp16(uint32_t s, const void* g) {
    asm volatile("cp.async.cg.shared.global [%0], [%1], 16;" :: "r"(s), "l"(g));
}
__device__ __forceinline__ void cp_commit() {
    asm volatile("cp.async.commit_group;" ::: "memory");
}
template <int N>
__device__ __forceinline__ void cp_wait() {
    asm volatile("cp.async.wait_group %0;" :: "n"(N) : "memory");
}
__device__ __forceinline__ void ldm_x4(uint32_t* r, uint32_t addr) {
    asm volatile("ldmatrix.sync.aligned.m8n8.x4.shared.b16 {%0,%1,%2,%3}, [%4];"
        : "=r"(r[0]), "=r"(r[1]), "=r"(r[2]), "=r"(r[3]) : "r"(addr));
}
__device__ __forceinline__ void ldm_x4t(uint32_t* r, uint32_t addr) {
    asm volatile("ldmatrix.sync.aligned.m8n8.x4.trans.shared.b16 {%0,%1,%2,%3}, [%4];"
        : "=r"(r[0]), "=r"(r[1]), "=r"(r[2]), "=r"(r[3]) : "r"(addr));
}
__device__ __forceinline__ void mma_f16(float* c, const uint32_t* a, const uint32_t* b) {
    asm volatile("mma.sync.aligned.m16n8k16.row.col.f32.f16.f16.f32 "
        "{%0,%1,%2,%3}, {%4,%5,%6,%7}, {%8,%9}, {%0,%1,%2,%3};"
        : "+f"(c[0]), "+f"(c[1]), "+f"(c[2]), "+f"(c[3])
        : "r"(a[0]), "r"(a[1]), "r"(a[2]), "r"(a[3]), "r"(b[0]), "r"(b[1]));
}
__device__ __forceinline__ float gelu_tanh(float x) {
    float x3 = x * x * x;
    float t  = tanhf(0.7978845608028654f * (x + 0.044715f * x3));
    return 0.5f * x * (1.0f + t);
}

// ---------------- unified fp16 HMMA GEMM, fusable ODE epilogue ----------------
// EPI: 0 = plain C output; 1 = fused ode_ew1; 2 = fused ode_ew2.
// PROD: 2 = fp16 2-product ((Ahi+Alo) @ Bhi).  1 = fp16 1-product (Ahi @ Bhi).
// EPI0: outF!=0 && flag==0 -> fp32; flag==1 -> fp16 into outF.
//       outHi!=0 -> fp16 hi (and lo iff outLo!=0).
#define AST 72
#define BSTN 72
#define BSTT 136
#define STG2 55296
#define STG1 36864
#define HSMEM2 (3 * STG2)     // 165888, 1 CTA/SM
#define HSMEM1 (2 * STG1)     // 73728,  2 CTA/SM (R10-proven config)

template<bool TRANSB, int EPI, int PROD>
__global__ void __launch_bounds__(256)
hgemm_kernel(const __half* __restrict__ Ahi, const __half* __restrict__ Alo,
             const __half* __restrict__ Bhi,
             int K, int lda, int ldb, int ldc,
             long long sA, long long sB, long long sC,
             float* __restrict__ outF,
             __half* __restrict__ outHi, __half* __restrict__ outLo,
             const float* __restrict__ bias, const float* __restrict__ addsrc, int do_gelu,
             const float* __restrict__ omg, float* __restrict__ abf,
             float* __restrict__ d1f, float* __restrict__ attnv,
             float* __restrict__ mixed, int flag)
{
    constexpr int STGB  = (PROD == 2) ? STG2 : STG1;
    constexpr int OFFAL = 18432;                         // A-lo (PROD == 2)
    constexpr int OFFBH = (PROD == 1) ? 18432 : 36864;   // B-hi
    extern __shared__ char smem[];
    const uint32_t sb = smem_u32(smem);
    const int tid = threadIdx.x;
    const int lane = tid & 31, w = tid >> 5;
    const int wm = w >> 2, wn = w & 3;
    const int n0 = blockIdx.x * 128;
    const int m0 = blockIdx.y * 128;
    const long long bz = blockIdx.z;

    Ahi += bz * sA;
    if (PROD == 2) Alo += bz * sA;
    Bhi += bz * sB;

    float acc[4][4][4];
#pragma unroll
    for (int i = 0; i < 4; i++)
#pragma unroll
        for (int j = 0; j < 4; j++)
#pragma unroll
            for (int r = 0; r < 4; r++) acc[i][j][r] = 0.f;

    auto issue = [&](int chunk, int buf) {
        const int k0 = chunk << 6;
        const uint32_t st = sb + buf * STGB;
        {
            const int row = tid >> 3, col = (tid & 7) * 8;
            const __half* gH = Ahi + (size_t)(m0 + row) * lda + k0 + col;
            uint32_t s = st + (row * AST + col) * 2;
#pragma unroll
            for (int j = 0; j < 4; j++)
                cp16(s + j * 32 * (AST * 2), gH + (size_t)j * 32 * lda);
            if (PROD == 2) {
                const __half* gL = Alo + (size_t)(m0 + row) * lda + k0 + col;
#pragma unroll
                for (int j = 0; j < 4; j++)
                    cp16(s + OFFAL + j * 32 * (AST * 2), gL + (size_t)j * 32 * lda);
            }
        }
        if (TRANSB) {
            const int rk = tid >> 2, col = (tid & 3) * 8;
            const __half* gH = Bhi + (size_t)(k0 + rk) * ldb + n0 + col;
            uint32_t s = st + OFFBH + (rk * BSTT + col) * 2;
#pragma unroll
            for (int j = 0; j < 4; j++)
                cp16(s + j * 64, gH + j * 32);
        } else {
            const int rn = tid >> 3, col = (tid & 7) * 8;
            const __half* gH = Bhi + (size_t)(n0 + rn) * ldb + k0 + col;
            uint32_t s = st + OFFBH + (rn * BSTN + col) * 2;
#pragma unroll
            for (int j = 0; j < 4; j++)
                cp16(s + j * 32 * (BSTN * 2), gH + (size_t)j * 32 * ldb);
        }
        cp_commit();
    };

    auto compute = [&](int buf) {
        const uint32_t st = sb + buf * STGB;
#pragma unroll
        for (int k16 = 0; k16 < 4; k16++) {
            uint32_t afrH[4][4], afrL[4][4], bfrH[4][2];
#pragma unroll
            for (int ms = 0; ms < 4; ms++) {
                int row = wm * 64 + ms * 16 + (lane & 15);
                int col = k16 * 16 + (lane >> 4) * 8;
                ldm_x4(afrH[ms], st + (row * AST + col) * 2);
                if (PROD == 2)
                    ldm_x4(afrL[ms], st + OFFAL + (row * AST + col) * 2);
            }
            if (TRANSB) {
                const int mat = lane >> 3, rr = lane & 7;
#pragma unroll
                for (int p = 0; p < 2; p++) {
                    int rk = k16 * 16 + (mat & 1) * 8 + rr;
                    int cn = wn * 32 + p * 16 + (mat >> 1) * 8;
                    ldm_x4t(&bfrH[p * 2][0], st + OFFBH + (rk * BSTT + cn) * 2);
                }
            } else {
                const int mat = lane >> 3, rr = lane & 7;
#pragma unroll
                for (int p = 0; p < 2; p++) {
                    int rn = wn * 32 + p * 16 + (mat >> 1) * 8 + rr;
                    int ck = k16 * 16 + (mat & 1) * 8;
                    ldm_x4(&bfrH[p * 2][0], st + OFFBH + (rn * BSTN + ck) * 2);
                }
            }
#pragma unroll
            for (int ms = 0; ms < 4; ms++)
#pragma unroll
                for (int ns = 0; ns < 4; ns++) {
                    mma_f16(acc[ms][ns], afrH[ms], bfrH[ns]);
                    if (PROD == 2)
                        mma_f16(acc[ms][ns], afrL[ms], bfrH[ns]);
                }
        }
    };

    const int nchunk = K >> 6;
    if (PROD == 2) {
        issue(0, 0);
        if (nchunk > 1) issue(1, 1);
#pragma unroll 1
        for (int i = 0; i < nchunk; i++) {
            if (i + 2 < nchunk)      { issue(i + 2, (i + 2) % 3); cp_wait<2>(); }
            else if (i + 1 < nchunk) { cp_wait<1>(); }
            else                     { cp_wait<0>(); }
            __syncthreads();
            compute(i % 3);
            __syncthreads();
        }
    } else {
        issue(0, 0);
#pragma unroll 1
        for (int i = 0; i < nchunk; i++) {
            if (i + 1 < nchunk) { issue(i + 1, (i + 1) & 1); cp_wait<1>(); }
            else                { cp_wait<0>(); }
            __syncthreads();
            compute(i & 1);
            __syncthreads();
        }
    }

    if (EPI == 0) {
        const long long cb = bz * sC;
#pragma unroll
        for (int ms = 0; ms < 4; ms++) {
#pragma unroll
            for (int ns = 0; ns < 4; ns++) {
                int r0 = wm * 64 + ms * 16 + (lane >> 2);
                int c0 = n0 + wn * 32 + ns * 8 + (lane & 3) * 2;
#pragma unroll
                for (int half = 0; half < 2; half++) {
                    long long r = m0 + r0 + half * 8;
                    float vx = acc[ms][ns][half * 2 + 0];
                    float vy = acc[ms][ns][half * 2 + 1];
                    if (bias)   { vx += bias[c0]; vy += bias[c0 + 1]; }
                    if (addsrc) {
                        float2 s = *reinterpret_cast<const float2*>(addsrc + r * ldc + c0);
                        vx += s.x; vy += s.y;
                    }
                    if (do_gelu) { vx = gelu_tanh(vx); vy = gelu_tanh(vy); }
                    long long o = cb + r * ldc + c0;
                    if (outF) {
                        if (flag)   // fp16 output
                            *reinterpret_cast<__half2*>(
                                reinterpret_cast<__half*>(outF) + o) =
                                __floats2half2_rn(vx, vy);
                        else
                            *reinterpret_cast<float2*>(outF + o) = make_float2(vx, vy);
                    }
                    if (outHi) {
                        __half2 h = __floats2half2_rn(vx, vy);
                        *reinterpret_cast<__half2*>(outHi + o) = h;
                        if (outLo) {
                            float2 hf = __half22float2(h);
                            *reinterpret_cast<__half2*>(outLo + o) =
                                __floats2half2_rn(vx - hf.x, vy - hf.y);
                        }
                    }
                }
            }
        }
    } else {
        // stage z tile into smem (unscale by AINV), then batched ODE elementwise
        float* zsm = reinterpret_cast<float*>(smem);
#pragma unroll
        for (int ms = 0; ms < 4; ms++)
#pragma unroll
            for (int ns = 0; ns < 4; ns++) {
                int r0 = wm * 64 + ms * 16 + (lane >> 2);
                int c0 = wn * 32 + ns * 8 + (lane & 3) * 2;
                zsm[r0 * 132 + c0]     = acc[ms][ns][0] * AINV;
                zsm[r0 * 132 + c0 + 1] = acc[ms][ns][1] * AINV;
                zsm[(r0 + 8) * 132 + c0]     = acc[ms][ns][2] * AINV;
                zsm[(r0 + 8) * 132 + c0 + 1] = acc[ms][ns][3] * AINV;
            }
        __syncthreads();
        const int h = (int)(bz & 15);
        __half* Xout = outHi;
#pragma unroll 1
        for (int ib = 0; ib < 2; ib++) {
            float2 a2[8], b2[8], d1a[8], d1b[8];
            int r8[8], cp8[8];
            size_t base8[8];
#pragma unroll
            for (int j = 0; j < 8; j++) {
                int lin = (ib * 8 + j) * 256 + tid;
                int r = lin >> 5, cp = (lin & 31) * 2;
                r8[j] = r; cp8[j] = cp;
                size_t base = ((size_t)bz * SS + m0 + r) * 128 + cp;
                base8[j] = base;
                a2[j] = *reinterpret_cast<const float2*>(abf + base);
                b2[j] = *reinterpret_cast<const float2*>(abf + base + 64);
                if (EPI == 2) {
                    d1a[j] = *reinterpret_cast<const float2*>(d1f + base);
                    d1b[j] = *reinterpret_cast<const float2*>(d1f + base + 64);
                }
            }
#pragma unroll
            for (int j = 0; j < 8; j++) {
                int r = r8[j], cp = cp8[j];
                size_t base = base8[j];
                size_t row = (size_t)bz * SS + m0 + r;
                float2 om2 = *reinterpret_cast<const float2*>(omg + h * 64 + cp);
                float za0 = zsm[r * 132 + cp],     za1 = zsm[r * 132 + cp + 1];
                float zb0 = zsm[r * 132 + cp + 64], zb1 = zsm[r * 132 + cp + 65];
                float ra0 = za0 * CA_C + zb0 * SA_C, rb0 = zb0 * CA_C - za0 * SA_C;
                float ra1 = za1 * CA_C + zb1 * SA_C, rb1 = zb1 * CA_C - za1 * SA_C;
                if (EPI == 1) {
                    if (flag)
                        *reinterpret_cast<float2*>(attnv + row * 64 + cp) =
                            make_float2(za0, za1);
                    float r20 = a2[j].x * a2[j].x + b2[j].x * b2[j].x;
                    float r21 = a2[j].y * a2[j].y + b2[j].y * b2[j].y;
                    float da0 = (MU_C - r20) * a2[j].x - om2.x * b2[j].x + K_C * (ra0 - a2[j].x);
                    float db0 = (MU_C - r20) * b2[j].x + om2.x * a2[j].x + K_C * (rb0 - b2[j].x);
                    float da1 = (MU_C - r21) * a2[j].y - om2.y * b2[j].y + K_C * (ra1 - a2[j].y);
                    float db1 = (MU_C - r21) * b2[j].y + om2.y * a2[j].y + K_C * (rb1 - b2[j].y);
                    *reinterpret_cast<float2*>(d1f + base)      = make_float2(da0, da1);
                    *reinterpret_cast<float2*>(d1f + base + 64) = make_float2(db0, db1);
                    float ap0 = a2[j].x + DT_C * da0, ap1 = a2[j].y + DT_C * da1;
                    float bp0 = b2[j].x + DT_C * db0, bp1 = b2[j].y + DT_C * db1;
                    *reinterpret_cast<__half2*>(Xout + base) = __floats2half2_rn(ap0, ap1);
                    *reinterpret_cast<__half2*>(Xout + base + 64) = __floats2half2_rn(bp0, bp1);
                } else {
                    float ap0 = a2[j].x + DT_C * d1a[j].x, ap1 = a2[j].y + DT_C * d1a[j].y;
                    float bp0 = b2[j].x + DT_C * d1b[j].x, bp1 = b2[j].y + DT_C * d1b[j].y;
                    float r20 = ap0 * ap0 + bp0 * bp0;
                    float r21 = ap1 * ap1 + bp1 * bp1;
                    float da20 = (MU_C - r20) * ap0 - om2.x * bp0 + K_C * (ra0 - ap0);
                    float db20 = (MU_C - r20) * bp0 + om2.x * ap0 + K_C * (rb0 - bp0);
                    float da21 = (MU_C - r21) * ap1 - om2.y * bp1 + K_C * (ra1 - ap1);
                    float db21 = (MU_C - r21) * bp1 + om2.y * ap1 + K_C * (rb1 - bp1);
                    float an0 = a2[j].x + 0.5f * DT_C * (d1a[j].x + da20);
                    float an1 = a2[j].y + 0.5f * DT_C * (d1a[j].y + da21);
                    float bn0 = b2[j].x + 0.5f * DT_C * (d1b[j].x + db20);
                    float bn1 = b2[j].y + 0.5f * DT_C * (d1b[j].y + db21);
                    *reinterpret_cast<float2*>(abf + base)      = make_float2(an0, an1);
                    *reinterpret_cast<float2*>(abf + base + 64) = make_float2(bn0, bn1);
                    if (flag) {
                        float2 av = *reinterpret_cast<const float2*>(attnv + row * 64 + cp);
                        *reinterpret_cast<float2*>(mixed + row * 64 + cp) =
                            make_float2(MIX_C * av.x + (1.0f - MIX_C) * an0,
                                        MIX_C * av.y + (1.0f - MIX_C) * an1);
                    } else {
                        *reinterpret_cast<__half2*>(Xout + base) = __floats2half2_rn(an0, an1);
                        *reinterpret_cast<__half2*>(Xout + base + 64) = __floats2half2_rn(bn0, bn1);
                    }
                }
            }
        }
    }
}

// ---------------- fp32 -> fp16 weight convert ----------------
__global__ void splitWh_kernel(const float* __restrict__ A, __half* __restrict__ h)
{
    size_t i = ((size_t)blockIdx.x * blockDim.x + threadIdx.x) * 4;
    float4 v = *reinterpret_cast<const float4*>(A + i);
    *reinterpret_cast<__half2*>(h + i)     = __floats2half2_rn(v.x, v.y);
    *reinterpret_cast<__half2*>(h + i + 2) = __floats2half2_rn(v.z, v.w);
}

// ---------------- LayerNorm (optional fp16 hi output) ----------------
__global__ void ln_kernel(const float* __restrict__ x, const float* __restrict__ g,
                          const float* __restrict__ be, float* __restrict__ out,
                          __half* __restrict__ outHi)
{
    __shared__ float sh[8];
    size_t row = blockIdx.x;
    int tid = threadIdx.x, lane = tid & 31, wid = tid >> 5;
    float4 v = reinterpret_cast<const float4*>(x + row * DD)[tid];

    float s = v.x + v.y + v.z + v.w;
#pragma unroll
    for (int o = 16; o; o >>= 1) s += __shfl_xor_sync(0xffffffffu, s, o);
    if (lane == 0) sh[wid] = s;
    __syncthreads();
    float tot = 0.f;
#pragma unroll
    for (int i = 0; i < 8; i++) tot += sh[i];
    float mean = tot * (1.0f / DD);

    float dx = v.x - mean, dy = v.y - mean, dz = v.z - mean, dw = v.w - mean;
    float s2 = dx*dx + dy*dy + dz*dz + dw*dw;
#pragma unroll
    for (int o = 16; o; o >>= 1) s2 += __shfl_xor_sync(0xffffffffu, s2, o);
    __syncthreads();
    if (lane == 0) sh[wid] = s2;
    __syncthreads();
    float tot2 = 0.f;
#pragma unroll
    for (int i = 0; i < 8; i++) tot2 += sh[i];
    float rstd = rsqrtf(tot2 * (1.0f / DD) + 1e-5f);

    float4 gv = reinterpret_cast<const float4*>(g)[tid];
    float4 bv = reinterpret_cast<const float4*>(be)[tid];
    float4 o4;
    o4.x = dx * rstd * gv.x + bv.x;
    o4.y = dy * rstd * gv.y + bv.y;
    o4.z = dz * rstd * gv.z + bv.z;
    o4.w = dw * rstd * gv.w + bv.w;
    reinterpret_cast<float4*>(out + row * DD)[tid] = o4;
    if (outHi) {
        size_t i = row * DD + tid * 4;
        *reinterpret_cast<__half2*>(outHi + i)     = __floats2half2_rn(o4.x, o4.y);
        *reinterpret_cast<__half2*>(outHi + i + 2) = __floats2half2_rn(o4.z, o4.w);
    }
}

// ---------------- QKV projection (3-way parallel, 64 rows/block) ----------------
__global__ void qkv_kernel(const float* __restrict__ xn,
                           const float* __restrict__ Wq, const float* __restrict__ Wk,
                           const float* __restrict__ Wv,
                           __half* __restrict__ qhi, __half* __restrict__ khi,
                           float* __restrict__ ab, __half* __restrict__ abX)
{
    __shared__ float sx[64][65];
    __shared__ float sw[64][65];
    int bh = blockIdx.y, b = bh >> 4, h = bh & 15;
    int wsel = blockIdx.z;
    int s0 = blockIdx.x * 64;
    int tid = threadIdx.x;

    const float* W = (wsel == 0 ? Wq : (wsel == 1 ? Wk : Wv)) + h * 4096;
    for (int idx = tid; idx < 4096; idx += 256) {
        int r = idx >> 6, d = idx & 63;
        sx[r][d] = xn[((size_t)(b * SS + s0 + r)) * DD + h * 64 + d];
        sw[r][d] = W[idx];
    }
    __syncthreads();
    int e = tid & 63, rq = tid >> 6;
#pragma unroll
    for (int i = 0; i < 16; i++) {
        int r = rq * 16 + i;
        float acc = 0.f;
#pragma unroll
        for (int d = 0; d < 64; d++) acc = fmaf(sx[r][d], sw[d][e], acc);
        size_t srow = (size_t)bh * SS + s0 + r;
        if (wsel == 0) {
            qhi[srow * 64 + e] = __float2half(acc);
        } else if (wsel == 1) {
            khi[srow * 64 + e] = __float2half(acc);
        } else {
            ab[srow * 128 + e] = acc; ab[srow * 128 + 64 + e] = 0.f;
            abX[srow * 128 + e] = __float2half(acc);
            abX[srow * 128 + 64 + e] = __float2half(0.f);
        }
    }
}

// ---------------- fused softmax (fp16 in) + scaled fp16 emit ----------------
__global__ void softmax_split_kernel(const __half* __restrict__ S,
                                     __half* __restrict__ Ahi)
{
    __shared__ float sh[8];
    size_t row = blockIdx.x;
    const __half* p = S + row * (size_t)SS;
    int tid = threadIdx.x, lane = tid & 31, wid = tid >> 5;

    float4 raw = reinterpret_cast<const float4*>(p)[tid];   // 8 halves
    const __half2* hp = reinterpret_cast<const __half2*>(&raw);
    float v[8];
#pragma unroll
    for (int i = 0; i < 4; i++) {
        float2 f = __half22float2(hp[i]);
        v[i * 2] = f.x * 0.125f; v[i * 2 + 1] = f.y * 0.125f;
    }

    float mx = v[0];
#pragma unroll
    for (int i = 1; i < 8; i++) mx = fmaxf(mx, v[i]);
#pragma unroll
    for (int o = 16; o; o >>= 1) mx = fmaxf(mx, __shfl_xor_sync(0xffffffffu, mx, o));
    if (lane == 0) sh[wid] = mx;
    __syncthreads();
    float m = sh[0];
#pragma unroll
    for (int i = 1; i < 8; i++) m = fmaxf(m, sh[i]);

    float s = 0.f;
#pragma unroll
    for (int i = 0; i < 8; i++) { v[i] = expf(v[i] - m); s += v[i]; }
#pragma unroll
    for (int o = 16; o; o >>= 1) s += __shfl_xor_sync(0xffffffffu, s, o);
    __syncthreads();
    if (lane == 0) sh[wid] = s;
    __syncthreads();
    float tot = 0.f;
#pragma unroll
    for (int i = 0; i < 8; i++) tot += sh[i];
    float inv = ASCALE / tot;

    size_t ob = row * (size_t)SS + tid * 8;
#pragma unroll
    for (int i = 0; i < 4; i++)
        *reinterpret_cast<__half2*>(Ahi + ob + i * 2) =
            __floats2half2_rn(v[i * 2] * inv, v[i * 2 + 1] * inv);
}

// ---------------- head projection + residual (64 rows/block) ----------------
__global__ void headout_kernel(const float* __restrict__ mix, const float* __restrict__ Wo,
                               const float* __restrict__ x, float* __restrict__ x1)
{
    __shared__ float sx[64][65];
    __shared__ float sw[64][65];
    int bh = blockIdx.y, b = bh >> 4, h = bh & 15;
    int s0 = blockIdx.x * 64;
    int tid = threadIdx.x;

    for (int idx = tid; idx < 4096; idx += 256) {
        int r = idx >> 6, d = idx & 63;
        sx[r][d] = mix[((size_t)bh * SS + s0 + r) * 64 + d];
        sw[r][d] = Wo[h * 4096 + idx];
    }
    __syncthreads();
    int e = tid & 63, rq = tid >> 6;
#pragma unroll
    for (int i = 0; i < 16; i++) {
        int r = rq * 16 + i;
        float acc = 0.f;
#pragma unroll
        for (int d = 0; d < 64; d++) acc = fmaf(sx[r][d], sw[d][e], acc);
        size_t o = ((size_t)(b * SS + s0 + r)) * DD + h * 64 + e;
        x1[o] = x[o] + acc;
    }
}

// ---------------- host side ----------------
extern "C" void kernel_launch(void* const* d_in, const int* in_sizes, int n_in,
                              void* d_out, int out_size)
{
    const float* x   = (const float*)d_in[0];
    const float* Wq  = (const float*)d_in[1];
    const float* Wk  = (const float*)d_in[2];
    const float* Wv  = (const float*)d_in[3];
    const float* Wo  = (const float*)d_in[4];
    const float* om  = (const float*)d_in[5];
    const float* g1  = (const float*)d_in[6];
    const float* be1 = (const float*)d_in[7];
    const float* g2  = (const float*)d_in[8];
    const float* be2 = (const float*)d_in[9];
    const float* W1  = (const float*)d_in[10];
    const float* bf1 = (const float*)d_in[11];
    const float* W2  = (const float*)d_in[12];
    const float* bf2 = (const float*)d_in[13];
    float* out = (float*)d_out;
    (void)in_sizes; (void)n_in; (void)out_size;

    float *xn, *ab, *d1, *attnv, *mixb, *x1;
    __half *S_, *Ahi, *xnhi, *qhi, *khi;
    __half *abX, *pX, *ffhi, *W1h, *W2h;
    cudaGetSymbolAddress((void**)&S_,    g_S);
    cudaGetSymbolAddress((void**)&Ahi,   g_Ahi);
    cudaGetSymbolAddress((void**)&xn,    g_xn);
    cudaGetSymbolAddress((void**)&xnhi,  g_xnhi);
    cudaGetSymbolAddress((void**)&qhi,   g_qhi);
    cudaGetSymbolAddress((void**)&khi,   g_khi);
    cudaGetSymbolAddress((void**)&ab,    g_ab);
    cudaGetSymbolAddress((void**)&d1,    g_d1);
    cudaGetSymbolAddress((void**)&abX,   g_abX);
    cudaGetSymbolAddress((void**)&pX,    g_pX);
    cudaGetSymbolAddress((void**)&attnv, g_attnv);
    cudaGetSymbolAddress((void**)&mixb,  g_mix);
    cudaGetSymbolAddress((void**)&x1,    g_x1);
    cudaGetSymbolAddress((void**)&ffhi,  g_ffhi);
    cudaGetSymbolAddress((void**)&W1h,   g_W1h);
    cudaGetSymbolAddress((void**)&W2h,   g_W2h);

    cudaFuncSetAttribute(hgemm_kernel<false, 0, 1>,
                         cudaFuncAttributeMaxDynamicSharedMemorySize, HSMEM1);
    cudaFuncSetAttribute(hgemm_kernel<true, 0, 1>,
                         cudaFuncAttributeMaxDynamicSharedMemorySize, HSMEM1);
    cudaFuncSetAttribute(hgemm_kernel<true, 1, 1>,
                         cudaFuncAttributeMaxDynamicSharedMemorySize, HSMEM1);
    cudaFuncSetAttribute(hgemm_kernel<true, 2, 1>,
                         cudaFuncAttributeMaxDynamicSharedMemorySize, HSMEM1);

    const long long sQK = (long long)SS * 64;
    const long long sAA = (long long)SS * SS;
    const long long sAB = (long long)SS * 128;

    splitWh_kernel<<<(unsigned)((size_t)DD * DFFC / 1024), 256>>>(W1, W1h);
    splitWh_kernel<<<(unsigned)((size_t)DFFC * DD / 1024), 256>>>(W2, W2h);

    // 1. LN1
    ln_kernel<<<NTOK, 256>>>(x, g1, be1, xn, nullptr);
    // 2. QKV (3-way parallel, 64 rows/block)
    qkv_kernel<<<dim3(SS / 64, BH, 3), 256>>>(xn, Wq, Wk, Wv, qhi, khi, ab, abX);
    // 3. scores (fp16 1-product) -> fp16 S
    hgemm_kernel<false, 0, 1><<<dim3(16, 16, BH), 256, HSMEM1>>>(
        qhi, nullptr, khi, 64, 64, 64, SS, sQK, sQK, sAA,
        reinterpret_cast<float*>(S_), nullptr, nullptr, nullptr, nullptr, 0,
        nullptr, nullptr, nullptr, nullptr, nullptr, 1);
    // 4. softmax (fp16 in) + scaled fp16 A
    softmax_split_kernel<<<BH * SS, 256>>>(S_, Ahi);
    // 5. Heun loop: fp16 1-product GEMM (2-stage, 2 CTAs/SM) + fused ODE epilogues
    for (int st = 0; st < 5; st++) {
        hgemm_kernel<true, 1, 1><<<dim3(1, 16, BH), 256, HSMEM1>>>(
            Ahi, nullptr, abX, SS, SS, 128, 128, sAA, sAB, sAB,
            nullptr, pX, nullptr, nullptr, nullptr, 0,
            om, ab, d1, attnv, nullptr, st == 0 ? 1 : 0);
        hgemm_kernel<true, 2, 1><<<dim3(1, 16, BH), 256, HSMEM1>>>(
            Ahi, nullptr, pX, SS, SS, 128, 128, sAA, sAB, sAB,
            nullptr, abX, nullptr, nullptr, nullptr, 0,
            om, ab, d1, attnv, mixb, st == 4 ? 1 : 0);
    }
    // 6. head projection + residual (64 rows/block)
    headout_kernel<<<dim3(SS / 64, BH), 256>>>(mixb, Wo, x, x1);
    // 7. LN2 -> fp32 + fp16 hi
    ln_kernel<<<NTOK, 256>>>(x1, g2, be2, xn, xnhi);
    // 8. FFN1 (fp16 1-product): gelu(xn @ W1 + bf1) -> ff fp16 hi
    hgemm_kernel<true, 0, 1><<<dim3(16, 32, 1), 256, HSMEM1>>>(
        xnhi, nullptr, W1h, DD, DD, DFFC, DFFC, 0, 0, 0,
        nullptr, ffhi, nullptr, bf1, nullptr, 1,
        nullptr, nullptr, nullptr, nullptr, nullptr, 0);
    // 9. FFN2 (fp16 1-product): out = x1 + ff @ W2 + bf2 (fp32 out)
    hgemm_kernel<true, 0, 1><<<dim3(8, 32, 1), 256, HSMEM1>>>(
        ffhi, nullptr, W2h, DFFC, DFFC, DD, DD, 0, 0, 0,
        out, nullptr, nullptr, bf2, x1, 0,
        nullptr, nullptr, nullptr, nullptr, nullptr, 0);
}

// round 17
// speedup vs baseline: 2.7443x; 1.0283x over previous
#include <cuda_runtime.h>
#include <cuda_bf16.h>
#include <cuda_fp16.h>
#include <math.h>
#include <stddef.h>
#include <stdint.h>

// ---------------- problem constants ----------------
#define BB   2
#define SS   2048
#define DD   1024
#define HH   16
#define HDIM 64
#define DFFC 2048
#define BH   (BB*HH)
#define NTOK (BB*SS)

#define MU_C   1.0f
#define K_C    3.0f
#define DT_C   0.02f
#define MIX_C  0.3f
#define CA_C   0.9950041652780258f
#define SA_C   0.09983341664682815f
#define ASCALE 2048.0f
#define AINV   (1.0f / 2048.0f)

// ---------------- scratch ----------------
__device__ __half g_S [(size_t)BH * SS * SS];           // fp16 raw scores
__device__ __half g_Ahi[(size_t)BH * SS * SS];          // fp16 scaled A
__device__ float g_xn  [(size_t)NTOK * DD];
__device__ __half g_xnhi[(size_t)NTOK * DD];
__device__ __half g_qhi[(size_t)BH * SS * 64];
__device__ __half g_khi[(size_t)BH * SS * 64];
__device__ float g_ab  [(size_t)BH * SS * 128];
__device__ float g_d1  [(size_t)BH * SS * 128];
__device__ __half g_abX[(size_t)BH * SS * 128];         // fp16 X state
__device__ __half g_pX [(size_t)BH * SS * 128];         // fp16 X predictor
__device__ float g_attnv[(size_t)BH * SS * 64];
__device__ __half g_mixh [(size_t)BH * SS * 64];        // fp16 mixed
__device__ float g_x1   [(size_t)NTOK * DD];
__device__ __half g_ffhi[(size_t)NTOK * DFFC];
__device__ __half g_W1h[(size_t)DD * DFFC];
__device__ __half g_W2h[(size_t)DFFC * DD];
__device__ __half g_Wqh[(size_t)HH * 64 * 64 + 128];    // padded for OOB cols
__device__ __half g_Wkh[(size_t)HH * 64 * 64 + 128];
__device__ __half g_Woh[(size_t)HH * 64 * 64 + 128];

// ---------------- low-level helpers ----------------
__device__ __forceinline__ uint32_t smem_u32(const void* p) {
    uint32_t a;
    asm("{ .reg .u64 t; cvta.to.shared.u64 t, %1; cvt.u32.u64 %0, t; }" : "=r"(a) : "l"(p));
    return a;
}
__device__ __forceinline__ void cp16(uint32_t s, const void* g) {
    asm volatile("cp.async.cg.shared.global [%0], [%1], 16;" :: "r"(s), "l"(g));
}
__device__ __forceinline__ void cp_commit() {
    asm volatile("cp.async.commit_group;" ::: "memory");
}
template <int N>
__device__ __forceinline__ void cp_wait() {
    asm volatile("cp.async.wait_group %0;" :: "n"(N) : "memory");
}
__device__ __forceinline__ void ldm_x4(uint32_t* r, uint32_t addr) {
    asm volatile("ldmatrix.sync.aligned.m8n8.x4.shared.b16 {%0,%1,%2,%3}, [%4];"
        : "=r"(r[0]), "=r"(r[1]), "=r"(r[2]), "=r"(r[3]) : "r"(addr));
}
__device__ __forceinline__ void ldm_x4t(uint32_t* r, uint32_t addr) {
    asm volatile("ldmatrix.sync.aligned.m8n8.x4.trans.shared.b16 {%0,%1,%2,%3}, [%4];"
        : "=r"(r[0]), "=r"(r[1]), "=r"(r[2]), "=r"(r[3]) : "r"(addr));
}
__device__ __forceinline__ void mma_f16(float* c, const uint32_t* a, const uint32_t* b) {
    asm volatile("mma.sync.aligned.m16n8k16.row.col.f32.f16.f16.f32 "
        "{%0,%1,%2,%3}, {%4,%5,%6,%7}, {%8,%9}, {%0,%1,%2,%3};"
        : "+f"(c[0]), "+f"(c[1]), "+f"(c[2]), "+f"(c[3])
        : "r"(a[0]), "r"(a[1]), "r"(a[2]), "r"(a[3]), "r"(b[0]), "r"(b[1]));
}
__device__ __forceinline__ float gelu_tanh(float x) {
    float x3 = x * x * x;
    float t  = tanhf(0.7978845608028654f * (x + 0.044715f * x3));
    return 0.5f * x * (1.0f + t);
}

// ---------------- unified fp16 HMMA GEMM, fusable ODE epilogue ----------------
// EPI: 0 = plain C output; 1 = fused ode_ew1; 2 = fused ode_ew2.
// PROD: 2 = 2-product ((Ahi+Alo) @ Bhi).  1 = 1-product (Ahi @ Bhi).
// Strides: if s?2 != 0, offset = (bz>>4)*s? + (bz&15)*s?2, else bz*s?.
// EPI0: outF!=0 && flag==0 -> fp32; flag==1 -> fp16 into outF. addsrc offset by cb.
//       Column stores gated by c0 < nvalid.
#define AST 72
#define BSTN 72
#define BSTT 136
#define STG2 55296
#define STG1 36864
#define HSMEM2 (3 * STG2)
#define HSMEM1 (2 * STG1)     // 73728, 2 CTA/SM (proven)

template<bool TRANSB, int EPI, int PROD>
__global__ void __launch_bounds__(256)
hgemm_kernel(const __half* __restrict__ Ahi, const __half* __restrict__ Alo,
             const __half* __restrict__ Bhi,
             int K, int lda, int ldb, int ldc,
             long long sA, long long sA2, long long sB, long long sB2,
             long long sC, long long sC2, int nvalid,
             float* __restrict__ outF,
             __half* __restrict__ outHi, __half* __restrict__ outLo,
             const float* __restrict__ bias, const float* __restrict__ addsrc, int do_gelu,
             const float* __restrict__ omg, float* __restrict__ abf,
             float* __restrict__ d1f, float* __restrict__ attnv,
             __half* __restrict__ mixed, int flag)
{
    constexpr int STGB  = (PROD == 2) ? STG2 : STG1;
    constexpr int OFFAL = 18432;
    constexpr int OFFBH = (PROD == 1) ? 18432 : 36864;
    extern __shared__ char smem[];
    const uint32_t sb = smem_u32(smem);
    const int tid = threadIdx.x;
    const int lane = tid & 31, w = tid >> 5;
    const int wm = w >> 2, wn = w & 3;
    const int n0 = blockIdx.x * 128;
    const int m0 = blockIdx.y * 128;
    const long long bz = blockIdx.z;

    if (sA2) Ahi += (bz >> 4) * sA + (bz & 15) * sA2;
    else     Ahi += bz * sA;
    if (PROD == 2) Alo += bz * sA;
    if (sB2) Bhi += (bz >> 4) * sB + (bz & 15) * sB2;
    else     Bhi += bz * sB;

    float acc[4][4][4];
#pragma unroll
    for (int i = 0; i < 4; i++)
#pragma unroll
        for (int j = 0; j < 4; j++)
#pragma unroll
            for (int r = 0; r < 4; r++) acc[i][j][r] = 0.f;

    auto issue = [&](int chunk, int buf) {
        const int k0 = chunk << 6;
        const uint32_t st = sb + buf * STGB;
        {
            const int row = tid >> 3, col = (tid & 7) * 8;
            const __half* gH = Ahi + (size_t)(m0 + row) * lda + k0 + col;
            uint32_t s = st + (row * AST + col) * 2;
#pragma unroll
            for (int j = 0; j < 4; j++)
                cp16(s + j * 32 * (AST * 2), gH + (size_t)j * 32 * lda);
            if (PROD == 2) {
                const __half* gL = Alo + (size_t)(m0 + row) * lda + k0 + col;
#pragma unroll
                for (int j = 0; j < 4; j++)
                    cp16(s + OFFAL + j * 32 * (AST * 2), gL + (size_t)j * 32 * lda);
            }
        }
        if (TRANSB) {
            const int rk = tid >> 2, col = (tid & 3) * 8;
            const __half* gH = Bhi + (size_t)(k0 + rk) * ldb + n0 + col;
            uint32_t s = st + OFFBH + (rk * BSTT + col) * 2;
#pragma unroll
            for (int j = 0; j < 4; j++)
                cp16(s + j * 64, gH + j * 32);
        } else {
            const int rn = tid >> 3, col = (tid & 7) * 8;
            const __half* gH = Bhi + (size_t)(n0 + rn) * ldb + k0 + col;
            uint32_t s = st + OFFBH + (rn * BSTN + col) * 2;
#pragma unroll
            for (int j = 0; j < 4; j++)
                cp16(s + j * 32 * (BSTN * 2), gH + (size_t)j * 32 * ldb);
        }
        cp_commit();
    };

    auto compute = [&](int buf) {
        const uint32_t st = sb + buf * STGB;
#pragma unroll
        for (int k16 = 0; k16 < 4; k16++) {
            uint32_t afrH[4][4], afrL[4][4], bfrH[4][2];
#pragma unroll
            for (int ms = 0; ms < 4; ms++) {
                int row = wm * 64 + ms * 16 + (lane & 15);
                int col = k16 * 16 + (lane >> 4) * 8;
                ldm_x4(afrH[ms], st + (row * AST + col) * 2);
                if (PROD == 2)
                    ldm_x4(afrL[ms], st + OFFAL + (row * AST + col) * 2);
            }
            if (TRANSB) {
                const int mat = lane >> 3, rr = lane & 7;
#pragma unroll
                for (int p = 0; p < 2; p++) {
                    int rk = k16 * 16 + (mat & 1) * 8 + rr;
                    int cn = wn * 32 + p * 16 + (mat >> 1) * 8;
                    ldm_x4t(&bfrH[p * 2][0], st + OFFBH + (rk * BSTT + cn) * 2);
                }
            } else {
                const int mat = lane >> 3, rr = lane & 7;
#pragma unroll
                for (int p = 0; p < 2; p++) {
                    int rn = wn * 32 + p * 16 + (mat >> 1) * 8 + rr;
                    int ck = k16 * 16 + (mat & 1) * 8;
                    ldm_x4(&bfrH[p * 2][0], st + OFFBH + (rn * BSTN + ck) * 2);
                }
            }
#pragma unroll
            for (int ms = 0; ms < 4; ms++)
#pragma unroll
                for (int ns = 0; ns < 4; ns++) {
                    mma_f16(acc[ms][ns], afrH[ms], bfrH[ns]);
                    if (PROD == 2)
                        mma_f16(acc[ms][ns], afrL[ms], bfrH[ns]);
                }
        }
    };

    const int nchunk = K >> 6;
    if (PROD == 2) {
        issue(0, 0);
        if (nchunk > 1) issue(1, 1);
#pragma unroll 1
        for (int i = 0; i < nchunk; i++) {
            if (i + 2 < nchunk)      { issue(i + 2, (i + 2) % 3); cp_wait<2>(); }
            else if (i + 1 < nchunk) { cp_wait<1>(); }
            else                     { cp_wait<0>(); }
            __syncthreads();
            compute(i % 3);
            __syncthreads();
        }
    } else {
        issue(0, 0);
#pragma unroll 1
        for (int i = 0; i < nchunk; i++) {
            if (i + 1 < nchunk) { issue(i + 1, (i + 1) & 1); cp_wait<1>(); }
            else                { cp_wait<0>(); }
            __syncthreads();
            compute(i & 1);
            __syncthreads();
        }
    }

    if (EPI == 0) {
        long long cb;
        if (sC2) cb = (bz >> 4) * sC + (bz & 15) * sC2;
        else     cb = bz * sC;
#pragma unroll
        for (int ms = 0; ms < 4; ms++) {
#pragma unroll
            for (int ns = 0; ns < 4; ns++) {
                int r0 = wm * 64 + ms * 16 + (lane >> 2);
                int c0 = n0 + wn * 32 + ns * 8 + (lane & 3) * 2;
                if (c0 >= nvalid) continue;
#pragma unroll
                for (int half = 0; half < 2; half++) {
                    long long r = m0 + r0 + half * 8;
                    float vx = acc[ms][ns][half * 2 + 0];
                    float vy = acc[ms][ns][half * 2 + 1];
                    if (bias)   { vx += bias[c0]; vy += bias[c0 + 1]; }
                    if (addsrc) {
                        float2 s = *reinterpret_cast<const float2*>(
                            addsrc + cb + r * ldc + c0);
                        vx += s.x; vy += s.y;
                    }
                    if (do_gelu) { vx = gelu_tanh(vx); vy = gelu_tanh(vy); }
                    long long o = cb + r * ldc + c0;
                    if (outF) {
                        if (flag)
                            *reinterpret_cast<__half2*>(
                                reinterpret_cast<__half*>(outF) + o) =
                                __floats2half2_rn(vx, vy);
                        else
                            *reinterpret_cast<float2*>(outF + o) = make_float2(vx, vy);
                    }
                    if (outHi) {
                        __half2 h = __floats2half2_rn(vx, vy);
                        *reinterpret_cast<__half2*>(outHi + o) = h;
                        if (outLo) {
                            float2 hf = __half22float2(h);
                            *reinterpret_cast<__half2*>(outLo + o) =
                                __floats2half2_rn(vx - hf.x, vy - hf.y);
                        }
                    }
                }
            }
        }
    } else {
        // stage z tile into smem (unscale by AINV), then batched ODE elementwise
        float* zsm = reinterpret_cast<float*>(smem);
#pragma unroll
        for (int ms = 0; ms < 4; ms++)
#pragma unroll
            for (int ns = 0; ns < 4; ns++) {
                int r0 = wm * 64 + ms * 16 + (lane >> 2);
                int c0 = wn * 32 + ns * 8 + (lane & 3) * 2;
                zsm[r0 * 132 + c0]     = acc[ms][ns][0] * AINV;
                zsm[r0 * 132 + c0 + 1] = acc[ms][ns][1] * AINV;
                zsm[(r0 + 8) * 132 + c0]     = acc[ms][ns][2] * AINV;
                zsm[(r0 + 8) * 132 + c0 + 1] = acc[ms][ns][3] * AINV;
            }
        __syncthreads();
        const int h = (int)(bz & 15);
        __half* Xout = outHi;
#pragma unroll 1
        for (int ib = 0; ib < 2; ib++) {
            float2 a2[8], b2[8], d1a[8], d1b[8];
            int r8[8], cp8[8];
            size_t base8[8];
#pragma unroll
            for (int j = 0; j < 8; j++) {
                int lin = (ib * 8 + j) * 256 + tid;
                int r = lin >> 5, cp = (lin & 31) * 2;
                r8[j] = r; cp8[j] = cp;
                size_t base = ((size_t)bz * SS + m0 + r) * 128 + cp;
                base8[j] = base;
                a2[j] = *reinterpret_cast<const float2*>(abf + base);
                b2[j] = *reinterpret_cast<const float2*>(abf + base + 64);
                if (EPI == 2) {
                    d1a[j] = *reinterpret_cast<const float2*>(d1f + base);
                    d1b[j] = *reinterpret_cast<const float2*>(d1f + base + 64);
                }
            }
#pragma unroll
            for (int j = 0; j < 8; j++) {
                int r = r8[j], cp = cp8[j];
                size_t base = base8[j];
                size_t row = (size_t)bz * SS + m0 + r;
                float2 om2 = *reinterpret_cast<const float2*>(omg + h * 64 + cp);
                float za0 = zsm[r * 132 + cp],     za1 = zsm[r * 132 + cp + 1];
                float zb0 = zsm[r * 132 + cp + 64], zb1 = zsm[r * 132 + cp + 65];
                float ra0 = za0 * CA_C + zb0 * SA_C, rb0 = zb0 * CA_C - za0 * SA_C;
                float ra1 = za1 * CA_C + zb1 * SA_C, rb1 = zb1 * CA_C - za1 * SA_C;
                if (EPI == 1) {
                    if (flag)
                        *reinterpret_cast<float2*>(attnv + row * 64 + cp) =
                            make_float2(za0, za1);
                    float r20 = a2[j].x * a2[j].x + b2[j].x * b2[j].x;
                    float r21 = a2[j].y * a2[j].y + b2[j].y * b2[j].y;
                    float da0 = (MU_C - r20) * a2[j].x - om2.x * b2[j].x + K_C * (ra0 - a2[j].x);
                    float db0 = (MU_C - r20) * b2[j].x + om2.x * a2[j].x + K_C * (rb0 - b2[j].x);
                    float da1 = (MU_C - r21) * a2[j].y - om2.y * b2[j].y + K_C * (ra1 - a2[j].y);
                    float db1 = (MU_C - r21) * b2[j].y + om2.y * a2[j].y + K_C * (rb1 - b2[j].y);
                    *reinterpret_cast<float2*>(d1f + base)      = make_float2(da0, da1);
                    *reinterpret_cast<float2*>(d1f + base + 64) = make_float2(db0, db1);
                    float ap0 = a2[j].x + DT_C * da0, ap1 = a2[j].y + DT_C * da1;
                    float bp0 = b2[j].x + DT_C * db0, bp1 = b2[j].y + DT_C * db1;
                    *reinterpret_cast<__half2*>(Xout + base) = __floats2half2_rn(ap0, ap1);
                    *reinterpret_cast<__half2*>(Xout + base + 64) = __floats2half2_rn(bp0, bp1);
                } else {
                    float ap0 = a2[j].x + DT_C * d1a[j].x, ap1 = a2[j].y + DT_C * d1a[j].y;
                    float bp0 = b2[j].x + DT_C * d1b[j].x, bp1 = b2[j].y + DT_C * d1b[j].y;
                    float r20 = ap0 * ap0 + bp0 * bp0;
                    float r21 = ap1 * ap1 + bp1 * bp1;
                    float da20 = (MU_C - r20) * ap0 - om2.x * bp0 + K_C * (ra0 - ap0);
                    float db20 = (MU_C - r20) * bp0 + om2.x * ap0 + K_C * (rb0 - bp0);
                    float da21 = (MU_C - r21) * ap1 - om2.y * bp1 + K_C * (ra1 - ap1);
                    float db21 = (MU_C - r21) * bp1 + om2.y * ap1 + K_C * (rb1 - bp1);
                    float an0 = a2[j].x + 0.5f * DT_C * (d1a[j].x + da20);
                    float an1 = a2[j].y + 0.5f * DT_C * (d1a[j].y + da21);
                    float bn0 = b2[j].x + 0.5f * DT_C * (d1b[j].x + db20);
                    float bn1 = b2[j].y + 0.5f * DT_C * (d1b[j].y + db21);
                    *reinterpret_cast<float2*>(abf + base)      = make_float2(an0, an1);
                    *reinterpret_cast<float2*>(abf + base + 64) = make_float2(bn0, bn1);
                    if (flag) {
                        float2 av = *reinterpret_cast<const float2*>(attnv + row * 64 + cp);
                        *reinterpret_cast<__half2*>(mixed + row * 64 + cp) =
                            __floats2half2_rn(MIX_C * av.x + (1.0f - MIX_C) * an0,
                                              MIX_C * av.y + (1.0f - MIX_C) * an1);
                    } else {
                        *reinterpret_cast<__half2*>(Xout + base) = __floats2half2_rn(an0, an1);
                        *reinterpret_cast<__half2*>(Xout + base + 64) = __floats2half2_rn(bn0, bn1);
                    }
                }
            }
        }
    }
}

// ---------------- fp32 -> fp16 convert ----------------
__global__ void splitWh_kernel(const float* __restrict__ A, __half* __restrict__ h)
{
    size_t i = ((size_t)blockIdx.x * blockDim.x + threadIdx.x) * 4;
    float4 v = *reinterpret_cast<const float4*>(A + i);
    *reinterpret_cast<__half2*>(h + i)     = __floats2half2_rn(v.x, v.y);
    *reinterpret_cast<__half2*>(h + i + 2) = __floats2half2_rn(v.z, v.w);
}

// ---------------- LayerNorm (optional fp16 hi output) ----------------
__global__ void ln_kernel(const float* __restrict__ x, const float* __restrict__ g,
                          const float* __restrict__ be, float* __restrict__ out,
                          __half* __restrict__ outHi)
{
    __shared__ float sh[8];
    size_t row = blockIdx.x;
    int tid = threadIdx.x, lane = tid & 31, wid = tid >> 5;
    float4 v = reinterpret_cast<const float4*>(x + row * DD)[tid];

    float s = v.x + v.y + v.z + v.w;
#pragma unroll
    for (int o = 16; o; o >>= 1) s += __shfl_xor_sync(0xffffffffu, s, o);
    if (lane == 0) sh[wid] = s;
    __syncthreads();
    float tot = 0.f;
#pragma unroll
    for (int i = 0; i < 8; i++) tot += sh[i];
    float mean = tot * (1.0f / DD);

    float dx = v.x - mean, dy = v.y - mean, dz = v.z - mean, dw = v.w - mean;
    float s2 = dx*dx + dy*dy + dz*dz + dw*dw;
#pragma unroll
    for (int o = 16; o; o >>= 1) s2 += __shfl_xor_sync(0xffffffffu, s2, o);
    __syncthreads();
    if (lane == 0) sh[wid] = s2;
    __syncthreads();
    float tot2 = 0.f;
#pragma unroll
    for (int i = 0; i < 8; i++) tot2 += sh[i];
    float rstd = rsqrtf(tot2 * (1.0f / DD) + 1e-5f);

    float4 gv = reinterpret_cast<const float4*>(g)[tid];
    float4 bv = reinterpret_cast<const float4*>(be)[tid];
    float4 o4;
    o4.x = dx * rstd * gv.x + bv.x;
    o4.y = dy * rstd * gv.y + bv.y;
    o4.z = dz * rstd * gv.z + bv.z;
    o4.w = dw * rstd * gv.w + bv.w;
    reinterpret_cast<float4*>(out + row * DD)[tid] = o4;
    if (outHi) {
        size_t i = row * DD + tid * 4;
        *reinterpret_cast<__half2*>(outHi + i)     = __floats2half2_rn(o4.x, o4.y);
        *reinterpret_cast<__half2*>(outHi + i + 2) = __floats2half2_rn(o4.z, o4.w);
    }
}

// ---------------- V projection only (SIMT, 64 rows/block) ----------------
__global__ void vproj_kernel(const float* __restrict__ xn, const float* __restrict__ Wv,
                             float* __restrict__ ab, __half* __restrict__ abX)
{
    __shared__ float sx[64][65];
    __shared__ float sw[64][65];
    int bh = blockIdx.y, b = bh >> 4, h = bh & 15;
    int s0 = blockIdx.x * 64;
    int tid = threadIdx.x;

    const float* W = Wv + h * 4096;
    for (int idx = tid; idx < 4096; idx += 256) {
        int r = idx >> 6, d = idx & 63;
        sx[r][d] = xn[((size_t)(b * SS + s0 + r)) * DD + h * 64 + d];
        sw[r][d] = W[idx];
    }
    __syncthreads();
    int e = tid & 63, rq = tid >> 6;
#pragma unroll
    for (int i = 0; i < 16; i++) {
        int r = rq * 16 + i;
        float acc = 0.f;
#pragma unroll
        for (int d = 0; d < 64; d++) acc = fmaf(sx[r][d], sw[d][e], acc);
        size_t srow = (size_t)bh * SS + s0 + r;
        ab[srow * 128 + e] = acc; ab[srow * 128 + 64 + e] = 0.f;
        abX[srow * 128 + e] = __float2half(acc);
        abX[srow * 128 + 64 + e] = __float2half(0.f);
    }
}

// ---------------- fused softmax (fp16 in) + scaled fp16 emit ----------------
__global__ void softmax_split_kernel(const __half* __restrict__ S,
                                     __half* __restrict__ Ahi)
{
    __shared__ float sh[8];
    size_t row = blockIdx.x;
    const __half* p = S + row * (size_t)SS;
    int tid = threadIdx.x, lane = tid & 31, wid = tid >> 5;

    float4 raw = reinterpret_cast<const float4*>(p)[tid];   // 8 halves
    const __half2* hp = reinterpret_cast<const __half2*>(&raw);
    float v[8];
#pragma unroll
    for (int i = 0; i < 4; i++) {
        float2 f = __half22float2(hp[i]);
        v[i * 2] = f.x * 0.125f; v[i * 2 + 1] = f.y * 0.125f;
    }

    float mx = v[0];
#pragma unroll
    for (int i = 1; i < 8; i++) mx = fmaxf(mx, v[i]);
#pragma unroll
    for (int o = 16; o; o >>= 1) mx = fmaxf(mx, __shfl_xor_sync(0xffffffffu, mx, o));
    if (lane == 0) sh[wid] = mx;
    __syncthreads();
    float m = sh[0];
#pragma unroll
    for (int i = 1; i < 8; i++) m = fmaxf(m, sh[i]);

    float s = 0.f;
#pragma unroll
    for (int i = 0; i < 8; i++) { v[i] = expf(v[i] - m); s += v[i]; }
#pragma unroll
    for (int o = 16; o; o >>= 1) s += __shfl_xor_sync(0xffffffffu, s, o);
    __syncthreads();
    if (lane == 0) sh[wid] = s;
    __syncthreads();
    float tot = 0.f;
#pragma unroll
    for (int i = 0; i < 8; i++) tot += sh[i];
    float inv = ASCALE / tot;

    size_t ob = row * (size_t)SS + tid * 8;
#pragma unroll
    for (int i = 0; i < 4; i++)
        *reinterpret_cast<__half2*>(Ahi + ob + i * 2) =
            __floats2half2_rn(v[i * 2] * inv, v[i * 2 + 1] * inv);
}

// ---------------- host side ----------------
extern "C" void kernel_launch(void* const* d_in, const int* in_sizes, int n_in,
                              void* d_out, int out_size)
{
    const float* x   = (const float*)d_in[0];
    const float* Wq  = (const float*)d_in[1];
    const float* Wk  = (const float*)d_in[2];
    const float* Wv  = (const float*)d_in[3];
    const float* Wo  = (const float*)d_in[4];
    const float* om  = (const float*)d_in[5];
    const float* g1  = (const float*)d_in[6];
    const float* be1 = (const float*)d_in[7];
    const float* g2  = (const float*)d_in[8];
    const float* be2 = (const float*)d_in[9];
    const float* W1  = (const float*)d_in[10];
    const float* bf1 = (const float*)d_in[11];
    const float* W2  = (const float*)d_in[12];
    const float* bf2 = (const float*)d_in[13];
    float* out = (float*)d_out;
    (void)in_sizes; (void)n_in; (void)out_size;

    float *xn, *ab, *d1, *attnv, *x1;
    __half *S_, *Ahi, *xnhi, *qhi, *khi, *mixh;
    __half *abX, *pX, *ffhi, *W1h, *W2h, *Wqh, *Wkh, *Woh;
    cudaGetSymbolAddress((void**)&S_,    g_S);
    cudaGetSymbolAddress((void**)&Ahi,   g_Ahi);
    cudaGetSymbolAddress((void**)&xn,    g_xn);
    cudaGetSymbolAddress((void**)&xnhi,  g_xnhi);
    cudaGetSymbolAddress((void**)&qhi,   g_qhi);
    cudaGetSymbolAddress((void**)&khi,   g_khi);
    cudaGetSymbolAddress((void**)&ab,    g_ab);
    cudaGetSymbolAddress((void**)&d1,    g_d1);
    cudaGetSymbolAddress((void**)&abX,   g_abX);
    cudaGetSymbolAddress((void**)&pX,    g_pX);
    cudaGetSymbolAddress((void**)&attnv, g_attnv);
    cudaGetSymbolAddress((void**)&mixh,  g_mixh);
    cudaGetSymbolAddress((void**)&x1,    g_x1);
    cudaGetSymbolAddress((void**)&ffhi,  g_ffhi);
    cudaGetSymbolAddress((void**)&W1h,   g_W1h);
    cudaGetSymbolAddress((void**)&W2h,   g_W2h);
    cudaGetSymbolAddress((void**)&Wqh,   g_Wqh);
    cudaGetSymbolAddress((void**)&Wkh,   g_Wkh);
    cudaGetSymbolAddress((void**)&Woh,   g_Woh);

    cudaFuncSetAttribute(hgemm_kernel<false, 0, 1>,
                         cudaFuncAttributeMaxDynamicSharedMemorySize, HSMEM1);
    cudaFuncSetAttribute(hgemm_kernel<true, 0, 1>,
                         cudaFuncAttributeMaxDynamicSharedMemorySize, HSMEM1);
    cudaFuncSetAttribute(hgemm_kernel<true, 1, 1>,
                         cudaFuncAttributeMaxDynamicSharedMemorySize, HSMEM1);
    cudaFuncSetAttribute(hgemm_kernel<true, 2, 1>,
                         cudaFuncAttributeMaxDynamicSharedMemorySize, HSMEM1);

    const long long sQK = (long long)SS * 64;
    const long long sAA = (long long)SS * SS;
    const long long sAB = (long long)SS * 128;
    const long long sBD = (long long)SS * DD;
    const int BIGN = 1 << 30;

    splitWh_kernel<<<(unsigned)((size_t)DD * DFFC / 1024), 256>>>(W1, W1h);
    splitWh_kernel<<<(unsigned)((size_t)DFFC * DD / 1024), 256>>>(W2, W2h);
    splitWh_kernel<<<64, 256>>>(Wq, Wqh);
    splitWh_kernel<<<64, 256>>>(Wk, Wkh);
    splitWh_kernel<<<64, 256>>>(Wo, Woh);

    // 1. LN1 -> fp32 + fp16
    ln_kernel<<<NTOK, 256>>>(x, g1, be1, xn, xnhi);
    // 2a. V projection (SIMT)
    vproj_kernel<<<dim3(SS / 64, BH), 256>>>(xn, Wv, ab, abX);
    // 2b. q = xn_h @ Wq_h (HMMA, per-head strides, fp16 out)
    hgemm_kernel<true, 0, 1><<<dim3(1, 16, BH), 256, HSMEM1>>>(
        xnhi, nullptr, Wqh, 64, DD, 64, 64,
        sBD, 64, 0, 4096, sQK, 0, 64,
        reinterpret_cast<float*>(qhi), nullptr, nullptr, nullptr, nullptr, 0,
        nullptr, nullptr, nullptr, nullptr, nullptr, 1);
    // 2c. k = xn_h @ Wk_h
    hgemm_kernel<true, 0, 1><<<dim3(1, 16, BH), 256, HSMEM1>>>(
        xnhi, nullptr, Wkh, 64, DD, 64, 64,
        sBD, 64, 0, 4096, sQK, 0, 64,
        reinterpret_cast<float*>(khi), nullptr, nullptr, nullptr, nullptr, 0,
        nullptr, nullptr, nullptr, nullptr, nullptr, 1);
    // 3. scores (fp16 1-product) -> fp16 S
    hgemm_kernel<false, 0, 1><<<dim3(16, 16, BH), 256, HSMEM1>>>(
        qhi, nullptr, khi, 64, 64, 64, SS,
        sQK, 0, sQK, 0, sAA, 0, BIGN,
        reinterpret_cast<float*>(S_), nullptr, nullptr, nullptr, nullptr, 0,
        nullptr, nullptr, nullptr, nullptr, nullptr, 1);
    // 4. softmax (fp16 in) + scaled fp16 A
    softmax_split_kernel<<<BH * SS, 256>>>(S_, Ahi);
    // 5. Heun loop: fp16 1-product GEMM (2-stage, 2 CTAs/SM) + fused ODE epilogues
    for (int st = 0; st < 5; st++) {
        hgemm_kernel<true, 1, 1><<<dim3(1, 16, BH), 256, HSMEM1>>>(
            Ahi, nullptr, abX, SS, SS, 128, 128,
            sAA, 0, sAB, 0, sAB, 0, BIGN,
            nullptr, pX, nullptr, nullptr, nullptr, 0,
            om, ab, d1, attnv, nullptr, st == 0 ? 1 : 0);
        hgemm_kernel<true, 2, 1><<<dim3(1, 16, BH), 256, HSMEM1>>>(
            Ahi, nullptr, pX, SS, SS, 128, 128,
            sAA, 0, sAB, 0, sAB, 0, BIGN,
            nullptr, abX, nullptr, nullptr, nullptr, 0,
            om, ab, d1, attnv, mixh, st == 4 ? 1 : 0);
    }
    // 6. head projection + residual: x1 = x + scatter(mix_h @ Wo_h)  (HMMA)
    hgemm_kernel<true, 0, 1><<<dim3(1, 16, BH), 256, HSMEM1>>>(
        mixh, nullptr, Woh, 64, 64, 64, DD,
        sQK, 0, 0, 4096, sBD, 64, 64,
        x1, nullptr, nullptr, nullptr, x, 0,
        nullptr, nullptr, nullptr, nullptr, nullptr, 0);
    // 7. LN2 -> fp32 + fp16
    ln_kernel<<<NTOK, 256>>>(x1, g2, be2, xn, xnhi);
    // 8. FFN1 (fp16 1-product)
    hgemm_kernel<true, 0, 1><<<dim3(16, 32, 1), 256, HSMEM1>>>(
        xnhi, nullptr, W1h, DD, DD, DFFC, DFFC,
        0, 0, 0, 0, 0, 0, BIGN,
        nullptr, ffhi, nullptr, bf1, nullptr, 1,
        nullptr, nullptr, nullptr, nullptr, nullptr, 0);
    // 9. FFN2 (fp16 1-product): out = x1 + ff @ W2 + bf2
    hgemm_kernel<true, 0, 1><<<dim3(8, 32, 1), 256, HSMEM1>>>(
        ffhi, nullptr, W2h, DFFC, DFFC, DD, DD,
        0, 0, 0, 0, 0, 0, BIGN,
        out, nullptr, nullptr, bf2, x1, 0,
        nullptr, nullptr, nullptr, nullptr, nullptr, 0);
}